// round 1
// baseline (speedup 1.0000x reference)
#include <cuda_runtime.h>
#include <math.h>

#define Bz 2
#define Cc 64
#define Hh 256
#define Ww 256
#define CQ 8
#define CRr 4
#define HW (Hh*Ww)
#define BCHW (Bz*Cc*HW)

// ---------------- scratch (device globals; no runtime allocation) ----------------
__device__ float g_q1[Bz*CQ*HW];
__device__ float g_q2[Bz*CQ*HW];
__device__ float g_k1[Bz*CQ*HW];
__device__ float g_k2[Bz*CQ*HW];
__device__ float g_v1[Bz*Cc*HW];
__device__ float g_v2[Bz*Cc*HW];
__device__ float g_e[(size_t)Bz*HW*512];   // [b][h][w][512]: [0:256)=eH(g), [256:512)=eW(v)
__device__ float g_att1[Bz*Cc*HW];
__device__ float g_att2[Bz*Cc*HW];
__device__ float g_t1[Bz*Cc*HW];
__device__ float g_t2[Bz*Cc*HW];
__device__ float g_pool[4*Bz*Cc];          // mean1,max1,mean2,max2
__device__ float g_gate[2*Bz*Cc];
__device__ float g_part[2*Cc*Bz*2];        // [branch][c][b][sum,sumsq]
__device__ float g_stat[2*Cc*2];           // [branch][c][mean,invstd]

// ---------------- conv1x1: out[b,o,p] = sum_c w[o,c] x[b,c,p] + bias[o] ----------------
template<int OC>
__global__ void conv1x1_kernel(const float* __restrict__ x, const float* __restrict__ w,
                               const float* __restrict__ bias, float* __restrict__ out) {
    __shared__ float ws[OC*Cc];
    __shared__ float bs[OC];
    for (int i = threadIdx.x; i < OC*Cc; i += 256) ws[i] = w[i];
    for (int i = threadIdx.x; i < OC; i += 256) bs[i] = bias[i];
    __syncthreads();
    int p = blockIdx.x*256 + threadIdx.x;          // Bz*HW pixels, exact grid
    int b = p / HW, hw = p - b*HW;
    const float* xb = x + (size_t)b*Cc*HW + hw;
    float acc[OC];
#pragma unroll
    for (int o = 0; o < OC; o++) acc[o] = bs[o];
    for (int c = 0; c < Cc; c++) {
        float xv = xb[(size_t)c*HW];
#pragma unroll
        for (int o = 0; o < OC; o++) acc[o] += ws[o*Cc + c]*xv;
    }
    float* ob = out + (size_t)b*OC*HW + hw;
#pragma unroll
    for (int o = 0; o < OC; o++) ob[(size_t)o*HW] = acc[o];
}

// ---------------- energies: 256x256 GEMM per (b,outer), K=CQ ----------------
// MODE 0: eH -> fixed w=o, rows h, cols g, diag mask. MODE 1: eW -> fixed h=o, rows w, cols v.
template<int MODE>
__global__ void energy_kernel(const float* __restrict__ q, const float* __restrict__ k,
                              float* __restrict__ e) {
    int b = blockIdx.y;
    int o = blockIdx.x;
    __shared__ float qs[CQ][Hh];
    __shared__ float ks[CQ][Hh];
    const size_t bq = (size_t)b*CQ*HW;
    for (int i = threadIdx.x; i < CQ*Hh; i += 256) {
        int c = i >> 8, r = i & 255;
        if (MODE == 0) {
            qs[c][r] = q[bq + (size_t)c*HW + r*Ww + o];
            ks[c][r] = k[bq + (size_t)c*HW + r*Ww + o];
        } else {
            qs[c][r] = q[bq + (size_t)c*HW + o*Ww + r];
            ks[c][r] = k[bq + (size_t)c*HW + o*Ww + r];
        }
    }
    __syncthreads();
    int warp = threadIdx.x >> 5, lane = threadIdx.x & 31;
    for (int r = warp; r < Hh; r += 8) {
        float qv[CQ];
#pragma unroll
        for (int c = 0; c < CQ; c++) qv[c] = qs[c][r];
        size_t base = (MODE == 0)
            ? ((size_t)(b*HW + r*Ww + o))*512
            : ((size_t)(b*HW + o*Ww + r))*512 + 256;
#pragma unroll
        for (int jj = 0; jj < 8; jj++) {
            int j = lane + jj*32;
            float acc = 0.f;
#pragma unroll
            for (int c = 0; c < CQ; c++) acc += qv[c]*ks[c][j];
            if (MODE == 0 && j == r) acc = -1e30f;
            e[base + j] = acc;
        }
    }
}

// ---------------- softmax over contiguous 512-row, 1 warp per pixel ----------------
__global__ void softmax_kernel(float* __restrict__ e) {
    int row = blockIdx.x*8 + (threadIdx.x >> 5);   // Bz*HW rows, exact
    int lane = threadIdx.x & 31;
    float* p = e + (size_t)row*512;
    float v[16];
    float mx = -1e30f;
#pragma unroll
    for (int i = 0; i < 16; i++) { v[i] = p[lane + i*32]; mx = fmaxf(mx, v[i]); }
#pragma unroll
    for (int s = 16; s > 0; s >>= 1) mx = fmaxf(mx, __shfl_xor_sync(0xffffffffu, mx, s));
    float sum = 0.f;
#pragma unroll
    for (int i = 0; i < 16; i++) { v[i] = __expf(v[i] - mx); sum += v[i]; }
#pragma unroll
    for (int s = 16; s > 0; s >>= 1) sum += __shfl_xor_sync(0xffffffffu, sum, s);
    float inv = 1.f/sum;
#pragma unroll
    for (int i = 0; i < 16; i++) p[lane + i*32] = v[i]*inv;
}

// ---------------- aggregation: out tile = A(256x256) x V(256x64) per (b,outer) ----------------
// MODE 0: outH: block per (b,w). V[g][c]=v[b,c,g,w]; A rows = aH[b,h,w,:]; write '='.
// MODE 1: outW: block per (b,h). V[g][c]=v[b,c,h,g]; A rows = aW[b,h,w,256+:]; '+='.
#define VROW 68                     // padded row stride in floats (17 float4)
#define AGG_SMEM ((256*VROW + 32*257)*4)
template<int MODE>
__global__ void agg_kernel(const float* __restrict__ e, const float* __restrict__ v,
                           float* __restrict__ out) {
    extern __shared__ float sm[];
    float* Vsm = sm;                      // 256 x VROW
    float* Asm = sm + 256*VROW;           // 32 x 257
    int b = blockIdx.y, o = blockIdx.x;
    const size_t vb = (size_t)b*Cc*HW;
    for (int i = threadIdx.x; i < Cc*Hh; i += 256) {
        int c = i >> 8, g = i & 255;
        float val = (MODE == 0) ? v[vb + (size_t)c*HW + g*Ww + o]
                                : v[vb + (size_t)c*HW + o*Ww + g];
        Vsm[g*VROW + c] = val;
    }
    int lane = threadIdx.x & 31;
    int wid  = threadIdx.x >> 5;          // 0..7 -> channels 8*wid..8*wid+7
    const float4* V4 = (const float4*)Vsm;
    for (int r0 = 0; r0 < Hh; r0 += 32) {
        __syncthreads();
        for (int i = threadIdx.x; i < 32*256; i += 256) {
            int rr = i >> 8, g = i & 255;
            size_t arow = (MODE == 0)
                ? ((size_t)(b*HW + (r0+rr)*Ww + o))*512 + g
                : ((size_t)(b*HW + o*Ww + (r0+rr)))*512 + 256 + g;
            Asm[rr*257 + g] = e[arow];
        }
        __syncthreads();
        float4 acc0 = make_float4(0.f,0.f,0.f,0.f);
        float4 acc1 = make_float4(0.f,0.f,0.f,0.f);
        const float* ar = Asm + lane*257;
#pragma unroll 4
        for (int g = 0; g < 256; g++) {
            float a = ar[g];
            float4 v0 = V4[g*17 + 2*wid];
            float4 v1 = V4[g*17 + 2*wid + 1];
            acc0.x += a*v0.x; acc0.y += a*v0.y; acc0.z += a*v0.z; acc0.w += a*v0.w;
            acc1.x += a*v1.x; acc1.y += a*v1.y; acc1.z += a*v1.z; acc1.w += a*v1.w;
        }
        int r = r0 + lane;
        int c0 = wid*8;
        float vals[8] = {acc0.x,acc0.y,acc0.z,acc0.w,acc1.x,acc1.y,acc1.z,acc1.w};
        if (MODE == 0) {
            size_t ob = vb + (size_t)c0*HW + r*Ww + o;
#pragma unroll
            for (int j = 0; j < 8; j++) out[ob + (size_t)j*HW] = vals[j];
        } else {
            size_t ob = vb + (size_t)c0*HW + o*Ww + r;
#pragma unroll
            for (int j = 0; j < 8; j++) out[ob + (size_t)j*HW] += vals[j];
        }
    }
}

// ---------------- pooling: per (b,c) mean/max of s1, s2 ----------------
__global__ void pool_kernel(const float* __restrict__ att1, const float* __restrict__ att2,
                            const float* __restrict__ x1, const float* __restrict__ x2,
                            const float* __restrict__ gamma1, const float* __restrict__ gamma2,
                            float* __restrict__ pool) {
    int c = blockIdx.x, b = blockIdx.y, tid = threadIdx.x;
    size_t base = ((size_t)b*Cc + c)*HW;
    float g1 = gamma1[0], g2 = gamma2[0];
    float sum1 = 0.f, sum2 = 0.f, mx1 = -1e30f, mx2 = -1e30f;
    for (int i = tid; i < HW; i += 256) {
        float a1 = att1[base+i], a2 = att2[base+i], xa = x1[base+i], xb = x2[base+i];
        float s1 = g2*a2 + xb + xa;
        float s2 = g1*a1 + xa + xb;
        sum1 += s1; sum2 += s2;
        mx1 = fmaxf(mx1, s1); mx2 = fmaxf(mx2, s2);
    }
    __shared__ float red[4][256];
    red[0][tid] = sum1; red[1][tid] = sum2; red[2][tid] = mx1; red[3][tid] = mx2;
    __syncthreads();
    for (int s = 128; s > 0; s >>= 1) {
        if (tid < s) {
            red[0][tid] += red[0][tid+s];
            red[1][tid] += red[1][tid+s];
            red[2][tid] = fmaxf(red[2][tid], red[2][tid+s]);
            red[3][tid] = fmaxf(red[3][tid], red[3][tid+s]);
        }
        __syncthreads();
    }
    if (tid == 0) {
        pool[(0*Bz + b)*Cc + c] = red[0][0]*(1.f/HW);
        pool[(1*Bz + b)*Cc + c] = red[2][0];
        pool[(2*Bz + b)*Cc + c] = red[1][0]*(1.f/HW);
        pool[(3*Bz + b)*Cc + c] = red[3][0];
    }
}

// ---------------- tiny gate MLP: sigmoid(mlp(mean)+mlp(max)) per branch/b/c ----------------
__global__ void gate_kernel(const float* __restrict__ w1a, const float* __restrict__ b1a,
                            const float* __restrict__ w2a, const float* __restrict__ b2a,
                            const float* __restrict__ w1b, const float* __restrict__ b1b,
                            const float* __restrict__ w2b, const float* __restrict__ b2b,
                            const float* __restrict__ pool, float* __restrict__ gate) {
    __shared__ float hid[2][Bz][2][CRr];
    int tid = threadIdx.x;
    if (tid < 2*Bz*2*CRr) {
        int r  = tid & (CRr-1);
        int mm = (tid >> 2) & 1;
        int bb = (tid >> 3) & 1;
        int br = (tid >> 4) & 1;
        const float* w1 = br ? w1b : w1a;
        const float* b1 = br ? b1b : b1a;
        const float* p = pool + ((size_t)(br*2 + mm)*Bz + bb)*Cc;
        float acc = b1[r];
        for (int c = 0; c < Cc; c++) acc += w1[r*Cc + c]*p[c];
        hid[br][bb][mm][r] = fmaxf(acc, 0.f);
    }
    __syncthreads();
    int c = tid & 63, bb = (tid >> 6) & 1, br = tid >> 7;
    const float* w2 = br ? w2b : w2a;
    const float* b2 = br ? b2b : b2a;
    float o = 2.f*b2[c];
    for (int mm = 0; mm < 2; mm++)
#pragma unroll
        for (int r = 0; r < CRr; r++) o += w2[c*CRr + r]*hid[br][bb][mm][r];
    gate[(br*Bz + bb)*Cc + c] = 1.f/(1.f + expf(-o));
}

// ---------------- t = gate*s + x (odd channels only) + per-channel BN partial sums ----------------
__global__ void bnsum_kernel(const float* __restrict__ att1, const float* __restrict__ att2,
                             const float* __restrict__ x1, const float* __restrict__ x2,
                             const float* __restrict__ gamma1, const float* __restrict__ gamma2,
                             const float* __restrict__ gate,
                             float* __restrict__ t1, float* __restrict__ t2,
                             float* __restrict__ part) {
    int c = blockIdx.x*2 + 1;                     // odd channels only (even copy x directly)
    int b = blockIdx.y, tid = threadIdx.x;
    size_t base = ((size_t)b*Cc + c)*HW;
    float g1 = gamma1[0], g2 = gamma2[0];
    float gt1 = gate[(0*Bz + b)*Cc + c];
    float gt2 = gate[(1*Bz + b)*Cc + c];
    float s1s = 0.f, s1q = 0.f, s2s = 0.f, s2q = 0.f;
    for (int i = tid; i < HW; i += 256) {
        float a1 = att1[base+i], a2 = att2[base+i], xa = x1[base+i], xb = x2[base+i];
        float s1 = g2*a2 + xb + xa;
        float v1 = gt1*s1 + xa;
        t1[base+i] = v1; s1s += v1; s1q += v1*v1;
        float s2 = g1*a1 + xa + xb;
        float v2 = gt2*s2 + xb;
        t2[base+i] = v2; s2s += v2; s2q += v2*v2;
    }
    __shared__ float red[4][256];
    red[0][tid] = s1s; red[1][tid] = s1q; red[2][tid] = s2s; red[3][tid] = s2q;
    __syncthreads();
    for (int s = 128; s > 0; s >>= 1) {
        if (tid < s)
            for (int k = 0; k < 4; k++) red[k][tid] += red[k][tid+s];
        __syncthreads();
    }
    if (tid == 0) {
        part[((0*Cc + c)*Bz + b)*2 + 0] = red[0][0];
        part[((0*Cc + c)*Bz + b)*2 + 1] = red[1][0];
        part[((1*Cc + c)*Bz + b)*2 + 0] = red[2][0];
        part[((1*Cc + c)*Bz + b)*2 + 1] = red[3][0];
    }
}

__global__ void bnstat_kernel(const float* __restrict__ part, float* __restrict__ stat) {
    int tid = threadIdx.x;                 // 128 threads: [branch(2)][c(64)]
    int br = tid >> 6, c = tid & 63;
    if (!(c & 1)) return;
    float s = 0.f, q = 0.f;
    for (int b = 0; b < Bz; b++) {
        s += part[((br*Cc + c)*Bz + b)*2 + 0];
        q += part[((br*Cc + c)*Bz + b)*2 + 1];
    }
    float N = (float)(Bz*HW);
    float m = s/N;
    float var = q/N - m*m;
    stat[(br*Cc + c)*2 + 0] = m;
    stat[(br*Cc + c)*2 + 1] = rsqrtf(var + 1e-5f);
}

// ---------------- finalize: BN+relu on odd channels, copy x on even; write both outputs ----------------
__global__ void final_kernel(const float* __restrict__ x1, const float* __restrict__ x2,
                             const float* __restrict__ t1, const float* __restrict__ t2,
                             const float* __restrict__ stat,
                             const float* __restrict__ sc1, const float* __restrict__ bi1,
                             const float* __restrict__ sc2, const float* __restrict__ bi2,
                             float* __restrict__ out) {
    size_t n = (size_t)blockIdx.x*256 + threadIdx.x;   // BCHW exact
    int c = (int)((n / HW) & 63);
    float o1, o2;
    if ((c & 1) == 0) {
        o1 = x1[n]; o2 = x2[n];
    } else {
        float m1 = stat[(0*Cc + c)*2], is1 = stat[(0*Cc + c)*2 + 1];
        o1 = fmaxf((t1[n] - m1)*is1*sc1[c] + bi1[c], 0.f);
        float m2 = stat[(1*Cc + c)*2], is2 = stat[(1*Cc + c)*2 + 1];
        o2 = fmaxf((t2[n] - m2)*is2*sc2[c] + bi2[c], 0.f);
    }
    out[n] = o1;
    out[(size_t)BCHW + n] = o2;
}

// ---------------- host launch ----------------
extern "C" void kernel_launch(void* const* d_in, const int* in_sizes, int n_in,
                              void* d_out, int out_size) {
    const float* x1  = (const float*)d_in[0];
    const float* x2  = (const float*)d_in[1];
    const float* wq1 = (const float*)d_in[2];
    const float* bq1 = (const float*)d_in[3];
    const float* wq2 = (const float*)d_in[4];
    const float* bq2 = (const float*)d_in[5];
    const float* wk1 = (const float*)d_in[6];
    const float* bk1 = (const float*)d_in[7];
    const float* wk2 = (const float*)d_in[8];
    const float* bk2 = (const float*)d_in[9];
    const float* wv1 = (const float*)d_in[10];
    const float* bv1 = (const float*)d_in[11];
    const float* wv2 = (const float*)d_in[12];
    const float* bv2 = (const float*)d_in[13];
    const float* gamma1 = (const float*)d_in[14];
    const float* gamma2 = (const float*)d_in[15];
    const float* sc1_w1 = (const float*)d_in[16];
    const float* sc1_b1 = (const float*)d_in[17];
    const float* sc1_w2 = (const float*)d_in[18];
    const float* sc1_b2 = (const float*)d_in[19];
    const float* sc2_w1 = (const float*)d_in[20];
    const float* sc2_b1 = (const float*)d_in[21];
    const float* sc2_w2 = (const float*)d_in[22];
    const float* sc2_b2 = (const float*)d_in[23];
    const float* bn1_scale = (const float*)d_in[24];
    const float* bn1_bias  = (const float*)d_in[25];
    const float* bn2_scale = (const float*)d_in[26];
    const float* bn2_bias  = (const float*)d_in[27];

    float *q1, *q2, *k1, *k2, *v1, *v2, *e, *att1, *att2, *t1, *t2, *pool, *gate, *part, *stat;
    cudaGetSymbolAddress((void**)&q1, g_q1);
    cudaGetSymbolAddress((void**)&q2, g_q2);
    cudaGetSymbolAddress((void**)&k1, g_k1);
    cudaGetSymbolAddress((void**)&k2, g_k2);
    cudaGetSymbolAddress((void**)&v1, g_v1);
    cudaGetSymbolAddress((void**)&v2, g_v2);
    cudaGetSymbolAddress((void**)&e,  g_e);
    cudaGetSymbolAddress((void**)&att1, g_att1);
    cudaGetSymbolAddress((void**)&att2, g_att2);
    cudaGetSymbolAddress((void**)&t1, g_t1);
    cudaGetSymbolAddress((void**)&t2, g_t2);
    cudaGetSymbolAddress((void**)&pool, g_pool);
    cudaGetSymbolAddress((void**)&gate, g_gate);
    cudaGetSymbolAddress((void**)&part, g_part);
    cudaGetSymbolAddress((void**)&stat, g_stat);

    cudaFuncSetAttribute(agg_kernel<0>, cudaFuncAttributeMaxDynamicSharedMemorySize, AGG_SMEM);
    cudaFuncSetAttribute(agg_kernel<1>, cudaFuncAttributeMaxDynamicSharedMemorySize, AGG_SMEM);

    // projections
    conv1x1_kernel<CQ><<<512, 256>>>(x1, wq1, bq1, q1);
    conv1x1_kernel<CQ><<<512, 256>>>(x2, wq2, bq2, q2);
    conv1x1_kernel<CQ><<<512, 256>>>(x1, wk1, bk1, k1);
    conv1x1_kernel<CQ><<<512, 256>>>(x2, wk2, bk2, k2);
    conv1x1_kernel<Cc><<<512, 256>>>(x1, wv1, bv1, v1);
    conv1x1_kernel<Cc><<<512, 256>>>(x2, wv2, bv2, v2);

    // criss-cross 1: att1 = cc(q2, k1, v1)
    energy_kernel<0><<<dim3(Ww, Bz), 256>>>(q2, k1, e);
    energy_kernel<1><<<dim3(Hh, Bz), 256>>>(q2, k1, e);
    softmax_kernel<<<Bz*HW/8, 256>>>(e);
    agg_kernel<0><<<dim3(Ww, Bz), 256, AGG_SMEM>>>(e, v1, att1);
    agg_kernel<1><<<dim3(Hh, Bz), 256, AGG_SMEM>>>(e, v1, att1);

    // criss-cross 2: att2 = cc(q1, k2, v2)
    energy_kernel<0><<<dim3(Ww, Bz), 256>>>(q1, k2, e);
    energy_kernel<1><<<dim3(Hh, Bz), 256>>>(q1, k2, e);
    softmax_kernel<<<Bz*HW/8, 256>>>(e);
    agg_kernel<0><<<dim3(Ww, Bz), 256, AGG_SMEM>>>(e, v2, att2);
    agg_kernel<1><<<dim3(Hh, Bz), 256, AGG_SMEM>>>(e, v2, att2);

    // ShareCA pooling + gates
    pool_kernel<<<dim3(Cc, Bz), 256>>>(att1, att2, x1, x2, gamma1, gamma2, pool);
    gate_kernel<<<1, 256>>>(sc1_w1, sc1_b1, sc1_w2, sc1_b2,
                            sc2_w1, sc2_b1, sc2_w2, sc2_b2, pool, gate);

    // BN stats (odd channels) + finalize
    bnsum_kernel<<<dim3(Cc/2, Bz), 256>>>(att1, att2, x1, x2, gamma1, gamma2, gate, t1, t2, part);
    bnstat_kernel<<<1, 128>>>(part, stat);
    final_kernel<<<BCHW/256, 256>>>(x1, x2, t1, t2, stat,
                                    bn1_scale, bn1_bias, bn2_scale, bn2_bias, (float*)d_out);
}

// round 3
// speedup vs baseline: 1.0617x; 1.0617x over previous
#include <cuda_runtime.h>
#include <math.h>

#define Bz 2
#define Cc 64
#define Hh 256
#define Ww 256
#define CQ 8
#define CRr 4
#define HW (Hh*Ww)
#define BCHW (Bz*Cc*HW)

// ---------------- scratch (device globals; no runtime allocation) ----------------
__device__ float g_q1[Bz*CQ*HW];
__device__ float g_q2[Bz*CQ*HW];
__device__ float g_k1[Bz*CQ*HW];
__device__ float g_k2[Bz*CQ*HW];
__device__ float g_v1[Bz*Cc*HW];
__device__ float g_v2[Bz*Cc*HW];
__device__ float g_m0[Bz*HW];              // criss 0 (att1 = cc(q2,k1,v1)): max then combined max
__device__ float g_s0[Bz*HW];              // criss 0: sum then 1/sum
__device__ float g_m1[Bz*HW];              // criss 1 (att2 = cc(q1,k2,v2))
__device__ float g_s1[Bz*HW];
__device__ float g_att1[Bz*Cc*HW];
__device__ float g_att2[Bz*Cc*HW];
__device__ float g_t1[Bz*Cc*HW];
__device__ float g_t2[Bz*Cc*HW];
__device__ float g_pool[4*Bz*Cc];          // mean1,max1,mean2,max2
__device__ float g_gate[2*Bz*Cc];
__device__ float g_part[2*Cc*Bz*2];        // [branch][c][b][sum,sumsq]
__device__ float g_stat[2*Cc*2];           // [branch][c][mean,invstd]

// ---------------- packed f32x2 helpers (FFMA2 path, 2x fp32 throughput) ----------------
__device__ __forceinline__ unsigned long long fma2(unsigned long long a, unsigned long long b,
                                                   unsigned long long c) {
    unsigned long long d;
    asm("fma.rn.f32x2 %0, %1, %2, %3;" : "=l"(d) : "l"(a), "l"(b), "l"(c));
    return d;
}
__device__ __forceinline__ unsigned long long packf2(float lo, float hi) {
    unsigned long long r;
    asm("mov.b64 %0, {%1, %2};" : "=l"(r) : "f"(lo), "f"(hi));
    return r;
}
__device__ __forceinline__ float2 unpackf2(unsigned long long a) {
    float2 r;
    asm("mov.b64 {%0, %1}, %2;" : "=f"(r.x), "=f"(r.y) : "l"(a));
    return r;
}

// ---------------- fused projection: x -> q(8), k(8), v(64) in one pass over x ----------------
__global__ __launch_bounds__(256) void proj_kernel(
    const float* __restrict__ x,
    const float* __restrict__ wq, const float* __restrict__ bq,
    const float* __restrict__ wk, const float* __restrict__ bk,
    const float* __restrict__ wv, const float* __restrict__ bv,
    float* __restrict__ q, float* __restrict__ k, float* __restrict__ v) {
    __shared__ unsigned long long ws2[64*40];
    __shared__ unsigned long long bs2[40];
    int tid = threadIdx.x;
    for (int i = tid; i < 64*40; i += 256) {
        int c = i / 40, t = i - (i/40)*40;
        float lo, hi;
        if (t < 4)      { lo = wq[(2*t)*Cc + c];       hi = wq[(2*t+1)*Cc + c]; }
        else if (t < 8) { lo = wk[(2*(t-4))*Cc + c];   hi = wk[(2*(t-4)+1)*Cc + c]; }
        else            { lo = wv[(2*(t-8))*Cc + c];   hi = wv[(2*(t-8)+1)*Cc + c]; }
        ws2[i] = packf2(lo, hi);
    }
    if (tid < 40) {
        int t = tid; float lo, hi;
        if (t < 4)      { lo = bq[2*t];       hi = bq[2*t+1]; }
        else if (t < 8) { lo = bk[2*(t-4)];   hi = bk[2*(t-4)+1]; }
        else            { lo = bv[2*(t-8)];   hi = bv[2*(t-8)+1]; }
        bs2[t] = packf2(lo, hi);
    }
    __syncthreads();
    int p = blockIdx.x*256 + tid;               // Bz*HW exact
    int b = p >> 16, hw = p & 65535;
    const float* xb = x + (size_t)b*Cc*HW + hw;
    unsigned long long acc[40];
#pragma unroll
    for (int t = 0; t < 40; t++) acc[t] = bs2[t];
    for (int c = 0; c < Cc; c++) {
        float xv = __ldg(xb + (size_t)c*HW);
        unsigned long long xx = packf2(xv, xv);
        const unsigned long long* w = ws2 + c*40;
#pragma unroll
        for (int t = 0; t < 40; t++) acc[t] = fma2(xx, w[t], acc[t]);
    }
    float* qo = q + (size_t)b*CQ*HW + hw;
    float* ko = k + (size_t)b*CQ*HW + hw;
    float* vo = v + (size_t)b*Cc*HW + hw;
#pragma unroll
    for (int t = 0; t < 4; t++) {
        float2 r = unpackf2(acc[t]);
        qo[(size_t)(2*t)*HW] = r.x; qo[(size_t)(2*t+1)*HW] = r.y;
    }
#pragma unroll
    for (int t = 4; t < 8; t++) {
        float2 r = unpackf2(acc[t]);
        ko[(size_t)(2*(t-4))*HW] = r.x; ko[(size_t)(2*(t-4)+1)*HW] = r.y;
    }
#pragma unroll
    for (int t = 8; t < 40; t++) {
        float2 r = unpackf2(acc[t]);
        vo[(size_t)(2*(t-8))*HW] = r.x; vo[(size_t)(2*(t-8)+1)*HW] = r.y;
    }
}

// ---------------- softmax stats (online, no energy buffer) ----------------
// MODE 0: column direction (eH, diag masked). Writes per-pixel (max, sum).
// MODE 1: row direction (eW); merges with MODE-0 stats -> (combined max, 1/total sum).
// z = 0: q2/k1 (att1 path), z = 1: q1/k2 (att2 path).
template<int MODE>
__global__ __launch_bounds__(256) void stat_kernel(
    const float* __restrict__ qA, const float* __restrict__ kA,
    const float* __restrict__ qB, const float* __restrict__ kB,
    float* __restrict__ m0, float* __restrict__ s0,
    float* __restrict__ m1, float* __restrict__ s1) {
    __shared__ float qsT[256*12];
    __shared__ float ksT[256*12];
    int b = blockIdx.y, o = blockIdx.x, z = blockIdx.z;
    const float* q = z ? qB : qA;
    const float* k = z ? kB : kA;
    float* mOut = z ? m1 : m0;
    float* sOut = z ? s1 : s0;
    size_t bq = (size_t)b*CQ*HW;
    for (int i = threadIdx.x; i < CQ*256; i += 256) {
        int c = i >> 8, r = i & 255;
        size_t idx = MODE ? bq + (size_t)c*HW + (size_t)o*Ww + r
                          : bq + (size_t)c*HW + (size_t)r*Ww + o;
        qsT[r*12 + c] = q[idx];
        ksT[r*12 + c] = k[idx];
    }
    __syncthreads();
    int lane = threadIdx.x & 31, wid = threadIdx.x >> 5;
    for (int r = wid; r < 256; r += 8) {
        const float4* qp = (const float4*)(qsT + r*12);
        float4 qa = qp[0], qb = qp[1];
        float e[8];
        float mx = -1e30f;
#pragma unroll
        for (int jj = 0; jj < 8; jj++) {
            int j = lane + jj*32;
            const float4* kp = (const float4*)(ksT + j*12);
            float4 ka = kp[0], kb = kp[1];
            float acc = qa.x*ka.x + qa.y*ka.y + qa.z*ka.z + qa.w*ka.w
                      + qb.x*kb.x + qb.y*kb.y + qb.z*kb.z + qb.w*kb.w;
            if (MODE == 0 && j == r) acc = -1e30f;
            e[jj] = acc;
            mx = fmaxf(mx, acc);
        }
#pragma unroll
        for (int s = 16; s > 0; s >>= 1) mx = fmaxf(mx, __shfl_xor_sync(0xffffffffu, mx, s));
        float sum = 0.f;
#pragma unroll
        for (int jj = 0; jj < 8; jj++) sum += __expf(e[jj] - mx);
#pragma unroll
        for (int s = 16; s > 0; s >>= 1) sum += __shfl_xor_sync(0xffffffffu, sum, s);
        if (lane == 0) {
            int hw = MODE ? o*Ww + r : r*Ww + o;
            size_t pix = (size_t)b*HW + hw;
            if (MODE == 0) {
                mOut[pix] = mx;
                sOut[pix] = sum;
            } else {
                float mh = mOut[pix], sh = sOut[pix];
                float mc = fmaxf(mh, mx);
                float stot = sh*__expf(mh - mc) + sum*__expf(mx - mc);
                mOut[pix] = mc;
                sOut[pix] = 1.f/stot;
            }
        }
    }
}

// ---------------- fused aggregation: energies recomputed, FFMA2 accumulation ----------------
// MODE 0: outH per (b,w): out[c,h,w] = sum_g A[h,g] v[c,g,w]  (writes '=')
// MODE 1: outW per (b,h): out[c,h,w] += sum_v A[w,v] v[c,h,v] (accumulates '+=')
#define VROW 68
#define AGG_SMEM ((256*VROW + 32*257 + 2*256*12)*4)
template<int MODE>
__global__ __launch_bounds__(256) void agg_kernel(
    const float* __restrict__ qA, const float* __restrict__ kA,
    const float* __restrict__ vA, float* __restrict__ outA,
    const float* __restrict__ qB, const float* __restrict__ kB,
    const float* __restrict__ vB, float* __restrict__ outB,
    const float* __restrict__ m0, const float* __restrict__ s0,
    const float* __restrict__ m1, const float* __restrict__ s1) {
    extern __shared__ float sm[];
    float* Vsm = sm;                      // 256 x VROW
    float* Asm = sm + 256*VROW;           // 32 x 257
    float* qsT = Asm + 32*257;            // 256 x 12
    float* ksT = qsT + 256*12;            // 256 x 12
    int b = blockIdx.y, o = blockIdx.x, z = blockIdx.z;
    const float* q = z ? qB : qA;
    const float* k = z ? kB : kA;
    const float* v = z ? vB : vA;
    float* out = z ? outB : outA;
    const float* mm = z ? m1 : m0;
    const float* ss = z ? s1 : s0;
    int tid = threadIdx.x;
    size_t vb = (size_t)b*Cc*HW;
    size_t bq = (size_t)b*CQ*HW;
    for (int i = tid; i < Cc*256; i += 256) {
        int c = i >> 8, g = i & 255;
        Vsm[g*VROW + c] = MODE ? v[vb + (size_t)c*HW + (size_t)o*Ww + g]
                               : v[vb + (size_t)c*HW + (size_t)g*Ww + o];
    }
    for (int i = tid; i < CQ*256; i += 256) {
        int c = i >> 8, r = i & 255;
        size_t idx = MODE ? bq + (size_t)c*HW + (size_t)o*Ww + r
                          : bq + (size_t)c*HW + (size_t)r*Ww + o;
        qsT[r*12 + c] = q[idx];
        ksT[r*12 + c] = k[idx];
    }
    __syncthreads();
    int lane = tid & 31, wid = tid >> 5;
    const double2* Vp = reinterpret_cast<const double2*>(Vsm + wid*8);
    for (int r0 = 0; r0 < 256; r0 += 32) {
        // --- compute A tile (32 rows x 256) on the fly ---
#pragma unroll
        for (int i = 0; i < 4; i++) {
            int rr = wid*4 + i;
            int r = r0 + rr;
            const float4* qp = (const float4*)(qsT + r*12);
            float4 qa = qp[0], qb = qp[1];
            int hw = MODE ? o*Ww + r : r*Ww + o;
            size_t pix = (size_t)b*HW + hw;
            float mr = mm[pix], isr = ss[pix];
#pragma unroll
            for (int jj = 0; jj < 8; jj++) {
                int j = lane + jj*32;
                const float4* kp = (const float4*)(ksT + j*12);
                float4 ka = kp[0], kb = kp[1];
                float acc = qa.x*ka.x + qa.y*ka.y + qa.z*ka.z + qa.w*ka.w
                          + qb.x*kb.x + qb.y*kb.y + qb.z*kb.z + qb.w*kb.w;
                float a = (MODE == 0 && j == r) ? 0.f : __expf(acc - mr)*isr;
                Asm[rr*257 + j] = a;
            }
        }
        __syncthreads();
        // --- A(32x256) x V(256x64) with packed f32x2 FMAs ---
        unsigned long long acc0 = 0ull, acc1 = 0ull, acc2 = 0ull, acc3 = 0ull;
        const float* ar = Asm + lane*257;
#pragma unroll 8
        for (int g = 0; g < 256; g++) {
            float a = ar[g];
            unsigned long long aa = packf2(a, a);
            double2 v0 = Vp[g*17];
            double2 v1 = Vp[g*17 + 1];
            acc0 = fma2(aa, __double_as_longlong(v0.x), acc0);
            acc1 = fma2(aa, __double_as_longlong(v0.y), acc1);
            acc2 = fma2(aa, __double_as_longlong(v1.x), acc2);
            acc3 = fma2(aa, __double_as_longlong(v1.y), acc3);
        }
        int r = r0 + lane;
        int c0 = wid*8;
        float2 p0 = unpackf2(acc0), p1 = unpackf2(acc1);
        float2 p2 = unpackf2(acc2), p3 = unpackf2(acc3);
        float vals[8] = {p0.x,p0.y,p1.x,p1.y,p2.x,p2.y,p3.x,p3.y};
        if (MODE == 0) {
            size_t ob = vb + (size_t)c0*HW + (size_t)r*Ww + o;
#pragma unroll
            for (int j2 = 0; j2 < 8; j2++) out[ob + (size_t)j2*HW] = vals[j2];
        } else {
            size_t ob = vb + (size_t)c0*HW + (size_t)o*Ww + r;
#pragma unroll
            for (int j2 = 0; j2 < 8; j2++) out[ob + (size_t)j2*HW] += vals[j2];
        }
        __syncthreads();
    }
}

// ---------------- pooling: per (b,c) mean/max of s1, s2 ----------------
__global__ void pool_kernel(const float* __restrict__ att1, const float* __restrict__ att2,
                            const float* __restrict__ x1, const float* __restrict__ x2,
                            const float* __restrict__ gamma1, const float* __restrict__ gamma2,
                            float* __restrict__ pool) {
    int c = blockIdx.x, b = blockIdx.y, tid = threadIdx.x;
    size_t base = ((size_t)b*Cc + c)*HW;
    float g1 = gamma1[0], g2 = gamma2[0];
    float sum1 = 0.f, sum2 = 0.f, mx1 = -1e30f, mx2 = -1e30f;
    for (int i = tid; i < HW; i += 256) {
        float a1 = att1[base+i], a2 = att2[base+i], xa = x1[base+i], xb = x2[base+i];
        float s1 = g2*a2 + xb + xa;
        float s2 = g1*a1 + xa + xb;
        sum1 += s1; sum2 += s2;
        mx1 = fmaxf(mx1, s1); mx2 = fmaxf(mx2, s2);
    }
    __shared__ float red[4][256];
    red[0][tid] = sum1; red[1][tid] = sum2; red[2][tid] = mx1; red[3][tid] = mx2;
    __syncthreads();
    for (int s = 128; s > 0; s >>= 1) {
        if (tid < s) {
            red[0][tid] += red[0][tid+s];
            red[1][tid] += red[1][tid+s];
            red[2][tid] = fmaxf(red[2][tid], red[2][tid+s]);
            red[3][tid] = fmaxf(red[3][tid], red[3][tid+s]);
        }
        __syncthreads();
    }
    if (tid == 0) {
        pool[(0*Bz + b)*Cc + c] = red[0][0]*(1.f/HW);
        pool[(1*Bz + b)*Cc + c] = red[2][0];
        pool[(2*Bz + b)*Cc + c] = red[1][0]*(1.f/HW);
        pool[(3*Bz + b)*Cc + c] = red[3][0];
    }
}

// ---------------- tiny gate MLP: sigmoid(mlp(mean)+mlp(max)) per branch/b/c ----------------
__global__ void gate_kernel(const float* __restrict__ w1a, const float* __restrict__ b1a,
                            const float* __restrict__ w2a, const float* __restrict__ b2a,
                            const float* __restrict__ w1b, const float* __restrict__ b1b,
                            const float* __restrict__ w2b, const float* __restrict__ b2b,
                            const float* __restrict__ pool, float* __restrict__ gate) {
    __shared__ float hid[2][Bz][2][CRr];
    int tid = threadIdx.x;
    if (tid < 2*Bz*2*CRr) {
        int r  = tid & (CRr-1);
        int mm = (tid >> 2) & 1;
        int bb = (tid >> 3) & 1;
        int br = (tid >> 4) & 1;
        const float* w1 = br ? w1b : w1a;
        const float* b1 = br ? b1b : b1a;
        const float* p = pool + ((size_t)(br*2 + mm)*Bz + bb)*Cc;
        float acc = b1[r];
        for (int c = 0; c < Cc; c++) acc += w1[r*Cc + c]*p[c];
        hid[br][bb][mm][r] = fmaxf(acc, 0.f);
    }
    __syncthreads();
    int c = tid & 63, bb = (tid >> 6) & 1, br = tid >> 7;
    const float* w2 = br ? w2b : w2a;
    const float* b2 = br ? b2b : b2a;
    float o = 2.f*b2[c];
    for (int mm = 0; mm < 2; mm++)
#pragma unroll
        for (int r = 0; r < CRr; r++) o += w2[c*CRr + r]*hid[br][bb][mm][r];
    gate[(br*Bz + bb)*Cc + c] = 1.f/(1.f + expf(-o));
}

// ---------------- t = gate*s + x (odd channels only) + per-channel BN partial sums ----------------
__global__ void bnsum_kernel(const float* __restrict__ att1, const float* __restrict__ att2,
                             const float* __restrict__ x1, const float* __restrict__ x2,
                             const float* __restrict__ gamma1, const float* __restrict__ gamma2,
                             const float* __restrict__ gate,
                             float* __restrict__ t1, float* __restrict__ t2,
                             float* __restrict__ part) {
    int c = blockIdx.x*2 + 1;                     // odd channels only (even copy x directly)
    int b = blockIdx.y, tid = threadIdx.x;
    size_t base = ((size_t)b*Cc + c)*HW;
    float g1 = gamma1[0], g2 = gamma2[0];
    float gt1 = gate[(0*Bz + b)*Cc + c];
    float gt2 = gate[(1*Bz + b)*Cc + c];
    float s1s = 0.f, s1q = 0.f, s2s = 0.f, s2q = 0.f;
    for (int i = tid; i < HW; i += 256) {
        float a1 = att1[base+i], a2 = att2[base+i], xa = x1[base+i], xb = x2[base+i];
        float s1 = g2*a2 + xb + xa;
        float v1 = gt1*s1 + xa;
        t1[base+i] = v1; s1s += v1; s1q += v1*v1;
        float s2 = g1*a1 + xa + xb;
        float v2 = gt2*s2 + xb;
        t2[base+i] = v2; s2s += v2; s2q += v2*v2;
    }
    __shared__ float red[4][256];
    red[0][tid] = s1s; red[1][tid] = s1q; red[2][tid] = s2s; red[3][tid] = s2q;
    __syncthreads();
    for (int s = 128; s > 0; s >>= 1) {
        if (tid < s)
            for (int kk = 0; kk < 4; kk++) red[kk][tid] += red[kk][tid+s];
        __syncthreads();
    }
    if (tid == 0) {
        part[((0*Cc + c)*Bz + b)*2 + 0] = red[0][0];
        part[((0*Cc + c)*Bz + b)*2 + 1] = red[1][0];
        part[((1*Cc + c)*Bz + b)*2 + 0] = red[2][0];
        part[((1*Cc + c)*Bz + b)*2 + 1] = red[3][0];
    }
}

__global__ void bnstat_kernel(const float* __restrict__ part, float* __restrict__ stat) {
    int tid = threadIdx.x;                 // 128 threads: [branch(2)][c(64)]
    int br = tid >> 6, c = tid & 63;
    if (!(c & 1)) return;
    float s = 0.f, q = 0.f;
    for (int b = 0; b < Bz; b++) {
        s += part[((br*Cc + c)*Bz + b)*2 + 0];
        q += part[((br*Cc + c)*Bz + b)*2 + 1];
    }
    float N = (float)(Bz*HW);
    float m = s/N;
    float var = q/N - m*m;
    stat[(br*Cc + c)*2 + 0] = m;
    stat[(br*Cc + c)*2 + 1] = rsqrtf(var + 1e-5f);
}

// ---------------- finalize: BN+relu on odd channels, copy x on even ----------------
__global__ void final_kernel(const float* __restrict__ x1, const float* __restrict__ x2,
                             const float* __restrict__ t1, const float* __restrict__ t2,
                             const float* __restrict__ stat,
                             const float* __restrict__ sc1, const float* __restrict__ bi1,
                             const float* __restrict__ sc2, const float* __restrict__ bi2,
                             float* __restrict__ out) {
    size_t n = (size_t)blockIdx.x*256 + threadIdx.x;   // BCHW exact
    int c = (int)((n / HW) & 63);
    float o1, o2;
    if ((c & 1) == 0) {
        o1 = x1[n]; o2 = x2[n];
    } else {
        float m1 = stat[(0*Cc + c)*2], is1 = stat[(0*Cc + c)*2 + 1];
        o1 = fmaxf((t1[n] - m1)*is1*sc1[c] + bi1[c], 0.f);
        float m2 = stat[(1*Cc + c)*2], is2 = stat[(1*Cc + c)*2 + 1];
        o2 = fmaxf((t2[n] - m2)*is2*sc2[c] + bi2[c], 0.f);
    }
    out[n] = o1;
    out[(size_t)BCHW + n] = o2;
}

// ---------------- host launch ----------------
extern "C" void kernel_launch(void* const* d_in, const int* in_sizes, int n_in,
                              void* d_out, int out_size) {
    const float* x1  = (const float*)d_in[0];
    const float* x2  = (const float*)d_in[1];
    const float* wq1 = (const float*)d_in[2];
    const float* bq1 = (const float*)d_in[3];
    const float* wq2 = (const float*)d_in[4];
    const float* bq2 = (const float*)d_in[5];
    const float* wk1 = (const float*)d_in[6];
    const float* bk1 = (const float*)d_in[7];
    const float* wk2 = (const float*)d_in[8];
    const float* bk2 = (const float*)d_in[9];
    const float* wv1 = (const float*)d_in[10];
    const float* bv1 = (const float*)d_in[11];
    const float* wv2 = (const float*)d_in[12];
    const float* bv2 = (const float*)d_in[13];
    const float* gamma1 = (const float*)d_in[14];
    const float* gamma2 = (const float*)d_in[15];
    const float* sc1_w1 = (const float*)d_in[16];
    const float* sc1_b1 = (const float*)d_in[17];
    const float* sc1_w2 = (const float*)d_in[18];
    const float* sc1_b2 = (const float*)d_in[19];
    const float* sc2_w1 = (const float*)d_in[20];
    const float* sc2_b1 = (const float*)d_in[21];
    const float* sc2_w2 = (const float*)d_in[22];
    const float* sc2_b2 = (const float*)d_in[23];
    const float* bn1_scale = (const float*)d_in[24];
    const float* bn1_bias  = (const float*)d_in[25];
    const float* bn2_scale = (const float*)d_in[26];
    const float* bn2_bias  = (const float*)d_in[27];

    float *q1, *q2, *k1, *k2, *v1, *v2, *m0, *s0, *m1, *s1;
    float *att1, *att2, *t1, *t2, *pool, *gate, *part, *stat;
    cudaGetSymbolAddress((void**)&q1, g_q1);
    cudaGetSymbolAddress((void**)&q2, g_q2);
    cudaGetSymbolAddress((void**)&k1, g_k1);
    cudaGetSymbolAddress((void**)&k2, g_k2);
    cudaGetSymbolAddress((void**)&v1, g_v1);
    cudaGetSymbolAddress((void**)&v2, g_v2);
    cudaGetSymbolAddress((void**)&m0, g_m0);
    cudaGetSymbolAddress((void**)&s0, g_s0);
    cudaGetSymbolAddress((void**)&m1, g_m1);
    cudaGetSymbolAddress((void**)&s1, g_s1);
    cudaGetSymbolAddress((void**)&att1, g_att1);
    cudaGetSymbolAddress((void**)&att2, g_att2);
    cudaGetSymbolAddress((void**)&t1, g_t1);
    cudaGetSymbolAddress((void**)&t2, g_t2);
    cudaGetSymbolAddress((void**)&pool, g_pool);
    cudaGetSymbolAddress((void**)&gate, g_gate);
    cudaGetSymbolAddress((void**)&part, g_part);
    cudaGetSymbolAddress((void**)&stat, g_stat);

    cudaFuncSetAttribute(agg_kernel<0>, cudaFuncAttributeMaxDynamicSharedMemorySize, AGG_SMEM);
    cudaFuncSetAttribute(agg_kernel<1>, cudaFuncAttributeMaxDynamicSharedMemorySize, AGG_SMEM);

    // fused projections (one read of each x)
    proj_kernel<<<512, 256>>>(x1, wq1, bq1, wk1, bk1, wv1, bv1, q1, k1, v1);
    proj_kernel<<<512, 256>>>(x2, wq2, bq2, wk2, bk2, wv2, bv2, q2, k2, v2);

    // online softmax stats for both criss-crosses (z=0: q2/k1, z=1: q1/k2)
    stat_kernel<0><<<dim3(Ww, Bz, 2), 256>>>(q2, k1, q1, k2, m0, s0, m1, s1);
    stat_kernel<1><<<dim3(Hh, Bz, 2), 256>>>(q2, k1, q1, k2, m0, s0, m1, s1);

    // fused aggregation (energies recomputed on the fly; FFMA2 inner loop)
    agg_kernel<0><<<dim3(Ww, Bz, 2), 256, AGG_SMEM>>>(q2, k1, v1, att1,
                                                      q1, k2, v2, att2,
                                                      m0, s0, m1, s1);
    agg_kernel<1><<<dim3(Hh, Bz, 2), 256, AGG_SMEM>>>(q2, k1, v1, att1,
                                                      q1, k2, v2, att2,
                                                      m0, s0, m1, s1);

    // ShareCA pooling + gates
    pool_kernel<<<dim3(Cc, Bz), 256>>>(att1, att2, x1, x2, gamma1, gamma2, pool);
    gate_kernel<<<1, 256>>>(sc1_w1, sc1_b1, sc1_w2, sc1_b2,
                            sc2_w1, sc2_b1, sc2_w2, sc2_b2, pool, gate);

    // BN stats (odd channels) + finalize
    bnsum_kernel<<<dim3(Cc/2, Bz), 256>>>(att1, att2, x1, x2, gamma1, gamma2, gate, t1, t2, part);
    bnstat_kernel<<<1, 128>>>(part, stat);
    final_kernel<<<BCHW/256, 256>>>(x1, x2, t1, t2, stat,
                                    bn1_scale, bn1_bias, bn2_scale, bn2_bias, (float*)d_out);
}

// round 4
// speedup vs baseline: 1.1993x; 1.1296x over previous
#include <cuda_runtime.h>
#include <math.h>

#define Bz 2
#define Cc 64
#define CQ 8
#define CRr 4
#define HWi 65536
#define BCHW (Bz*Cc*HWi)      // 8388608

// plane offsets (in planes of 65536 floats) inside g_qkv / g_qkvT
#define PQ1 0
#define PQ2 16
#define PK1 32
#define PK2 48
#define PV1 64
#define PV2 192
#define NPLANES 320

// ---------------- scratch (device globals) ----------------
__device__ float g_qkv [NPLANES*HWi];
__device__ float g_qkvT[NPLANES*HWi];
__device__ float g_mW [2*Bz*HWi];
__device__ float g_sW [2*Bz*HWi];
__device__ float g_mHT[2*Bz*HWi];
__device__ float g_sHT[2*Bz*HWi];
__device__ float g_fH [2*Bz*HWi];
__device__ float g_fW [2*Bz*HWi];
__device__ float g_attHT[2*BCHW];
__device__ float g_attW [2*BCHW];
__device__ float g_s1[BCHW];
__device__ float g_s2[BCHW];
__device__ float g_pp[12*Bz*Cc*8];    // [stat][b][c][slice]
__device__ float g_gate[2*Bz*Cc];
__device__ float g_stat[2*Cc*2];

// ---------------- packed f32x2 helpers ----------------
__device__ __forceinline__ unsigned long long fma2(unsigned long long a, unsigned long long b,
                                                   unsigned long long c) {
    unsigned long long d;
    asm("fma.rn.f32x2 %0, %1, %2, %3;" : "=l"(d) : "l"(a), "l"(b), "l"(c));
    return d;
}
__device__ __forceinline__ unsigned long long packf2(float lo, float hi) {
    unsigned long long r;
    asm("mov.b64 %0, {%1, %2};" : "=l"(r) : "f"(lo), "f"(hi));
    return r;
}
__device__ __forceinline__ float2 unpackf2(unsigned long long a) {
    float2 r;
    asm("mov.b64 {%0, %1}, %2;" : "=f"(r.x), "=f"(r.y) : "l"(a));
    return r;
}

// ---------------- fused projection: x -> q(8), k(8), v(64) ----------------
__global__ __launch_bounds__(256) void proj_kernel(
    const float* __restrict__ x,
    const float* __restrict__ wq, const float* __restrict__ bq,
    const float* __restrict__ wk, const float* __restrict__ bk,
    const float* __restrict__ wv, const float* __restrict__ bv,
    float* __restrict__ q, float* __restrict__ k, float* __restrict__ v) {
    __shared__ unsigned long long ws2[64*40];
    __shared__ unsigned long long bs2[40];
    int tid = threadIdx.x;
    for (int i = tid; i < 64*40; i += 256) {
        int c = i / 40, t = i - (i/40)*40;
        float lo, hi;
        if (t < 4)      { lo = wq[(2*t)*Cc + c];       hi = wq[(2*t+1)*Cc + c]; }
        else if (t < 8) { lo = wk[(2*(t-4))*Cc + c];   hi = wk[(2*(t-4)+1)*Cc + c]; }
        else            { lo = wv[(2*(t-8))*Cc + c];   hi = wv[(2*(t-8)+1)*Cc + c]; }
        ws2[i] = packf2(lo, hi);
    }
    if (tid < 40) {
        int t = tid; float lo, hi;
        if (t < 4)      { lo = bq[2*t];       hi = bq[2*t+1]; }
        else if (t < 8) { lo = bk[2*(t-4)];   hi = bk[2*(t-4)+1]; }
        else            { lo = bv[2*(t-8)];   hi = bv[2*(t-8)+1]; }
        bs2[t] = packf2(lo, hi);
    }
    __syncthreads();
    int p = blockIdx.x*256 + tid;               // Bz*HW exact
    int b = p >> 16, hw = p & 65535;
    const float* xb = x + (size_t)b*Cc*HWi + hw;
    unsigned long long acc[40];
#pragma unroll
    for (int t = 0; t < 40; t++) acc[t] = bs2[t];
    for (int c = 0; c < Cc; c++) {
        float xv = __ldg(xb + (size_t)c*HWi);
        unsigned long long xx = packf2(xv, xv);
        const unsigned long long* w = ws2 + c*40;
#pragma unroll
        for (int t = 0; t < 40; t++) acc[t] = fma2(xx, w[t], acc[t]);
    }
    float* qo = q + (size_t)b*CQ*HWi + hw;
    float* ko = k + (size_t)b*CQ*HWi + hw;
    float* vo = v + (size_t)b*Cc*HWi + hw;
#pragma unroll
    for (int t = 0; t < 4; t++) {
        float2 r = unpackf2(acc[t]);
        qo[(size_t)(2*t)*HWi] = r.x; qo[(size_t)(2*t+1)*HWi] = r.y;
    }
#pragma unroll
    for (int t = 4; t < 8; t++) {
        float2 r = unpackf2(acc[t]);
        ko[(size_t)(2*(t-4))*HWi] = r.x; ko[(size_t)(2*(t-4)+1)*HWi] = r.y;
    }
#pragma unroll
    for (int t = 8; t < 40; t++) {
        float2 r = unpackf2(acc[t]);
        vo[(size_t)(2*(t-8))*HWi] = r.x; vo[(size_t)(2*(t-8)+1)*HWi] = r.y;
    }
}

// ---------------- tiled per-plane transpose ----------------
__global__ __launch_bounds__(256) void transpose_kernel(const float* __restrict__ src,
                                                        float* __restrict__ dst) {
    __shared__ float sm[32][33];
    int plane = blockIdx.y;
    int t = blockIdx.x;                     // 64 tiles
    int h0 = (t >> 3)*32, w0 = (t & 7)*32;
    const float* sp = src + (size_t)plane*HWi;
    float* dp = dst + (size_t)plane*HWi;
    int lx = threadIdx.x & 31, ly = threadIdx.x >> 5;
#pragma unroll
    for (int i = 0; i < 4; i++) {
        int hl = ly*4 + i;
        sm[hl][lx] = sp[(h0+hl)*256 + w0 + lx];
    }
    __syncthreads();
#pragma unroll
    for (int i = 0; i < 4; i++) {
        int wl = ly*4 + i;
        dp[(w0+wl)*256 + h0 + lx] = sm[lx][wl];
    }
}

// ---------------- per-direction softmax stats ----------------
// One template serves both directions: normal arrays -> W-direction stats,
// transposed arrays -> H-direction stats (DIAG masks the diagonal).
template<bool DIAG>
__global__ __launch_bounds__(256) void stat_kernel(
    const float* __restrict__ qA, const float* __restrict__ kA,
    const float* __restrict__ qB, const float* __restrict__ kB,
    float* __restrict__ mOut, float* __restrict__ sOut) {
    __shared__ float qs[256*12];
    __shared__ float ks[256*12];
    int o = blockIdx.x, b = blockIdx.y, z = blockIdx.z;
    const float* q = z ? qB : qA;
    const float* k = z ? kB : kA;
    size_t bq = (size_t)b*CQ*HWi + (size_t)o*256;
    for (int i = threadIdx.x; i < CQ*256; i += 256) {
        int c = i >> 8, r = i & 255;
        qs[r*12 + c] = q[bq + (size_t)c*HWi + r];
        ks[r*12 + c] = k[bq + (size_t)c*HWi + r];
    }
    __syncthreads();
    int lane = threadIdx.x & 31, wid = threadIdx.x >> 5;
    size_t obase = ((size_t)z*Bz + b)*HWi + o*256;
    for (int r = wid; r < 256; r += 8) {
        float4 qa = *(const float4*)(qs + r*12);
        float4 qb = *(const float4*)(qs + r*12 + 4);
        float e[8]; float mx = -1e30f;
#pragma unroll
        for (int jj = 0; jj < 8; jj++) {
            int j = lane + jj*32;
            float4 ka = *(const float4*)(ks + j*12);
            float4 kb = *(const float4*)(ks + j*12 + 4);
            float acc = qa.x*ka.x + qa.y*ka.y + qa.z*ka.z + qa.w*ka.w
                      + qb.x*kb.x + qb.y*kb.y + qb.z*kb.z + qb.w*kb.w;
            if (DIAG && j == r) acc = -1e30f;
            e[jj] = acc; mx = fmaxf(mx, acc);
        }
#pragma unroll
        for (int s = 16; s > 0; s >>= 1) mx = fmaxf(mx, __shfl_xor_sync(0xffffffffu, mx, s));
        float sum = 0.f;
#pragma unroll
        for (int jj = 0; jj < 8; jj++) sum += __expf(e[jj] - mx);
#pragma unroll
        for (int s = 16; s > 0; s >>= 1) sum += __shfl_xor_sync(0xffffffffu, sum, s);
        if (lane == 0) {
            mOut[obase + r] = mx;
            sOut[obase + r] = sum;
        }
    }
}

// ---------------- merge factors ----------------
__global__ void factor_kernel(const float* __restrict__ mHT, const float* __restrict__ sHT,
                              const float* __restrict__ mW, const float* __restrict__ sW,
                              float* __restrict__ fH, float* __restrict__ fW) {
    int p = blockIdx.x*256 + threadIdx.x;
    int b = blockIdx.y, z = blockIdx.z;
    size_t zb = ((size_t)z*Bz + b)*HWi;
    int h = p >> 8, w = p & 255;
    float mh = mHT[zb + w*256 + h], sh = sHT[zb + w*256 + h];
    float mw = mW[zb + p],          sw = sW[zb + p];
    float m = fmaxf(mh, mw);
    float eh = __expf(mh - m), ew = __expf(mw - m);
    float inv = 1.f/(sh*eh + sw*ew);
    fH[zb + p] = eh*inv;
    fW[zb + p] = ew*inv;
}

// ---------------- aggregation: C(128x64) = A(128x256) x V(256x64) per (b,o,half,z) ----------------
// Same kernel for both directions: feed (q,k,v,m,out) normal for W-dir, transposed for H-dir.
// A recomputed on the fly, stored as duplicated pairs for direct FFMA2 operands.
#define AGG_SMEM ((32*128*2 + 32*68 + 128*12 + 256*12 + 128)*4)
template<bool DIAG>
__global__ __launch_bounds__(256,2) void agg_kernel(
    const float* __restrict__ qA, const float* __restrict__ kA,
    const float* __restrict__ vA, float* __restrict__ outA,
    const float* __restrict__ qB, const float* __restrict__ kB,
    const float* __restrict__ vB, float* __restrict__ outB,
    const float* __restrict__ mArr) {
    extern __shared__ float sm[];
    float* Adup = sm;                    // 32 cols x 128 rows, dup pairs (8192 floats)
    float* Vsm  = sm + 8192;             // 32 x 68
    float* qs   = Vsm + 32*68;           // 128 x 12
    float* ks   = qs + 128*12;           // 256 x 12
    float* msm  = ks + 256*12;           // 128
    int o = blockIdx.x;
    int b = blockIdx.y & 1, half = blockIdx.y >> 1;
    int z = blockIdx.z;
    const float* q = z ? qB : qA;
    const float* k = z ? kB : kA;
    const float* v = z ? vB : vA;
    float* out = z ? outB : outA;
    int tid = threadIdx.x;
    size_t lineQ = (size_t)b*CQ*HWi + (size_t)o*256;
    size_t lineV = (size_t)b*Cc*HWi + (size_t)o*256;
    for (int i = tid; i < CQ*256; i += 256) {
        int c = i >> 8, r = i & 255;
        ks[r*12 + c] = k[lineQ + (size_t)c*HWi + r];
    }
    for (int i = tid; i < CQ*128; i += 256) {
        int c = i >> 7, r = i & 127;
        qs[r*12 + c] = q[lineQ + (size_t)c*HWi + half*128 + r];
    }
    if (tid < 128)
        msm[tid] = mArr[((size_t)z*Bz + b)*HWi + o*256 + half*128 + tid];

    int tcol = tid & 3, trow = tid >> 2;     // trow 0..63 -> rows trow, trow+64
    int rl = tid & 31, jg = tid >> 5;
    unsigned long long acc[16];
#pragma unroll
    for (int i = 0; i < 16; i++) acc[i] = 0ull;

    for (int g0 = 0; g0 < 256; g0 += 32) {
        __syncthreads();
        // stage V chunk: Vsm[gg][c]
        for (int i = tid; i < 32*64; i += 256) {
            int c = i >> 5, gg = i & 31;
            Vsm[gg*68 + c] = v[lineV + (size_t)c*HWi + g0 + gg];
        }
        // compute A chunk (exp(e - m)), duplicated pairs
#pragma unroll
        for (int rp = 0; rp < 4; rp++) {
            int r = rp*32 + rl;
            float4 qa = *(const float4*)(qs + r*12);
            float4 qb = *(const float4*)(qs + r*12 + 4);
            float mr = msm[r];
#pragma unroll
            for (int jj = 0; jj < 4; jj++) {
                int j = jg*4 + jj;
                int g = g0 + j;
                float4 ka = *(const float4*)(ks + g*12);
                float4 kb = *(const float4*)(ks + g*12 + 4);
                float e = qa.x*ka.x + qa.y*ka.y + qa.z*ka.z + qa.w*ka.w
                        + qb.x*kb.x + qb.y*kb.y + qb.z*kb.z + qb.w*kb.w;
                float a = __expf(e - mr);
                if (DIAG && g == half*128 + r) a = 0.f;
                *(float2*)(Adup + (j*128 + r)*2) = make_float2(a, a);
            }
        }
        __syncthreads();
        const double*  Ad = (const double*)Adup;   // pair (j,r) at idx j*128+r
        const double2* Vd = (const double2*)Vsm;   // (gg, 4ch) at gg*17 + tcol*4 + jj
#pragma unroll 8
        for (int gg = 0; gg < 32; gg++) {
            unsigned long long a0 = __double_as_longlong(Ad[gg*128 + trow]);
            unsigned long long a1 = __double_as_longlong(Ad[gg*128 + trow + 64]);
#pragma unroll
            for (int jj = 0; jj < 4; jj++) {
                double2 vv = Vd[gg*17 + tcol*4 + jj];
                unsigned long long v0 = __double_as_longlong(vv.x);
                unsigned long long v1 = __double_as_longlong(vv.y);
                acc[jj*2+0]   = fma2(a0, v0, acc[jj*2+0]);
                acc[jj*2+1]   = fma2(a0, v1, acc[jj*2+1]);
                acc[8+jj*2+0] = fma2(a1, v0, acc[8+jj*2+0]);
                acc[8+jj*2+1] = fma2(a1, v1, acc[8+jj*2+1]);
            }
        }
    }
    size_t outBase = (size_t)b*Cc*HWi + (size_t)o*256 + half*128;
#pragma unroll
    for (int rr = 0; rr < 2; rr++) {
        int h = trow + rr*64;
#pragma unroll
        for (int pp = 0; pp < 8; pp++) {
            float2 val = unpackf2(acc[rr*8 + pp]);
            int c = tcol*16 + pp*2;
            out[outBase + (size_t)c*HWi + h]     = val.x;
            out[outBase + (size_t)(c+1)*HWi + h] = val.y;
        }
    }
}

// ---------------- merge: transpose H-dir output, combine, emit s planes ----------------
__global__ __launch_bounds__(256) void merge_kernel(
    const float* __restrict__ attHT, const float* __restrict__ attW,
    const float* __restrict__ fH, const float* __restrict__ fW,
    const float* __restrict__ x1, const float* __restrict__ x2,
    const float* __restrict__ gamma1, const float* __restrict__ gamma2,
    float* __restrict__ s1, float* __restrict__ s2) {
    __shared__ float sm1[32][33], sm2[32][33];
    int t = blockIdx.x, c = blockIdx.y, b = blockIdx.z;
    int w0 = (t & 7)*32, h0 = (t >> 3)*32;
    size_t pbase = ((size_t)b*Cc + c)*HWi;
    int lx = threadIdx.x & 31, ly = threadIdx.x >> 5;
    const float* a1T = attHT + pbase;
    const float* a2T = attHT + (size_t)BCHW + pbase;
#pragma unroll
    for (int i = 0; i < 4; i++) {
        int wl = ly*4 + i;
        size_t idx = (size_t)(w0+wl)*256 + h0 + lx;
        sm1[wl][lx] = a1T[idx];
        sm2[wl][lx] = a2T[idx];
    }
    __syncthreads();
    float g1 = gamma1[0], g2 = gamma2[0];
    size_t fb0 = (size_t)b*HWi;
    size_t fb1 = (size_t)(Bz + b)*HWi;
#pragma unroll
    for (int i = 0; i < 4; i++) {
        int hl = ly*4 + i;
        int p = (h0+hl)*256 + w0 + lx;
        float a1 = sm1[lx][hl]*fH[fb0 + p] + attW[pbase + p]*fW[fb0 + p];
        float a2 = sm2[lx][hl]*fH[fb1 + p] + attW[(size_t)BCHW + pbase + p]*fW[fb1 + p];
        float xa = x1[pbase + p], xb = x2[pbase + p];
        s1[pbase + p] = g2*a2 + xb + xa;
        s2[pbase + p] = g1*a1 + xa + xb;
    }
}

// ---------------- pool: 12 moment partials per (b,c,slice) ----------------
__global__ __launch_bounds__(256) void pool_kernel(
    const float* __restrict__ s1, const float* __restrict__ s2,
    const float* __restrict__ x1, const float* __restrict__ x2,
    float* __restrict__ pp) {
    int c = blockIdx.x, b = blockIdx.y, sl = blockIdx.z;
    int tid = threadIdx.x;
    size_t base = ((size_t)b*Cc + c)*HWi + sl*8192;
    bool odd = (c & 1);
    float vals[12];
    float sum1=0, sum2=0, mx1=-1e30f, mx2=-1e30f;
    float q1=0, xs1=0, xq1=0, sx1=0, q2=0, xs2=0, xq2=0, sx2=0;
    for (int i = tid; i < 8192; i += 256) {
        float v1 = s1[base+i], v2 = s2[base+i];
        sum1 += v1; sum2 += v2;
        mx1 = fmaxf(mx1, v1); mx2 = fmaxf(mx2, v2);
        if (odd) {
            float xa = x1[base+i], xb = x2[base+i];
            q1 += v1*v1; xs1 += xa; xq1 += xa*xa; sx1 += v1*xa;
            q2 += v2*v2; xs2 += xb; xq2 += xb*xb; sx2 += v2*xb;
        }
    }
    vals[0]=sum1; vals[1]=mx1; vals[2]=sum2; vals[3]=mx2;
    vals[4]=q1; vals[5]=xs1; vals[6]=xq1; vals[7]=sx1;
    vals[8]=q2; vals[9]=xs2; vals[10]=xq2; vals[11]=sx2;
    __shared__ float red[12][8];
    int lane = tid & 31, wid = tid >> 5;
#pragma unroll
    for (int kk = 0; kk < 12; kk++) {
        float v = vals[kk];
        if (kk == 1 || kk == 3) {
#pragma unroll
            for (int s = 16; s > 0; s >>= 1) v = fmaxf(v, __shfl_xor_sync(0xffffffffu, v, s));
        } else {
#pragma unroll
            for (int s = 16; s > 0; s >>= 1) v += __shfl_xor_sync(0xffffffffu, v, s);
        }
        if (lane == 0) red[kk][wid] = v;
    }
    __syncthreads();
    if (tid < 12) {
        float acc = red[tid][0];
        for (int wwi = 1; wwi < 8; wwi++)
            acc = (tid == 1 || tid == 3) ? fmaxf(acc, red[tid][wwi]) : acc + red[tid][wwi];
        pp[(((size_t)tid*Bz + b)*Cc + c)*8 + sl] = acc;
    }
}

// ---------------- gate: reduce pool partials + tiny MLP ----------------
__global__ void gate_kernel(const float* __restrict__ w1a, const float* __restrict__ b1a,
                            const float* __restrict__ w2a, const float* __restrict__ b2a,
                            const float* __restrict__ w1b, const float* __restrict__ b1b,
                            const float* __restrict__ w2b, const float* __restrict__ b2b,
                            const float* __restrict__ pp, float* __restrict__ gate) {
    __shared__ float pool_s[4][Bz][Cc];
    __shared__ float hid[2][Bz][2][CRr];
    int tid = threadIdx.x;
    for (int e = tid; e < 4*Bz*Cc; e += 256) {
        int kk = e >> 7, rem = e & 127;
        int bb = rem >> 6, c = rem & 63;
        bool ismax = (kk == 1 || kk == 3);
        float acc = ismax ? -1e30f : 0.f;
        for (int sl = 0; sl < 8; sl++) {
            float v = pp[(((size_t)kk*Bz + bb)*Cc + c)*8 + sl];
            acc = ismax ? fmaxf(acc, v) : acc + v;
        }
        if (!ismax) acc *= (1.f/65536.f);
        pool_s[kk][bb][c] = acc;
    }
    __syncthreads();
    if (tid < 2*Bz*2*CRr) {
        int r  = tid & (CRr-1);
        int mm = (tid >> 2) & 1;
        int bb = (tid >> 3) & 1;
        int br = (tid >> 4) & 1;
        const float* w1 = br ? w1b : w1a;
        const float* b1 = br ? b1b : b1a;
        const float* p = pool_s[br*2 + mm][bb];
        float acc = b1[r];
        for (int c = 0; c < Cc; c++) acc += w1[r*Cc + c]*p[c];
        hid[br][bb][mm][r] = fmaxf(acc, 0.f);
    }
    __syncthreads();
    int c = tid & 63, bb = (tid >> 6) & 1, br = tid >> 7;
    const float* w2 = br ? w2b : w2a;
    const float* b2 = br ? b2b : b2a;
    float o = 2.f*b2[c];
    for (int mm = 0; mm < 2; mm++)
#pragma unroll
        for (int r = 0; r < CRr; r++) o += w2[c*CRr + r]*hid[br][bb][mm][r];
    gate[(br*Bz + bb)*Cc + c] = 1.f/(1.f + expf(-o));
}

// ---------------- BN stats from moments (t = gate*s + x, odd channels) ----------------
__global__ void bnstat_kernel(const float* __restrict__ pp, const float* __restrict__ gate,
                              float* __restrict__ stat) {
    int tid = threadIdx.x;                 // 128: [branch][c]
    int br = tid >> 6, c = tid & 63;
    if (!(c & 1)) return;
    int k_s  = br ? 2 : 0;
    int k_q  = br ? 8 : 4;
    int k_x  = br ? 9 : 5;
    int k_xq = br ? 10 : 6;
    int k_sx = br ? 11 : 7;
    float sumT = 0.f, sumT2 = 0.f;
    for (int b = 0; b < Bz; b++) {
        float gt = gate[(br*Bz + b)*Cc + c];
        float S=0, Q=0, X=0, XQ=0, SX=0;
        for (int sl = 0; sl < 8; sl++) {
            S  += pp[(((size_t)k_s*Bz + b)*Cc + c)*8 + sl];
            Q  += pp[(((size_t)k_q*Bz + b)*Cc + c)*8 + sl];
            X  += pp[(((size_t)k_x*Bz + b)*Cc + c)*8 + sl];
            XQ += pp[(((size_t)k_xq*Bz + b)*Cc + c)*8 + sl];
            SX += pp[(((size_t)k_sx*Bz + b)*Cc + c)*8 + sl];
        }
        sumT  += gt*S + X;
        sumT2 += gt*gt*Q + 2.f*gt*SX + XQ;
    }
    float N = (float)(Bz*HWi);
    float m = sumT/N;
    float var = sumT2/N - m*m;
    stat[(br*Cc + c)*2 + 0] = m;
    stat[(br*Cc + c)*2 + 1] = rsqrtf(var + 1e-5f);
}

// ---------------- finalize ----------------
__global__ void final_kernel(const float* __restrict__ x1, const float* __restrict__ x2,
                             const float* __restrict__ s1, const float* __restrict__ s2,
                             const float* __restrict__ gate, const float* __restrict__ stat,
                             const float* __restrict__ sc1, const float* __restrict__ bi1,
                             const float* __restrict__ sc2, const float* __restrict__ bi2,
                             float* __restrict__ out) {
    int n = blockIdx.x*256 + threadIdx.x;   // BCHW exact
    int c = (n >> 16) & 63;
    int b = n >> 22;
    float o1, o2;
    if ((c & 1) == 0) {
        o1 = x1[n]; o2 = x2[n];
    } else {
        float gt1 = gate[(0*Bz + b)*Cc + c];
        float gt2 = gate[(1*Bz + b)*Cc + c];
        float t1 = gt1*s1[n] + x1[n];
        float t2 = gt2*s2[n] + x2[n];
        float m1 = stat[(0*Cc + c)*2], is1 = stat[(0*Cc + c)*2 + 1];
        float m2 = stat[(1*Cc + c)*2], is2 = stat[(1*Cc + c)*2 + 1];
        o1 = fmaxf((t1 - m1)*is1*sc1[c] + bi1[c], 0.f);
        o2 = fmaxf((t2 - m2)*is2*sc2[c] + bi2[c], 0.f);
    }
    out[n] = o1;
    out[BCHW + n] = o2;
}

// ---------------- host launch ----------------
extern "C" void kernel_launch(void* const* d_in, const int* in_sizes, int n_in,
                              void* d_out, int out_size) {
    const float* x1  = (const float*)d_in[0];
    const float* x2  = (const float*)d_in[1];
    const float* wq1 = (const float*)d_in[2];
    const float* bq1 = (const float*)d_in[3];
    const float* wq2 = (const float*)d_in[4];
    const float* bq2 = (const float*)d_in[5];
    const float* wk1 = (const float*)d_in[6];
    const float* bk1 = (const float*)d_in[7];
    const float* wk2 = (const float*)d_in[8];
    const float* bk2 = (const float*)d_in[9];
    const float* wv1 = (const float*)d_in[10];
    const float* bv1 = (const float*)d_in[11];
    const float* wv2 = (const float*)d_in[12];
    const float* bv2 = (const float*)d_in[13];
    const float* gamma1 = (const float*)d_in[14];
    const float* gamma2 = (const float*)d_in[15];
    const float* sc1_w1 = (const float*)d_in[16];
    const float* sc1_b1 = (const float*)d_in[17];
    const float* sc1_w2 = (const float*)d_in[18];
    const float* sc1_b2 = (const float*)d_in[19];
    const float* sc2_w1 = (const float*)d_in[20];
    const float* sc2_b1 = (const float*)d_in[21];
    const float* sc2_w2 = (const float*)d_in[22];
    const float* sc2_b2 = (const float*)d_in[23];
    const float* bn1_scale = (const float*)d_in[24];
    const float* bn1_bias  = (const float*)d_in[25];
    const float* bn2_scale = (const float*)d_in[26];
    const float* bn2_bias  = (const float*)d_in[27];

    float *qkv, *qkvT, *mW, *sW, *mHT, *sHT, *fH, *fW;
    float *attHT, *attW, *s1, *s2, *pp, *gate, *stat;
    cudaGetSymbolAddress((void**)&qkv,  g_qkv);
    cudaGetSymbolAddress((void**)&qkvT, g_qkvT);
    cudaGetSymbolAddress((void**)&mW,  g_mW);
    cudaGetSymbolAddress((void**)&sW,  g_sW);
    cudaGetSymbolAddress((void**)&mHT, g_mHT);
    cudaGetSymbolAddress((void**)&sHT, g_sHT);
    cudaGetSymbolAddress((void**)&fH,  g_fH);
    cudaGetSymbolAddress((void**)&fW,  g_fW);
    cudaGetSymbolAddress((void**)&attHT, g_attHT);
    cudaGetSymbolAddress((void**)&attW,  g_attW);
    cudaGetSymbolAddress((void**)&s1, g_s1);
    cudaGetSymbolAddress((void**)&s2, g_s2);
    cudaGetSymbolAddress((void**)&pp, g_pp);
    cudaGetSymbolAddress((void**)&gate, g_gate);
    cudaGetSymbolAddress((void**)&stat, g_stat);

    float* q1 = qkv + (size_t)PQ1*HWi;
    float* q2 = qkv + (size_t)PQ2*HWi;
    float* k1 = qkv + (size_t)PK1*HWi;
    float* k2 = qkv + (size_t)PK2*HWi;
    float* v1 = qkv + (size_t)PV1*HWi;
    float* v2 = qkv + (size_t)PV2*HWi;
    float* q1T = qkvT + (size_t)PQ1*HWi;
    float* q2T = qkvT + (size_t)PQ2*HWi;
    float* k1T = qkvT + (size_t)PK1*HWi;
    float* k2T = qkvT + (size_t)PK2*HWi;
    float* v1T = qkvT + (size_t)PV1*HWi;
    float* v2T = qkvT + (size_t)PV2*HWi;

    cudaFuncSetAttribute(agg_kernel<true>,  cudaFuncAttributeMaxDynamicSharedMemorySize, AGG_SMEM);
    cudaFuncSetAttribute(agg_kernel<false>, cudaFuncAttributeMaxDynamicSharedMemorySize, AGG_SMEM);

    // projections
    proj_kernel<<<512, 256>>>(x1, wq1, bq1, wk1, bk1, wv1, bv1, q1, k1, v1);
    proj_kernel<<<512, 256>>>(x2, wq2, bq2, wk2, bk2, wv2, bv2, q2, k2, v2);

    // transpose all q/k/v planes
    transpose_kernel<<<dim3(64, NPLANES), 256>>>(qkv, qkvT);

    // per-direction softmax stats (z=0: criss att1 = q2/k1, z=1: att2 = q1/k2)
    stat_kernel<false><<<dim3(256, Bz, 2), 256>>>(q2, k1, q1, k2, mW, sW);
    stat_kernel<true ><<<dim3(256, Bz, 2), 256>>>(q2T, k1T, q1T, k2T, mHT, sHT);

    // merge factors
    factor_kernel<<<dim3(256, Bz, 2), 256>>>(mHT, sHT, mW, sW, fH, fW);

    // aggregation: H-direction (transposed arrays, diag mask) and W-direction
    agg_kernel<true ><<<dim3(256, Bz*2, 2), 256, AGG_SMEM>>>(
        q2T, k1T, v1T, attHT, q1T, k2T, v2T, attHT + BCHW, mHT);
    agg_kernel<false><<<dim3(256, Bz*2, 2), 256, AGG_SMEM>>>(
        q2, k1, v1, attW, q1, k2, v2, attW + BCHW, mW);

    // merge + ShareCA s-planes
    merge_kernel<<<dim3(64, Cc, Bz), 256>>>(attHT, attW, fH, fW, x1, x2,
                                            gamma1, gamma2, s1, s2);

    // pooled moments, gates, BN stats, finalize
    pool_kernel<<<dim3(Cc, Bz, 8), 256>>>(s1, s2, x1, x2, pp);
    gate_kernel<<<1, 256>>>(sc1_w1, sc1_b1, sc1_w2, sc1_b2,
                            sc2_w1, sc2_b1, sc2_w2, sc2_b2, pp, gate);
    bnstat_kernel<<<1, 128>>>(pp, gate, stat);
    final_kernel<<<BCHW/256, 256>>>(x1, x2, s1, s2, gate, stat,
                                    bn1_scale, bn1_bias, bn2_scale, bn2_bias, (float*)d_out);
}

// round 8
// speedup vs baseline: 1.3319x; 1.1106x over previous
#include <cuda_runtime.h>
#include <math.h>

#define Bz 2
#define Cc 64
#define CQ 8
#define CRr 4
#define HWi 65536
#define BCHW (Bz*Cc*HWi)      // 8388608

// plane offsets (in planes of 65536 floats) inside g_qkv / g_qkvT
#define PQ1 0
#define PQ2 16
#define PK1 32
#define PK2 48
#define PV1 64
#define PV2 192
#define NPLANES 320

// ---------------- scratch (device globals) ----------------
__device__ float g_qkv [NPLANES*HWi];
__device__ float g_qkvT[NPLANES*HWi];
__device__ float g_mW [2*Bz*HWi];     // W-direction per-pixel max (normal layout)
__device__ float g_sW [2*Bz*HWi];
__device__ float g_mH [2*Bz*HWi];     // H-direction per-pixel max (transposed layout)
__device__ float g_sH [2*Bz*HWi];
__device__ float g_fH [2*Bz*HWi];
__device__ float g_fW [2*Bz*HWi];
__device__ float g_attHT[2*BCHW];
__device__ float g_attW [2*BCHW];
__device__ float g_s1[BCHW];
__device__ float g_s2[BCHW];
__device__ float g_pp[12*Bz*Cc*64];   // [stat][b][c][tile]
__device__ float g_gate[2*Bz*Cc];
__device__ float g_stat[2*Cc*2];

// ---------------- packed f32x2 helpers ----------------
__device__ __forceinline__ unsigned long long fma2(unsigned long long a, unsigned long long b,
                                                   unsigned long long c) {
    unsigned long long d;
    asm("fma.rn.f32x2 %0, %1, %2, %3;" : "=l"(d) : "l"(a), "l"(b), "l"(c));
    return d;
}
__device__ __forceinline__ unsigned long long mul2(unsigned long long a, unsigned long long b) {
    unsigned long long d;
    asm("mul.rn.f32x2 %0, %1, %2;" : "=l"(d) : "l"(a), "l"(b));
    return d;
}
__device__ __forceinline__ unsigned long long packf2(float lo, float hi) {
    unsigned long long r;
    asm("mov.b64 %0, {%1, %2};" : "=l"(r) : "f"(lo), "f"(hi));
    return r;
}
__device__ __forceinline__ float2 unpackf2(unsigned long long a) {
    float2 r;
    asm("mov.b64 {%0, %1}, %2;" : "=f"(r.x), "=f"(r.y) : "l"(a));
    return r;
}

// k smem swizzled offset: rows j and j+16 land on different banks, 16B alignment kept
__device__ __forceinline__ int ksoff(int j) { return j*12 + ((j>>4)&1)*4; }

// ---------------- fused projection: x -> q(8), k(8), v(64) ----------------
__global__ __launch_bounds__(256) void proj_kernel(
    const float* __restrict__ x,
    const float* __restrict__ wq, const float* __restrict__ bq,
    const float* __restrict__ wk, const float* __restrict__ bk,
    const float* __restrict__ wv, const float* __restrict__ bv,
    float* __restrict__ q, float* __restrict__ k, float* __restrict__ v) {
    __shared__ unsigned long long ws2[64*40];
    __shared__ unsigned long long bs2[40];
    int tid = threadIdx.x;
    for (int i = tid; i < 64*40; i += 256) {
        int c = i / 40, t = i - (i/40)*40;
        float lo, hi;
        if (t < 4)      { lo = wq[(2*t)*Cc + c];       hi = wq[(2*t+1)*Cc + c]; }
        else if (t < 8) { lo = wk[(2*(t-4))*Cc + c];   hi = wk[(2*(t-4)+1)*Cc + c]; }
        else            { lo = wv[(2*(t-8))*Cc + c];   hi = wv[(2*(t-8)+1)*Cc + c]; }
        ws2[i] = packf2(lo, hi);
    }
    if (tid < 40) {
        int t = tid; float lo, hi;
        if (t < 4)      { lo = bq[2*t];       hi = bq[2*t+1]; }
        else if (t < 8) { lo = bk[2*(t-4)];   hi = bk[2*(t-4)+1]; }
        else            { lo = bv[2*(t-8)];   hi = bv[2*(t-8)+1]; }
        bs2[t] = packf2(lo, hi);
    }
    __syncthreads();
    int p = blockIdx.x*256 + tid;               // Bz*HW exact
    int b = p >> 16, hw = p & 65535;
    const float* xb = x + (size_t)b*Cc*HWi + hw;
    unsigned long long acc[40];
#pragma unroll
    for (int t = 0; t < 40; t++) acc[t] = bs2[t];
    for (int c = 0; c < Cc; c++) {
        float xv = __ldg(xb + (size_t)c*HWi);
        unsigned long long xx = packf2(xv, xv);
        const unsigned long long* w = ws2 + c*40;
#pragma unroll
        for (int t = 0; t < 40; t++) acc[t] = fma2(xx, w[t], acc[t]);
    }
    float* qo = q + (size_t)b*CQ*HWi + hw;
    float* ko = k + (size_t)b*CQ*HWi + hw;
    float* vo = v + (size_t)b*Cc*HWi + hw;
#pragma unroll
    for (int t = 0; t < 4; t++) {
        float2 r = unpackf2(acc[t]);
        qo[(size_t)(2*t)*HWi] = r.x; qo[(size_t)(2*t+1)*HWi] = r.y;
    }
#pragma unroll
    for (int t = 4; t < 8; t++) {
        float2 r = unpackf2(acc[t]);
        ko[(size_t)(2*(t-4))*HWi] = r.x; ko[(size_t)(2*(t-4)+1)*HWi] = r.y;
    }
#pragma unroll
    for (int t = 8; t < 40; t++) {
        float2 r = unpackf2(acc[t]);
        vo[(size_t)(2*(t-8))*HWi] = r.x; vo[(size_t)(2*(t-8)+1)*HWi] = r.y;
    }
}

// ---------------- tiled per-plane transpose ----------------
__global__ __launch_bounds__(256) void transpose_kernel(const float* __restrict__ src,
                                                        float* __restrict__ dst) {
    __shared__ float sm[32][33];
    int plane = blockIdx.y;
    int t = blockIdx.x;                     // 64 tiles
    int h0 = (t >> 3)*32, w0 = (t & 7)*32;
    const float* sp = src + (size_t)plane*HWi;
    float* dp = dst + (size_t)plane*HWi;
    int lx = threadIdx.x & 31, ly = threadIdx.x >> 5;
#pragma unroll
    for (int i = 0; i < 4; i++) {
        int hl = ly*4 + i;
        sm[hl][lx] = sp[(h0+hl)*256 + w0 + lx];
    }
    __syncthreads();
#pragma unroll
    for (int i = 0; i < 4; i++) {
        int wl = ly*4 + i;
        dp[(w0+wl)*256 + h0 + lx] = sm[lx][wl];
    }
}

// ---------------- aggregation with ONLINE softmax stats ----------------
// grid (256, 4, 4): x=o (line), y=(half<<1)|b, z=(dir<<1)|zc
// dir 0: W-direction (normal arrays, no diag). dir 1: H-direction (transposed, diag mask).
// zc 0: att1 = cc(q2,k1,v1). zc 1: att2 = cc(q1,k2,v2).
// Emits raw out_dir = sum_g exp(e - m_dir) v  and per-pixel (m_dir, s_dir).
#define AGG_F (8192 + 32*68 + 3080 + 128*12 + 3*128)
#define AGG_SMEM (AGG_F*4)
__global__ __launch_bounds__(256,3) void agg_kernel(
    const float* __restrict__ qkv, const float* __restrict__ qkvT,
    float* __restrict__ attW, float* __restrict__ attHT,
    float* __restrict__ mW, float* __restrict__ sW,
    float* __restrict__ mH, float* __restrict__ sH) {
    extern __shared__ float sm[];
    float* Adup = sm;                    // 32 cols x 128 rows dup pairs (8192 floats)
    float* Vsm  = sm + 8192;             // 32 x 68
    float* ks   = Vsm + 32*68;           // swizzled 256 rows x 8 (3080)
    float* qs   = ks + 3080;             // 128 x 12
    float* msm  = qs + 128*12;           // 128 running max
    float* ssm  = msm + 128;             // 128 running sum
    float* resc = ssm + 128;             // 128 rescale
    int o = blockIdx.x;
    int b = blockIdx.y & 1, half = blockIdx.y >> 1;
    int zc = blockIdx.z & 1, dir = blockIdx.z >> 1;
    const float* base = dir ? qkvT : qkv;
    const float* qp = base + (size_t)((zc ? PQ1 : PQ2) + b*CQ)*HWi + (size_t)o*256;
    const float* kp = base + (size_t)((zc ? PK2 : PK1) + b*CQ)*HWi + (size_t)o*256;
    const float* vp = base + (size_t)((zc ? PV2 : PV1) + b*Cc)*HWi + (size_t)o*256;
    float* out = (dir ? attHT : attW) + (size_t)zc*BCHW + (size_t)b*Cc*HWi
               + (size_t)o*256 + half*128;
    int tid = threadIdx.x;
    for (int i = tid; i < CQ*256; i += 256) {
        int c = i >> 8, j = i & 255;
        ks[ksoff(j) + c] = kp[(size_t)c*HWi + j];
    }
    for (int i = tid; i < CQ*128; i += 256) {
        int c = i >> 7, r = i & 127;
        qs[r*12 + c] = qp[(size_t)c*HWi + half*128 + r];
    }
    if (tid < 128) { msm[tid] = -1e30f; ssm[tid] = 0.f; }
    __syncthreads();

    int r = tid >> 1, jhalf = tid & 1;
    float4 qa = *(const float4*)(qs + r*12);
    float4 qb = *(const float4*)(qs + r*12 + 4);
    int gdiag = half*128 + r;
    int tcol = tid & 3, trow = tid >> 2;
    unsigned long long acc[16];
#pragma unroll
    for (int i = 0; i < 16; i++) acc[i] = 0ull;

    for (int g0 = 0; g0 < 256; g0 += 32) {
        __syncthreads();
        // stage V chunk (coalesced gmem)
        for (int i = tid; i < 32*64; i += 256) {
            int c = i >> 5, gg = i & 31;
            Vsm[gg*68 + c] = vp[(size_t)c*HWi + g0 + gg];
        }
        // A chunk: 16 energies per thread (row r, cols jhalf*16..+15)
        float e[16];
        float cmax = -1e30f;
#pragma unroll
        for (int jj = 0; jj < 16; jj++) {
            int jg = g0 + jhalf*16 + jj;
            const float4* kq = (const float4*)(ks + ksoff(jg));
            float4 ka = kq[0], kb = kq[1];
            float ev = qa.x*ka.x + qa.y*ka.y + qa.z*ka.z + qa.w*ka.w
                     + qb.x*kb.x + qb.y*kb.y + qb.z*kb.z + qb.w*kb.w;
            if (dir && jg == gdiag) ev = -1e30f;
            e[jj] = ev;
            cmax = fmaxf(cmax, ev);
        }
        cmax = fmaxf(cmax, __shfl_xor_sync(0xffffffffu, cmax, 1));
        float mold = msm[r];
        float mnew = fmaxf(mold, cmax);
        float csum = 0.f;
#pragma unroll
        for (int jj = 0; jj < 16; jj++) {
            float a = __expf(e[jj] - mnew);
            csum += a;
            *(float2*)(Adup + ((jhalf*16 + jj)*128 + r)*2) = make_float2(a, a);
        }
        csum += __shfl_xor_sync(0xffffffffu, csum, 1);
        if (!jhalf) {
            float rs = __expf(mold - mnew);
            resc[r] = rs;
            ssm[r] = ssm[r]*rs + csum;
            msm[r] = mnew;
        }
        __syncthreads();
        // rescale accumulators, then accumulate this chunk
        float r0f = resc[trow], r1f = resc[trow + 64];
        unsigned long long r0 = packf2(r0f, r0f);
        unsigned long long r1 = packf2(r1f, r1f);
#pragma unroll
        for (int i = 0; i < 8; i++) {
            acc[i]   = mul2(acc[i],   r0);
            acc[8+i] = mul2(acc[8+i], r1);
        }
        const double*  Ad = (const double*)Adup;   // pair (j,r) at index j*128 + r
        const double2* Vd = (const double2*)Vsm;
#pragma unroll 8
        for (int gg = 0; gg < 32; gg++) {
            unsigned long long a0 = __double_as_longlong(Ad[gg*128 + trow]);
            unsigned long long a1 = __double_as_longlong(Ad[gg*128 + trow + 64]);
#pragma unroll
            for (int jj = 0; jj < 4; jj++) {
                double2 vv = Vd[gg*17 + tcol*4 + jj];
                unsigned long long v0 = __double_as_longlong(vv.x);
                unsigned long long v1 = __double_as_longlong(vv.y);
                acc[jj*2+0]   = fma2(a0, v0, acc[jj*2+0]);
                acc[jj*2+1]   = fma2(a0, v1, acc[jj*2+1]);
                acc[8+jj*2+0] = fma2(a1, v0, acc[8+jj*2+0]);
                acc[8+jj*2+1] = fma2(a1, v1, acc[8+jj*2+1]);
            }
        }
    }
#pragma unroll
    for (int rr = 0; rr < 2; rr++) {
        int h = trow + rr*64;
#pragma unroll
        for (int pp = 0; pp < 8; pp++) {
            float2 val = unpackf2(acc[rr*8 + pp]);
            int c = tcol*16 + pp*2;
            out[(size_t)c*HWi + h]     = val.x;
            out[(size_t)(c+1)*HWi + h] = val.y;
        }
    }
    __syncthreads();
    if (tid < 128) {
        size_t idx = ((size_t)zc*Bz + b)*HWi + o*256 + half*128 + tid;
        float* mo = dir ? mH : mW;
        float* so = dir ? sH : sW;
        mo[idx] = msm[tid];
        so[idx] = ssm[tid];
    }
}

// ---------------- merge factors (exact two-direction softmax combine) ----------------
__global__ void factor_kernel(const float* __restrict__ mH, const float* __restrict__ sH,
                              const float* __restrict__ mW, const float* __restrict__ sW,
                              float* __restrict__ fH, float* __restrict__ fW) {
    int p = blockIdx.x*256 + threadIdx.x;
    int b = blockIdx.y, z = blockIdx.z;
    size_t zb = ((size_t)z*Bz + b)*HWi;
    int h = p >> 8, w = p & 255;
    float mh = mH[zb + w*256 + h], sh = sH[zb + w*256 + h];
    float mw = mW[zb + p],         sw = sW[zb + p];
    float m = fmaxf(mh, mw);
    float eh = __expf(mh - m), ew = __expf(mw - m);
    float inv = 1.f/(sh*eh + sw*ew);
    fH[zb + p] = eh*inv;
    fW[zb + p] = ew*inv;
}

// ---------------- merge + fused pool: combine directions, emit s (odd c), 12 moments ----------------
__global__ __launch_bounds__(256) void merge_kernel(
    const float* __restrict__ attHT, const float* __restrict__ attW,
    const float* __restrict__ fH, const float* __restrict__ fW,
    const float* __restrict__ x1, const float* __restrict__ x2,
    const float* __restrict__ gamma1, const float* __restrict__ gamma2,
    float* __restrict__ s1, float* __restrict__ s2, float* __restrict__ pp) {
    __shared__ float sm1[32][33], sm2[32][33];
    int t = blockIdx.x, c = blockIdx.y, b = blockIdx.z;
    int w0 = (t & 7)*32, h0 = (t >> 3)*32;
    size_t pbase = ((size_t)b*Cc + c)*HWi;
    int lx = threadIdx.x & 31, ly = threadIdx.x >> 5;
    const float* a1T = attHT + pbase;
    const float* a2T = attHT + (size_t)BCHW + pbase;
#pragma unroll
    for (int i = 0; i < 4; i++) {
        int wl = ly*4 + i;
        size_t idx = (size_t)(w0+wl)*256 + h0 + lx;
        sm1[wl][lx] = a1T[idx];
        sm2[wl][lx] = a2T[idx];
    }
    __syncthreads();
    float g1 = gamma1[0], g2 = gamma2[0];
    size_t fb0 = (size_t)b*HWi;
    size_t fb1 = (size_t)(Bz + b)*HWi;
    bool odd = (c & 1);
    float sum1=0, sum2=0, mx1=-1e30f, mx2=-1e30f;
    float q1=0, xs1=0, xq1=0, sx1=0, q2=0, xs2=0, xq2=0, sx2=0;
#pragma unroll
    for (int i = 0; i < 4; i++) {
        int hl = ly*4 + i;
        int p = (h0+hl)*256 + w0 + lx;
        float a1 = sm1[lx][hl]*fH[fb0 + p] + attW[pbase + p]*fW[fb0 + p];
        float a2 = sm2[lx][hl]*fH[fb1 + p] + attW[(size_t)BCHW + pbase + p]*fW[fb1 + p];
        float xa = x1[pbase + p], xb = x2[pbase + p];
        float v1 = g2*a2 + xb + xa;
        float v2 = g1*a1 + xa + xb;
        if (odd) { s1[pbase + p] = v1; s2[pbase + p] = v2; }
        sum1 += v1; sum2 += v2;
        mx1 = fmaxf(mx1, v1); mx2 = fmaxf(mx2, v2);
        if (odd) {
            q1 += v1*v1; xs1 += xa; xq1 += xa*xa; sx1 += v1*xa;
            q2 += v2*v2; xs2 += xb; xq2 += xb*xb; sx2 += v2*xb;
        }
    }
    float vals[12] = {sum1, mx1, sum2, mx2, q1, xs1, xq1, sx1, q2, xs2, xq2, sx2};
    __shared__ float red[12][8];
    int lane = threadIdx.x & 31, wid = threadIdx.x >> 5;
#pragma unroll
    for (int kk = 0; kk < 12; kk++) {
        float v = vals[kk];
        if (kk == 1 || kk == 3) {
#pragma unroll
            for (int s = 16; s > 0; s >>= 1) v = fmaxf(v, __shfl_xor_sync(0xffffffffu, v, s));
        } else {
#pragma unroll
            for (int s = 16; s > 0; s >>= 1) v += __shfl_xor_sync(0xffffffffu, v, s);
        }
        if (lane == 0) red[kk][wid] = v;
    }
    __syncthreads();
    if (threadIdx.x < 12) {
        int kk = threadIdx.x;
        float acc = red[kk][0];
        for (int wwi = 1; wwi < 8; wwi++)
            acc = (kk == 1 || kk == 3) ? fmaxf(acc, red[kk][wwi]) : acc + red[kk][wwi];
        pp[(((size_t)kk*Bz + b)*Cc + c)*64 + t] = acc;
    }
}

// ---------------- gate: reduce pool partials + tiny MLP ----------------
__global__ void gate_kernel(const float* __restrict__ w1a, const float* __restrict__ b1a,
                            const float* __restrict__ w2a, const float* __restrict__ b2a,
                            const float* __restrict__ w1b, const float* __restrict__ b1b,
                            const float* __restrict__ w2b, const float* __restrict__ b2b,
                            const float* __restrict__ pp, float* __restrict__ gate) {
    __shared__ float pool_s[4][Bz][Cc];
    __shared__ float hid[2][Bz][2][CRr];
    int tid = threadIdx.x;
    for (int e = tid; e < 4*Bz*Cc; e += 256) {
        int kk = e >> 7, rem = e & 127;
        int bb = rem >> 6, c = rem & 63;
        bool ismax = (kk == 1 || kk == 3);
        float acc = ismax ? -1e30f : 0.f;
        for (int sl = 0; sl < 64; sl++) {
            float v = pp[(((size_t)kk*Bz + bb)*Cc + c)*64 + sl];
            acc = ismax ? fmaxf(acc, v) : acc + v;
        }
        if (!ismax) acc *= (1.f/65536.f);
        pool_s[kk][bb][c] = acc;
    }
    __syncthreads();
    if (tid < 2*Bz*2*CRr) {
        int r  = tid & (CRr-1);
        int mm = (tid >> 2) & 1;
        int bb = (tid >> 3) & 1;
        int br = (tid >> 4) & 1;
        const float* w1 = br ? w1b : w1a;
        const float* b1 = br ? b1b : b1a;
        const float* p = pool_s[br*2 + mm][bb];
        float acc = b1[r];
        for (int c = 0; c < Cc; c++) acc += w1[r*Cc + c]*p[c];
        hid[br][bb][mm][r] = fmaxf(acc, 0.f);
    }
    __syncthreads();
    int c = tid & 63, bb = (tid >> 6) & 1, br = tid >> 7;
    const float* w2 = br ? w2b : w2a;
    const float* b2 = br ? b2b : b2a;
    float o = 2.f*b2[c];
    for (int mm = 0; mm < 2; mm++)
#pragma unroll
        for (int r = 0; r < CRr; r++) o += w2[c*CRr + r]*hid[br][bb][mm][r];
    gate[(br*Bz + bb)*Cc + c] = 1.f/(1.f + expf(-o));
}

// ---------------- BN stats from moments (t = gate*s + x, odd channels) ----------------
__global__ void bnstat_kernel(const float* __restrict__ pp, const float* __restrict__ gate,
                              float* __restrict__ stat) {
    int tid = threadIdx.x;                 // 128: [branch][c]
    int br = tid >> 6, c = tid & 63;
    if (!(c & 1)) return;
    int k_s  = br ? 2 : 0;
    int k_q  = br ? 8 : 4;
    int k_x  = br ? 9 : 5;
    int k_xq = br ? 10 : 6;
    int k_sx = br ? 11 : 7;
    float sumT = 0.f, sumT2 = 0.f;
    for (int b = 0; b < Bz; b++) {
        float gt = gate[(br*Bz + b)*Cc + c];
        float S=0, Q=0, X=0, XQ=0, SX=0;
        for (int sl = 0; sl < 64; sl++) {
            S  += pp[(((size_t)k_s*Bz + b)*Cc + c)*64 + sl];
            Q  += pp[(((size_t)k_q*Bz + b)*Cc + c)*64 + sl];
            X  += pp[(((size_t)k_x*Bz + b)*Cc + c)*64 + sl];
            XQ += pp[(((size_t)k_xq*Bz + b)*Cc + c)*64 + sl];
            SX += pp[(((size_t)k_sx*Bz + b)*Cc + c)*64 + sl];
        }
        sumT  += gt*S + X;
        sumT2 += gt*gt*Q + 2.f*gt*SX + XQ;
    }
    float N = (float)(Bz*HWi);
    float m = sumT/N;
    float var = sumT2/N - m*m;
    stat[(br*Cc + c)*2 + 0] = m;
    stat[(br*Cc + c)*2 + 1] = rsqrtf(var + 1e-5f);
}

// ---------------- finalize ----------------
__global__ void final_kernel(const float* __restrict__ x1, const float* __restrict__ x2,
                             const float* __restrict__ s1, const float* __restrict__ s2,
                             const float* __restrict__ gate, const float* __restrict__ stat,
                             const float* __restrict__ sc1, const float* __restrict__ bi1,
                             const float* __restrict__ sc2, const float* __restrict__ bi2,
                             float* __restrict__ out) {
    int n = blockIdx.x*256 + threadIdx.x;   // BCHW exact
    int c = (n >> 16) & 63;
    int b = n >> 22;
    float o1, o2;
    if ((c & 1) == 0) {
        o1 = x1[n]; o2 = x2[n];
    } else {
        float gt1 = gate[(0*Bz + b)*Cc + c];
        float gt2 = gate[(1*Bz + b)*Cc + c];
        float t1 = gt1*s1[n] + x1[n];
        float t2 = gt2*s2[n] + x2[n];
        float m1 = stat[(0*Cc + c)*2], is1 = stat[(0*Cc + c)*2 + 1];
        float m2 = stat[(1*Cc + c)*2], is2 = stat[(1*Cc + c)*2 + 1];
        o1 = fmaxf((t1 - m1)*is1*sc1[c] + bi1[c], 0.f);
        o2 = fmaxf((t2 - m2)*is2*sc2[c] + bi2[c], 0.f);
    }
    out[n] = o1;
    out[BCHW + n] = o2;
}

// ---------------- host launch ----------------
extern "C" void kernel_launch(void* const* d_in, const int* in_sizes, int n_in,
                              void* d_out, int out_size) {
    const float* x1  = (const float*)d_in[0];
    const float* x2  = (const float*)d_in[1];
    const float* wq1 = (const float*)d_in[2];
    const float* bq1 = (const float*)d_in[3];
    const float* wq2 = (const float*)d_in[4];
    const float* bq2 = (const float*)d_in[5];
    const float* wk1 = (const float*)d_in[6];
    const float* bk1 = (const float*)d_in[7];
    const float* wk2 = (const float*)d_in[8];
    const float* bk2 = (const float*)d_in[9];
    const float* wv1 = (const float*)d_in[10];
    const float* bv1 = (const float*)d_in[11];
    const float* wv2 = (const float*)d_in[12];
    const float* bv2 = (const float*)d_in[13];
    const float* gamma1 = (const float*)d_in[14];
    const float* gamma2 = (const float*)d_in[15];
    const float* sc1_w1 = (const float*)d_in[16];
    const float* sc1_b1 = (const float*)d_in[17];
    const float* sc1_w2 = (const float*)d_in[18];
    const float* sc1_b2 = (const float*)d_in[19];
    const float* sc2_w1 = (const float*)d_in[20];
    const float* sc2_b1 = (const float*)d_in[21];
    const float* sc2_w2 = (const float*)d_in[22];
    const float* sc2_b2 = (const float*)d_in[23];
    const float* bn1_scale = (const float*)d_in[24];
    const float* bn1_bias  = (const float*)d_in[25];
    const float* bn2_scale = (const float*)d_in[26];
    const float* bn2_bias  = (const float*)d_in[27];

    float *qkv, *qkvT, *mW, *sW, *mH, *sH, *fH, *fW;
    float *attHT, *attW, *s1, *s2, *pp, *gate, *stat;
    cudaGetSymbolAddress((void**)&qkv,  g_qkv);
    cudaGetSymbolAddress((void**)&qkvT, g_qkvT);
    cudaGetSymbolAddress((void**)&mW,  g_mW);
    cudaGetSymbolAddress((void**)&sW,  g_sW);
    cudaGetSymbolAddress((void**)&mH,  g_mH);
    cudaGetSymbolAddress((void**)&sH,  g_sH);
    cudaGetSymbolAddress((void**)&fH,  g_fH);
    cudaGetSymbolAddress((void**)&fW,  g_fW);
    cudaGetSymbolAddress((void**)&attHT, g_attHT);
    cudaGetSymbolAddress((void**)&attW,  g_attW);
    cudaGetSymbolAddress((void**)&s1, g_s1);
    cudaGetSymbolAddress((void**)&s2, g_s2);
    cudaGetSymbolAddress((void**)&pp, g_pp);
    cudaGetSymbolAddress((void**)&gate, g_gate);
    cudaGetSymbolAddress((void**)&stat, g_stat);

    float* q1 = qkv + (size_t)PQ1*HWi;
    float* q2 = qkv + (size_t)PQ2*HWi;
    float* k1 = qkv + (size_t)PK1*HWi;
    float* k2 = qkv + (size_t)PK2*HWi;
    float* v1 = qkv + (size_t)PV1*HWi;
    float* v2 = qkv + (size_t)PV2*HWi;

    cudaFuncSetAttribute(agg_kernel, cudaFuncAttributeMaxDynamicSharedMemorySize, AGG_SMEM);

    // projections
    proj_kernel<<<512, 256>>>(x1, wq1, bq1, wk1, bk1, wv1, bv1, q1, k1, v1);
    proj_kernel<<<512, 256>>>(x2, wq2, bq2, wk2, bk2, wv2, bv2, q2, k2, v2);

    // transpose all q/k/v planes
    transpose_kernel<<<dim3(64, NPLANES), 256>>>(qkv, qkvT);

    // aggregation with online per-direction softmax (one launch: both dirs, both crisses)
    agg_kernel<<<dim3(256, 4, 4), 256, AGG_SMEM>>>(qkv, qkvT, attW, attHT, mW, sW, mH, sH);

    // exact cross-direction merge factors
    factor_kernel<<<dim3(256, Bz, 2), 256>>>(mH, sH, mW, sW, fH, fW);

    // merge + ShareCA s-planes (odd channels) + fused pooled moments
    merge_kernel<<<dim3(64, Cc, Bz), 256>>>(attHT, attW, fH, fW, x1, x2,
                                            gamma1, gamma2, s1, s2, pp);

    // gates, BN stats, finalize
    gate_kernel<<<1, 256>>>(sc1_w1, sc1_b1, sc1_w2, sc1_b2,
                            sc2_w1, sc2_b1, sc2_w2, sc2_b2, pp, gate);
    bnstat_kernel<<<1, 128>>>(pp, gate, stat);
    final_kernel<<<BCHW/256, 256>>>(x1, x2, s1, s2, gate, stat,
                                    bn1_scale, bn1_bias, bn2_scale, bn2_bias, (float*)d_out);
}

// round 9
// speedup vs baseline: 2.1218x; 1.5930x over previous
#include <cuda_runtime.h>
#include <math.h>

#define Bz 2
#define Cc 64
#define CQ 8
#define CRr 4
#define HWi 65536
#define BCHW (Bz*Cc*HWi)      // 8388608

// plane offsets (in planes of 65536 floats) inside g_qkv / g_qkvT
#define PQ1 0
#define PQ2 16
#define PK1 32
#define PK2 48
#define PV1 64
#define PV2 192
#define NPLANES 320

// ---------------- scratch (device globals) ----------------
__device__ float g_qkv [NPLANES*HWi];
__device__ float g_qkvT[NPLANES*HWi];
__device__ float g_mW [2*Bz*HWi];
__device__ float g_sW [2*Bz*HWi];
__device__ float g_mH [2*Bz*HWi];
__device__ float g_sH [2*Bz*HWi];
__device__ float g_fH [2*Bz*HWi];
__device__ float g_fW [2*Bz*HWi];
__device__ float g_attHT[2*BCHW];
__device__ float g_attW [2*BCHW];
__device__ float g_s1[BCHW];
__device__ float g_s2[BCHW];
__device__ float g_pp[12*Bz*Cc*64];   // [stat][b][c][tile]
__device__ float g_gate[2*Bz*Cc];
__device__ float g_stat[2*Cc*2];

// ---------------- packed f32x2 helpers ----------------
__device__ __forceinline__ unsigned long long fma2(unsigned long long a, unsigned long long b,
                                                   unsigned long long c) {
    unsigned long long d;
    asm("fma.rn.f32x2 %0, %1, %2, %3;" : "=l"(d) : "l"(a), "l"(b), "l"(c));
    return d;
}
__device__ __forceinline__ unsigned long long mul2(unsigned long long a, unsigned long long b) {
    unsigned long long d;
    asm("mul.rn.f32x2 %0, %1, %2;" : "=l"(d) : "l"(a), "l"(b));
    return d;
}
__device__ __forceinline__ unsigned long long packf2(float lo, float hi) {
    unsigned long long r;
    asm("mov.b64 %0, {%1, %2};" : "=l"(r) : "f"(lo), "f"(hi));
    return r;
}
__device__ __forceinline__ float2 unpackf2(unsigned long long a) {
    float2 r;
    asm("mov.b64 {%0, %1}, %2;" : "=f"(r.x), "=f"(r.y) : "l"(a));
    return r;
}

// k smem swizzled offset: rows j and j+16 land on different banks, 16B alignment kept
__device__ __forceinline__ int ksoff(int j) { return j*12 + ((j>>4)&1)*4; }

// ---------------- fused projection: x -> q(8), k(8), v(64) ----------------
__global__ __launch_bounds__(256) void proj_kernel(
    const float* __restrict__ x,
    const float* __restrict__ wq, const float* __restrict__ bq,
    const float* __restrict__ wk, const float* __restrict__ bk,
    const float* __restrict__ wv, const float* __restrict__ bv,
    float* __restrict__ q, float* __restrict__ k, float* __restrict__ v) {
    __shared__ unsigned long long ws2[64*40];
    __shared__ unsigned long long bs2[40];
    int tid = threadIdx.x;
    for (int i = tid; i < 64*40; i += 256) {
        int c = i / 40, t = i - (i/40)*40;
        float lo, hi;
        if (t < 4)      { lo = wq[(2*t)*Cc + c];       hi = wq[(2*t+1)*Cc + c]; }
        else if (t < 8) { lo = wk[(2*(t-4))*Cc + c];   hi = wk[(2*(t-4)+1)*Cc + c]; }
        else            { lo = wv[(2*(t-8))*Cc + c];   hi = wv[(2*(t-8)+1)*Cc + c]; }
        ws2[i] = packf2(lo, hi);
    }
    if (tid < 40) {
        int t = tid; float lo, hi;
        if (t < 4)      { lo = bq[2*t];       hi = bq[2*t+1]; }
        else if (t < 8) { lo = bk[2*(t-4)];   hi = bk[2*(t-4)+1]; }
        else            { lo = bv[2*(t-8)];   hi = bv[2*(t-8)+1]; }
        bs2[t] = packf2(lo, hi);
    }
    __syncthreads();
    int p = blockIdx.x*256 + tid;               // Bz*HW exact
    int b = p >> 16, hw = p & 65535;
    const float* xb = x + (size_t)b*Cc*HWi + hw;
    unsigned long long acc[40];
#pragma unroll
    for (int t = 0; t < 40; t++) acc[t] = bs2[t];
    for (int c = 0; c < Cc; c++) {
        float xv = __ldg(xb + (size_t)c*HWi);
        unsigned long long xx = packf2(xv, xv);
        const unsigned long long* w = ws2 + c*40;
#pragma unroll
        for (int t = 0; t < 40; t++) acc[t] = fma2(xx, w[t], acc[t]);
    }
    float* qo = q + (size_t)b*CQ*HWi + hw;
    float* ko = k + (size_t)b*CQ*HWi + hw;
    float* vo = v + (size_t)b*Cc*HWi + hw;
#pragma unroll
    for (int t = 0; t < 4; t++) {
        float2 r = unpackf2(acc[t]);
        qo[(size_t)(2*t)*HWi] = r.x; qo[(size_t)(2*t+1)*HWi] = r.y;
    }
#pragma unroll
    for (int t = 4; t < 8; t++) {
        float2 r = unpackf2(acc[t]);
        ko[(size_t)(2*(t-4))*HWi] = r.x; ko[(size_t)(2*(t-4)+1)*HWi] = r.y;
    }
#pragma unroll
    for (int t = 8; t < 40; t++) {
        float2 r = unpackf2(acc[t]);
        vo[(size_t)(2*(t-8))*HWi] = r.x; vo[(size_t)(2*(t-8)+1)*HWi] = r.y;
    }
}

// ---------------- tiled per-plane transpose ----------------
__global__ __launch_bounds__(256) void transpose_kernel(const float* __restrict__ src,
                                                        float* __restrict__ dst) {
    __shared__ float sm[32][33];
    int plane = blockIdx.y;
    int t = blockIdx.x;                     // 64 tiles
    int h0 = (t >> 3)*32, w0 = (t & 7)*32;
    const float* sp = src + (size_t)plane*HWi;
    float* dp = dst + (size_t)plane*HWi;
    int lx = threadIdx.x & 31, ly = threadIdx.x >> 5;
#pragma unroll
    for (int i = 0; i < 4; i++) {
        int hl = ly*4 + i;
        sm[hl][lx] = sp[(h0+hl)*256 + w0 + lx];
    }
    __syncthreads();
#pragma unroll
    for (int i = 0; i < 4; i++) {
        int wl = ly*4 + i;
        dp[(w0+wl)*256 + h0 + lx] = sm[lx][wl];
    }
}

// ---------------- aggregation with ONLINE softmax, 128 threads, 4 rows x 16 ch ----------------
// grid (256, 4, 4): x=o (line), y=(half<<1)|b, z=(dir<<1)|zc
// dir 0: W-direction (normal arrays, no diag). dir 1: H-direction (transposed, diag mask).
// Thread tid owns softmax row tid (local). GEMM tile: trow=tid>>2 (+32k rows), tcol=tid&3 (16 ch).
// V stored XOR-swizzled in 16B chunks: chunk location = chunk ^ (gg&15)  -> conflict-free LDS.128.
#define AGG_F (4096 + 32*72 + 3080 + 128)
#define AGG_SMEM (AGG_F*4)
__global__ __launch_bounds__(128,4) void agg_kernel(
    const float* __restrict__ qkv, const float* __restrict__ qkvT,
    float* __restrict__ attW, float* __restrict__ attHT,
    float* __restrict__ mW, float* __restrict__ sW,
    float* __restrict__ mH, float* __restrict__ sH) {
    extern __shared__ float sm[];
    float* Asm  = sm;                    // [j 0..31][r 0..127]  j*128+r  (plain exp values)
    float* Vsm  = sm + 4096;             // [gg 0..31][72] xor-swizzled 16B chunks
    float* ks   = Vsm + 32*72;           // swizzled 256 rows x 8 (3080)
    float* resc = ks + 3080;             // [128] per-row rescale for current chunk
    int o = blockIdx.x;
    int b = blockIdx.y & 1, half = blockIdx.y >> 1;
    int zc = blockIdx.z & 1, dir = blockIdx.z >> 1;
    const float* base = dir ? qkvT : qkv;
    const float* qp = base + (size_t)((zc ? PQ1 : PQ2) + b*CQ)*HWi + (size_t)o*256;
    const float* kp = base + (size_t)((zc ? PK2 : PK1) + b*CQ)*HWi + (size_t)o*256;
    const float* vp = base + (size_t)((zc ? PV2 : PV1) + b*Cc)*HWi + (size_t)o*256;
    float* out = (dir ? attHT : attW) + (size_t)zc*BCHW + (size_t)b*Cc*HWi
               + (size_t)o*256 + half*128;
    int tid = threadIdx.x;
    for (int i = tid; i < CQ*256; i += 128) {
        int c = i >> 8, j = i & 255;
        ks[ksoff(j) + c] = kp[(size_t)c*HWi + j];
    }
    // q row for this thread (softmax row = tid)
    float q_reg[8];
#pragma unroll
    for (int c = 0; c < 8; c++) q_reg[c] = qp[(size_t)c*HWi + half*128 + tid];
    float m_run = -1e30f, s_run = 0.f;
    int gdiag = half*128 + tid;          // global col equal to this row's global index
    int tcol = tid & 3, trow = tid >> 2; // GEMM tile coords: rows trow+32k, ch 16j+4*tcol+{0..3}
    unsigned long long acc[32];
#pragma unroll
    for (int i = 0; i < 32; i++) acc[i] = 0ull;
    __syncthreads();                     // ks ready

    for (int g0 = 0; g0 < 256; g0 += 32) {
        __syncthreads();                 // previous GEMM done reading Asm/Vsm/resc
        // ---- stage V chunk: thread loads one 16B channel-chunk (4 ch) for one gg ----
        for (int i = tid; i < 512; i += 128) {
            int gg = i & 31, cq = i >> 5;         // cq = channel chunk 0..15
            float4 vv;
            vv.x = vp[(size_t)(4*cq+0)*HWi + g0 + gg];
            vv.y = vp[(size_t)(4*cq+1)*HWi + g0 + gg];
            vv.z = vp[(size_t)(4*cq+2)*HWi + g0 + gg];
            vv.w = vp[(size_t)(4*cq+3)*HWi + g0 + gg];
            *(float4*)(Vsm + gg*72 + ((cq ^ (gg & 15)) << 2)) = vv;
        }
        // ---- energies pass 1: raw e -> Asm, track chunk max ----
        float cmax = -1e30f;
#pragma unroll 8
        for (int j = 0; j < 32; j++) {
            int jg = g0 + j;
            const float4* kq = (const float4*)(ks + ksoff(jg));
            float4 ka = kq[0], kb = kq[1];
            float ev = q_reg[0]*ka.x + q_reg[1]*ka.y + q_reg[2]*ka.z + q_reg[3]*ka.w
                     + q_reg[4]*kb.x + q_reg[5]*kb.y + q_reg[6]*kb.z + q_reg[7]*kb.w;
            if (dir && jg == gdiag) ev = -1e30f;
            Asm[j*128 + tid] = ev;
            cmax = fmaxf(cmax, ev);
        }
        float mnew = fmaxf(m_run, cmax);
        // ---- pass 2: exp in place, row sum, rescale factor ----
        float csum = 0.f;
#pragma unroll 8
        for (int j = 0; j < 32; j++) {
            float a = __expf(Asm[j*128 + tid] - mnew);
            Asm[j*128 + tid] = a;
            csum += a;
        }
        float rs = __expf(m_run - mnew);
        s_run = s_run*rs + csum;
        m_run = mnew;
        resc[tid] = rs;
        __syncthreads();                 // Asm/Vsm/resc ready
        // ---- rescale accumulators ----
        unsigned long long rr[4];
#pragma unroll
        for (int k = 0; k < 4; k++) {
            float rv = resc[trow + 32*k];
            rr[k] = packf2(rv, rv);
        }
#pragma unroll
        for (int k = 0; k < 4; k++)
#pragma unroll
            for (int i = 0; i < 8; i++) acc[k*8 + i] = mul2(acc[k*8 + i], rr[k]);
        // ---- GEMM: 32 gg x (4 rows x 16 ch) ----
#pragma unroll 4
        for (int gg = 0; gg < 32; gg++) {
            int sw = gg & 15;
            unsigned long long aa[4];
#pragma unroll
            for (int k = 0; k < 4; k++) {
                float av = Asm[gg*128 + trow + 32*k];
                aa[k] = packf2(av, av);
            }
#pragma unroll
            for (int j = 0; j < 4; j++) {
                double2 dd = *(const double2*)(Vsm + gg*72 + (((j*4 + tcol) ^ sw) << 2));
                unsigned long long v0 = __double_as_longlong(dd.x);
                unsigned long long v1 = __double_as_longlong(dd.y);
#pragma unroll
                for (int k = 0; k < 4; k++) {
                    acc[k*8 + j*2 + 0] = fma2(aa[k], v0, acc[k*8 + j*2 + 0]);
                    acc[k*8 + j*2 + 1] = fma2(aa[k], v1, acc[k*8 + j*2 + 1]);
                }
            }
        }
    }
    // ---- write outputs: rows trow+32k, channels 16j+4tcol+{0..3} ----
#pragma unroll
    for (int k = 0; k < 4; k++) {
        int h = trow + 32*k;
#pragma unroll
        for (int j = 0; j < 4; j++) {
            float2 p0 = unpackf2(acc[k*8 + j*2 + 0]);
            float2 p1 = unpackf2(acc[k*8 + j*2 + 1]);
            int c0 = 16*j + 4*tcol;
            out[(size_t)(c0+0)*HWi + h] = p0.x;
            out[(size_t)(c0+1)*HWi + h] = p0.y;
            out[(size_t)(c0+2)*HWi + h] = p1.x;
            out[(size_t)(c0+3)*HWi + h] = p1.y;
        }
    }
    // ---- per-row softmax stats (thread == row) ----
    {
        size_t idx = ((size_t)zc*Bz + b)*HWi + o*256 + half*128 + tid;
        float* mo = dir ? mH : mW;
        float* so = dir ? sH : sW;
        mo[idx] = m_run;
        so[idx] = s_run;
    }
}

// ---------------- merge factors (exact two-direction softmax combine) ----------------
__global__ void factor_kernel(const float* __restrict__ mH, const float* __restrict__ sH,
                              const float* __restrict__ mW, const float* __restrict__ sW,
                              float* __restrict__ fH, float* __restrict__ fW) {
    int p = blockIdx.x*256 + threadIdx.x;
    int b = blockIdx.y, z = blockIdx.z;
    size_t zb = ((size_t)z*Bz + b)*HWi;
    int h = p >> 8, w = p & 255;
    float mh = mH[zb + w*256 + h], sh = sH[zb + w*256 + h];
    float mw = mW[zb + p],         sw = sW[zb + p];
    float m = fmaxf(mh, mw);
    float eh = __expf(mh - m), ew = __expf(mw - m);
    float inv = 1.f/(sh*eh + sw*ew);
    fH[zb + p] = eh*inv;
    fW[zb + p] = ew*inv;
}

// ---------------- merge + fused pool: combine directions, emit s (odd c), 12 moments ----------------
__global__ __launch_bounds__(256) void merge_kernel(
    const float* __restrict__ attHT, const float* __restrict__ attW,
    const float* __restrict__ fH, const float* __restrict__ fW,
    const float* __restrict__ x1, const float* __restrict__ x2,
    const float* __restrict__ gamma1, const float* __restrict__ gamma2,
    float* __restrict__ s1, float* __restrict__ s2, float* __restrict__ pp) {
    __shared__ float sm1[32][33], sm2[32][33];
    int t = blockIdx.x, c = blockIdx.y, b = blockIdx.z;
    int w0 = (t & 7)*32, h0 = (t >> 3)*32;
    size_t pbase = ((size_t)b*Cc + c)*HWi;
    int lx = threadIdx.x & 31, ly = threadIdx.x >> 5;
    const float* a1T = attHT + pbase;
    const float* a2T = attHT + (size_t)BCHW + pbase;
#pragma unroll
    for (int i = 0; i < 4; i++) {
        int wl = ly*4 + i;
        size_t idx = (size_t)(w0+wl)*256 + h0 + lx;
        sm1[wl][lx] = a1T[idx];
        sm2[wl][lx] = a2T[idx];
    }
    __syncthreads();
    float g1 = gamma1[0], g2 = gamma2[0];
    size_t fb0 = (size_t)b*HWi;
    size_t fb1 = (size_t)(Bz + b)*HWi;
    bool odd = (c & 1);
    float sum1=0, sum2=0, mx1=-1e30f, mx2=-1e30f;
    float q1=0, xs1=0, xq1=0, sx1=0, q2=0, xs2=0, xq2=0, sx2=0;
#pragma unroll
    for (int i = 0; i < 4; i++) {
        int hl = ly*4 + i;
        int p = (h0+hl)*256 + w0 + lx;
        float a1 = sm1[lx][hl]*fH[fb0 + p] + attW[pbase + p]*fW[fb0 + p];
        float a2 = sm2[lx][hl]*fH[fb1 + p] + attW[(size_t)BCHW + pbase + p]*fW[fb1 + p];
        float xa = x1[pbase + p], xb = x2[pbase + p];
        float v1 = g2*a2 + xb + xa;
        float v2 = g1*a1 + xa + xb;
        if (odd) { s1[pbase + p] = v1; s2[pbase + p] = v2; }
        sum1 += v1; sum2 += v2;
        mx1 = fmaxf(mx1, v1); mx2 = fmaxf(mx2, v2);
        if (odd) {
            q1 += v1*v1; xs1 += xa; xq1 += xa*xa; sx1 += v1*xa;
            q2 += v2*v2; xs2 += xb; xq2 += xb*xb; sx2 += v2*xb;
        }
    }
    float vals[12] = {sum1, mx1, sum2, mx2, q1, xs1, xq1, sx1, q2, xs2, xq2, sx2};
    __shared__ float red[12][8];
    int lane = threadIdx.x & 31, wid = threadIdx.x >> 5;
#pragma unroll
    for (int kk = 0; kk < 12; kk++) {
        float v = vals[kk];
        if (kk == 1 || kk == 3) {
#pragma unroll
            for (int s = 16; s > 0; s >>= 1) v = fmaxf(v, __shfl_xor_sync(0xffffffffu, v, s));
        } else {
#pragma unroll
            for (int s = 16; s > 0; s >>= 1) v += __shfl_xor_sync(0xffffffffu, v, s);
        }
        if (lane == 0) red[kk][wid] = v;
    }
    __syncthreads();
    if (threadIdx.x < 12) {
        int kk = threadIdx.x;
        float acc = red[kk][0];
        for (int wwi = 1; wwi < 8; wwi++)
            acc = (kk == 1 || kk == 3) ? fmaxf(acc, red[kk][wwi]) : acc + red[kk][wwi];
        pp[(((size_t)kk*Bz + b)*Cc + c)*64 + t] = acc;
    }
}

// ---------------- gate: reduce pool partials + tiny MLP ----------------
__global__ void gate_kernel(const float* __restrict__ w1a, const float* __restrict__ b1a,
                            const float* __restrict__ w2a, const float* __restrict__ b2a,
                            const float* __restrict__ w1b, const float* __restrict__ b1b,
                            const float* __restrict__ w2b, const float* __restrict__ b2b,
                            const float* __restrict__ pp, float* __restrict__ gate) {
    __shared__ float pool_s[4][Bz][Cc];
    __shared__ float hid[2][Bz][2][CRr];
    int tid = threadIdx.x;
    for (int e = tid; e < 4*Bz*Cc; e += 256) {
        int kk = e >> 7, rem = e & 127;
        int bb = rem >> 6, c = rem & 63;
        bool ismax = (kk == 1 || kk == 3);
        float acc = ismax ? -1e30f : 0.f;
        for (int sl = 0; sl < 64; sl++) {
            float v = pp[(((size_t)kk*Bz + bb)*Cc + c)*64 + sl];
            acc = ismax ? fmaxf(acc, v) : acc + v;
        }
        if (!ismax) acc *= (1.f/65536.f);
        pool_s[kk][bb][c] = acc;
    }
    __syncthreads();
    if (tid < 2*Bz*2*CRr) {
        int r  = tid & (CRr-1);
        int mm = (tid >> 2) & 1;
        int bb = (tid >> 3) & 1;
        int br = (tid >> 4) & 1;
        const float* w1 = br ? w1b : w1a;
        const float* b1 = br ? b1b : b1a;
        const float* p = pool_s[br*2 + mm][bb];
        float acc = b1[r];
        for (int c = 0; c < Cc; c++) acc += w1[r*Cc + c]*p[c];
        hid[br][bb][mm][r] = fmaxf(acc, 0.f);
    }
    __syncthreads();
    int c = tid & 63, bb = (tid >> 6) & 1, br = tid >> 7;
    const float* w2 = br ? w2b : w2a;
    const float* b2 = br ? b2b : b2a;
    float o = 2.f*b2[c];
    for (int mm = 0; mm < 2; mm++)
#pragma unroll
        for (int r = 0; r < CRr; r++) o += w2[c*CRr + r]*hid[br][bb][mm][r];
    gate[(br*Bz + bb)*Cc + c] = 1.f/(1.f + expf(-o));
}

// ---------------- BN stats from moments (t = gate*s + x, odd channels) ----------------
__global__ void bnstat_kernel(const float* __restrict__ pp, const float* __restrict__ gate,
                              float* __restrict__ stat) {
    int tid = threadIdx.x;                 // 128: [branch][c]
    int br = tid >> 6, c = tid & 63;
    if (!(c & 1)) return;
    int k_s  = br ? 2 : 0;
    int k_q  = br ? 8 : 4;
    int k_x  = br ? 9 : 5;
    int k_xq = br ? 10 : 6;
    int k_sx = br ? 11 : 7;
    float sumT = 0.f, sumT2 = 0.f;
    for (int b = 0; b < Bz; b++) {
        float gt = gate[(br*Bz + b)*Cc + c];
        float S=0, Q=0, X=0, XQ=0, SX=0;
        for (int sl = 0; sl < 64; sl++) {
            S  += pp[(((size_t)k_s*Bz + b)*Cc + c)*64 + sl];
            Q  += pp[(((size_t)k_q*Bz + b)*Cc + c)*64 + sl];
            X  += pp[(((size_t)k_x*Bz + b)*Cc + c)*64 + sl];
            XQ += pp[(((size_t)k_xq*Bz + b)*Cc + c)*64 + sl];
            SX += pp[(((size_t)k_sx*Bz + b)*Cc + c)*64 + sl];
        }
        sumT  += gt*S + X;
        sumT2 += gt*gt*Q + 2.f*gt*SX + XQ;
    }
    float N = (float)(Bz*HWi);
    float m = sumT/N;
    float var = sumT2/N - m*m;
    stat[(br*Cc + c)*2 + 0] = m;
    stat[(br*Cc + c)*2 + 1] = rsqrtf(var + 1e-5f);
}

// ---------------- finalize ----------------
__global__ void final_kernel(const float* __restrict__ x1, const float* __restrict__ x2,
                             const float* __restrict__ s1, const float* __restrict__ s2,
                             const float* __restrict__ gate, const float* __restrict__ stat,
                             const float* __restrict__ sc1, const float* __restrict__ bi1,
                             const float* __restrict__ sc2, const float* __restrict__ bi2,
                             float* __restrict__ out) {
    int n = blockIdx.x*256 + threadIdx.x;   // BCHW exact
    int c = (n >> 16) & 63;
    int b = n >> 22;
    float o1, o2;
    if ((c & 1) == 0) {
        o1 = x1[n]; o2 = x2[n];
    } else {
        float gt1 = gate[(0*Bz + b)*Cc + c];
        float gt2 = gate[(1*Bz + b)*Cc + c];
        float t1 = gt1*s1[n] + x1[n];
        float t2 = gt2*s2[n] + x2[n];
        float m1 = stat[(0*Cc + c)*2], is1 = stat[(0*Cc + c)*2 + 1];
        float m2 = stat[(1*Cc + c)*2], is2 = stat[(1*Cc + c)*2 + 1];
        o1 = fmaxf((t1 - m1)*is1*sc1[c] + bi1[c], 0.f);
        o2 = fmaxf((t2 - m2)*is2*sc2[c] + bi2[c], 0.f);
    }
    out[n] = o1;
    out[BCHW + n] = o2;
}

// ---------------- host launch ----------------
extern "C" void kernel_launch(void* const* d_in, const int* in_sizes, int n_in,
                              void* d_out, int out_size) {
    const float* x1  = (const float*)d_in[0];
    const float* x2  = (const float*)d_in[1];
    const float* wq1 = (const float*)d_in[2];
    const float* bq1 = (const float*)d_in[3];
    const float* wq2 = (const float*)d_in[4];
    const float* bq2 = (const float*)d_in[5];
    const float* wk1 = (const float*)d_in[6];
    const float* bk1 = (const float*)d_in[7];
    const float* wk2 = (const float*)d_in[8];
    const float* bk2 = (const float*)d_in[9];
    const float* wv1 = (const float*)d_in[10];
    const float* bv1 = (const float*)d_in[11];
    const float* wv2 = (const float*)d_in[12];
    const float* bv2 = (const float*)d_in[13];
    const float* gamma1 = (const float*)d_in[14];
    const float* gamma2 = (const float*)d_in[15];
    const float* sc1_w1 = (const float*)d_in[16];
    const float* sc1_b1 = (const float*)d_in[17];
    const float* sc1_w2 = (const float*)d_in[18];
    const float* sc1_b2 = (const float*)d_in[19];
    const float* sc2_w1 = (const float*)d_in[20];
    const float* sc2_b1 = (const float*)d_in[21];
    const float* sc2_w2 = (const float*)d_in[22];
    const float* sc2_b2 = (const float*)d_in[23];
    const float* bn1_scale = (const float*)d_in[24];
    const float* bn1_bias  = (const float*)d_in[25];
    const float* bn2_scale = (const float*)d_in[26];
    const float* bn2_bias  = (const float*)d_in[27];

    float *qkv, *qkvT, *mW, *sW, *mH, *sH, *fH, *fW;
    float *attHT, *attW, *s1, *s2, *pp, *gate, *stat;
    cudaGetSymbolAddress((void**)&qkv,  g_qkv);
    cudaGetSymbolAddress((void**)&qkvT, g_qkvT);
    cudaGetSymbolAddress((void**)&mW,  g_mW);
    cudaGetSymbolAddress((void**)&sW,  g_sW);
    cudaGetSymbolAddress((void**)&mH,  g_mH);
    cudaGetSymbolAddress((void**)&sH,  g_sH);
    cudaGetSymbolAddress((void**)&fH,  g_fH);
    cudaGetSymbolAddress((void**)&fW,  g_fW);
    cudaGetSymbolAddress((void**)&attHT, g_attHT);
    cudaGetSymbolAddress((void**)&attW,  g_attW);
    cudaGetSymbolAddress((void**)&s1, g_s1);
    cudaGetSymbolAddress((void**)&s2, g_s2);
    cudaGetSymbolAddress((void**)&pp, g_pp);
    cudaGetSymbolAddress((void**)&gate, g_gate);
    cudaGetSymbolAddress((void**)&stat, g_stat);

    float* q1 = qkv + (size_t)PQ1*HWi;
    float* q2 = qkv + (size_t)PQ2*HWi;
    float* k1 = qkv + (size_t)PK1*HWi;
    float* k2 = qkv + (size_t)PK2*HWi;
    float* v1 = qkv + (size_t)PV1*HWi;
    float* v2 = qkv + (size_t)PV2*HWi;

    cudaFuncSetAttribute(agg_kernel, cudaFuncAttributeMaxDynamicSharedMemorySize, AGG_SMEM);

    // projections
    proj_kernel<<<512, 256>>>(x1, wq1, bq1, wk1, bk1, wv1, bv1, q1, k1, v1);
    proj_kernel<<<512, 256>>>(x2, wq2, bq2, wk2, bk2, wv2, bv2, q2, k2, v2);

    // transpose all q/k/v planes
    transpose_kernel<<<dim3(64, NPLANES), 256>>>(qkv, qkvT);

    // aggregation with online per-direction softmax (one launch: both dirs, both crisses)
    agg_kernel<<<dim3(256, 4, 4), 128, AGG_SMEM>>>(qkv, qkvT, attW, attHT, mW, sW, mH, sH);

    // exact cross-direction merge factors
    factor_kernel<<<dim3(256, Bz, 2), 256>>>(mH, sH, mW, sW, fH, fW);

    // merge + ShareCA s-planes (odd channels) + fused pooled moments
    merge_kernel<<<dim3(64, Cc, Bz), 256>>>(attHT, attW, fH, fW, x1, x2,
                                            gamma1, gamma2, s1, s2, pp);

    // gates, BN stats, finalize
    gate_kernel<<<1, 256>>>(sc1_w1, sc1_b1, sc1_w2, sc1_b2,
                            sc2_w1, sc2_b1, sc2_w2, sc2_b2, pp, gate);
    bnstat_kernel<<<1, 128>>>(pp, gate, stat);
    final_kernel<<<BCHW/256, 256>>>(x1, x2, s1, s2, gate, stat,
                                    bn1_scale, bn1_bias, bn2_scale, bn2_bias, (float*)d_out);
}

// round 10
// speedup vs baseline: 3.3205x; 1.5650x over previous
#include <cuda_runtime.h>
#include <math.h>

#define Bz 2
#define Cc 64
#define CQ 8
#define CRr 4
#define HWi 65536
#define BCHW (Bz*Cc*HWi)      // 8388608

// plane offsets (in planes of 65536 floats) inside g_qkv / g_qkvT
#define PQ1 0
#define PQ2 16
#define PK1 32
#define PK2 48
#define PV1 64
#define PV2 192
#define NPLANES 320

// ---------------- scratch (device globals) ----------------
__device__ float g_qkv [NPLANES*HWi];
__device__ float g_qkvT[NPLANES*HWi];
__device__ float g_mW [2*Bz*HWi];
__device__ float g_sW [2*Bz*HWi];
__device__ float g_mH [2*Bz*HWi];
__device__ float g_sH [2*Bz*HWi];
__device__ float g_fH [2*Bz*HWi];
__device__ float g_fW [2*Bz*HWi];
__device__ float g_attHT[2*BCHW];
__device__ float g_attW [2*BCHW];
__device__ float g_s1[BCHW];
__device__ float g_s2[BCHW];
__device__ float g_pp[12*Bz*Cc*64];   // [stat][b][c][tile]
__device__ float g_gate[2*Bz*Cc];
__device__ float g_stat[2*Cc*2];

// ---------------- packed f32x2 helpers ----------------
__device__ __forceinline__ unsigned long long fma2(unsigned long long a, unsigned long long b,
                                                   unsigned long long c) {
    unsigned long long d;
    asm("fma.rn.f32x2 %0, %1, %2, %3;" : "=l"(d) : "l"(a), "l"(b), "l"(c));
    return d;
}
__device__ __forceinline__ unsigned long long packf2(float lo, float hi) {
    unsigned long long r;
    asm("mov.b64 %0, {%1, %2};" : "=l"(r) : "f"(lo), "f"(hi));
    return r;
}
__device__ __forceinline__ float2 unpackf2(unsigned long long a) {
    float2 r;
    asm("mov.b64 {%0, %1}, %2;" : "=f"(r.x), "=f"(r.y) : "l"(a));
    return r;
}
// pack two f32 into bf16x2: lo -> low half, hi -> high half
__device__ __forceinline__ unsigned int cvtbf2(float lo, float hi) {
    unsigned int r;
    asm("cvt.rn.bf16x2.f32 %0, %1, %2;" : "=r"(r) : "f"(hi), "f"(lo));
    return r;
}
// D += A * B  (m16n8k16, bf16 inputs, f32 accum)
__device__ __forceinline__ void mma_bf16(float* d,
    unsigned int a0, unsigned int a1, unsigned int a2, unsigned int a3,
    unsigned int b0, unsigned int b1) {
    asm volatile("mma.sync.aligned.m16n8k16.row.col.f32.bf16.bf16.f32 "
        "{%0,%1,%2,%3}, {%4,%5,%6,%7}, {%8,%9}, {%0,%1,%2,%3};"
        : "+f"(d[0]), "+f"(d[1]), "+f"(d[2]), "+f"(d[3])
        : "r"(a0), "r"(a1), "r"(a2), "r"(a3), "r"(b0), "r"(b1));
}

// ---------------- fused projection: x -> q(8), k(8), v(64) ----------------
__global__ __launch_bounds__(256) void proj_kernel(
    const float* __restrict__ x,
    const float* __restrict__ wq, const float* __restrict__ bq,
    const float* __restrict__ wk, const float* __restrict__ bk,
    const float* __restrict__ wv, const float* __restrict__ bv,
    float* __restrict__ q, float* __restrict__ k, float* __restrict__ v) {
    __shared__ unsigned long long ws2[64*40];
    __shared__ unsigned long long bs2[40];
    int tid = threadIdx.x;
    for (int i = tid; i < 64*40; i += 256) {
        int c = i / 40, t = i - (i/40)*40;
        float lo, hi;
        if (t < 4)      { lo = wq[(2*t)*Cc + c];       hi = wq[(2*t+1)*Cc + c]; }
        else if (t < 8) { lo = wk[(2*(t-4))*Cc + c];   hi = wk[(2*(t-4)+1)*Cc + c]; }
        else            { lo = wv[(2*(t-8))*Cc + c];   hi = wv[(2*(t-8)+1)*Cc + c]; }
        ws2[i] = packf2(lo, hi);
    }
    if (tid < 40) {
        int t = tid; float lo, hi;
        if (t < 4)      { lo = bq[2*t];       hi = bq[2*t+1]; }
        else if (t < 8) { lo = bk[2*(t-4)];   hi = bk[2*(t-4)+1]; }
        else            { lo = bv[2*(t-8)];   hi = bv[2*(t-8)+1]; }
        bs2[t] = packf2(lo, hi);
    }
    __syncthreads();
    int p = blockIdx.x*256 + tid;               // Bz*HW exact
    int b = p >> 16, hw = p & 65535;
    const float* xb = x + (size_t)b*Cc*HWi + hw;
    unsigned long long acc[40];
#pragma unroll
    for (int t = 0; t < 40; t++) acc[t] = bs2[t];
    for (int c = 0; c < Cc; c++) {
        float xv = __ldg(xb + (size_t)c*HWi);
        unsigned long long xx = packf2(xv, xv);
        const unsigned long long* w = ws2 + c*40;
#pragma unroll
        for (int t = 0; t < 40; t++) acc[t] = fma2(xx, w[t], acc[t]);
    }
    float* qo = q + (size_t)b*CQ*HWi + hw;
    float* ko = k + (size_t)b*CQ*HWi + hw;
    float* vo = v + (size_t)b*Cc*HWi + hw;
#pragma unroll
    for (int t = 0; t < 4; t++) {
        float2 r = unpackf2(acc[t]);
        qo[(size_t)(2*t)*HWi] = r.x; qo[(size_t)(2*t+1)*HWi] = r.y;
    }
#pragma unroll
    for (int t = 4; t < 8; t++) {
        float2 r = unpackf2(acc[t]);
        ko[(size_t)(2*(t-4))*HWi] = r.x; ko[(size_t)(2*(t-4)+1)*HWi] = r.y;
    }
#pragma unroll
    for (int t = 8; t < 40; t++) {
        float2 r = unpackf2(acc[t]);
        vo[(size_t)(2*(t-8))*HWi] = r.x; vo[(size_t)(2*(t-8)+1)*HWi] = r.y;
    }
}

// ---------------- tiled per-plane transpose ----------------
__global__ __launch_bounds__(256) void transpose_kernel(const float* __restrict__ src,
                                                        float* __restrict__ dst) {
    __shared__ float sm[32][33];
    int plane = blockIdx.y;
    int t = blockIdx.x;                     // 64 tiles
    int h0 = (t >> 3)*32, w0 = (t & 7)*32;
    const float* sp = src + (size_t)plane*HWi;
    float* dp = dst + (size_t)plane*HWi;
    int lx = threadIdx.x & 31, ly = threadIdx.x >> 5;
#pragma unroll
    for (int i = 0; i < 4; i++) {
        int hl = ly*4 + i;
        sm[hl][lx] = sp[(h0+hl)*256 + w0 + lx];
    }
    __syncthreads();
#pragma unroll
    for (int i = 0; i < 4; i++) {
        int wl = ly*4 + i;
        dp[(w0+wl)*256 + h0 + lx] = sm[lx][wl];
    }
}

// ---------------- aggregation: online softmax (fp32) + bf16 tensor-core P·V ----------------
// grid (256, 4, 4): x=o (line), y=(half<<1)|b, z=(dir<<1)|zc; 256 threads = 8 warps.
// Warp w owns m-tile rows [w*16, w*16+16) of the 128-row half-tile, all 64 channels.
// Thread (gid,tg): computes energies for rows (w*16+gid, +8) at k-pairs (2tg,2tg+1),(2tg+8,2tg+9)
// per k-step — exactly its mma A-fragment. Row softmax reduced over the 4-lane tg group.
// V staged as bf16x2 with k-pairs permuted so (b0,b1) is one LDS.64; stride 24 words (bank-clean).
__global__ __launch_bounds__(256,2) void agg_kernel(
    const float* __restrict__ qkv, const float* __restrict__ qkvT,
    float* __restrict__ attW, float* __restrict__ attHT,
    float* __restrict__ mW, float* __restrict__ sW,
    float* __restrict__ mH, float* __restrict__ sH) {
    __shared__ __align__(16) unsigned int Vbf[64*24];     // [c][ks*8 + perm(kk)]
    __shared__ unsigned long long kfs[8*17];              // [c][g-pair] fp32 pairs
    int o = blockIdx.x;
    int b = blockIdx.y & 1, half = blockIdx.y >> 1;
    int zc = blockIdx.z & 1, dir = blockIdx.z >> 1;
    const float* base = dir ? qkvT : qkv;
    const float* qp = base + (size_t)((zc ? PQ1 : PQ2) + b*CQ)*HWi + (size_t)o*256;
    const float* kp = base + (size_t)((zc ? PK2 : PK1) + b*CQ)*HWi + (size_t)o*256;
    const float* vp = base + (size_t)((zc ? PV2 : PV1) + b*Cc)*HWi + (size_t)o*256;
    float* out = (dir ? attHT : attW) + (size_t)zc*BCHW + (size_t)b*Cc*HWi
               + (size_t)o*256 + half*128;
    int tid = threadIdx.x;
    int w = tid >> 5, lane = tid & 31;
    int gid = lane >> 2, tg = lane & 3;
    int r0 = w*16 + gid, r1 = r0 + 8;           // local rows in half-tile

    // q for this thread's two rows, packed (q,q) for f32x2 energy FMAs
    unsigned long long qq0[8], qq1[8];
#pragma unroll
    for (int c = 0; c < 8; c++) {
        float v0 = qp[(size_t)c*HWi + half*128 + r0];
        float v1 = qp[(size_t)c*HWi + half*128 + r1];
        qq0[c] = packf2(v0, v0);
        qq1[c] = packf2(v1, v1);
    }
    float m0 = -1e30f, s0 = 0.f, m1 = -1e30f, s1 = 0.f;
    int gd0 = half*128 + r0, gd1 = half*128 + r1;

    float dacc[8][4];
#pragma unroll
    for (int i = 0; i < 8; i++)
#pragma unroll
        for (int j = 0; j < 4; j++) dacc[i][j] = 0.f;

    int stc = tid >> 2, stj = tid & 3;          // V staging coords
    int kc = tid >> 4, kpp = tid & 15;          // k staging coords (tid<128)

    float2 pv[4]; float2 pk = make_float2(0.f, 0.f);
    // ---- prefetch + stage chunk 0 ----
#pragma unroll
    for (int t = 0; t < 4; t++) {
        int kl = stj + 4*t, ks = kl >> 3, kk = kl & 7;
        pv[t] = *(const float2*)(vp + (size_t)stc*HWi + ks*16 + 2*kk);
    }
    if (tid < 128) pk = *(const float2*)(kp + (size_t)kc*HWi + 2*kpp);
#pragma unroll
    for (int t = 0; t < 4; t++) {
        int kl = stj + 4*t, ks = kl >> 3, kk = kl & 7;
        Vbf[stc*24 + ks*8 + 2*(kk&3) + (kk>>2)] = cvtbf2(pv[t].x, pv[t].y);
    }
    if (tid < 128) kfs[kc*17 + kpp] = packf2(pk.x, pk.y);
    __syncthreads();

    for (int g0 = 0; g0 < 256; g0 += 32) {
        // prefetch next chunk into registers (latency overlapped with compute)
        if (g0 + 32 < 256) {
#pragma unroll
            for (int t = 0; t < 4; t++) {
                int kl = stj + 4*t, ks = kl >> 3, kk = kl & 7;
                pv[t] = *(const float2*)(vp + (size_t)stc*HWi + g0 + 32 + ks*16 + 2*kk);
            }
            if (tid < 128) pk = *(const float2*)(kp + (size_t)kc*HWi + g0 + 32 + 2*kpp);
        }
        // ---- energies (fp32, f32x2-paired over g) ----
        float e0[8], e1[8];
        float cm0 = -1e30f, cm1 = -1e30f;
#pragma unroll
        for (int p4 = 0; p4 < 4; p4++) {
            int pp = tg + 4*p4;
            unsigned long long acc0 = 0ull, acc1 = 0ull;
#pragma unroll
            for (int c = 0; c < 8; c++) {
                unsigned long long kw = kfs[c*17 + pp];
                acc0 = fma2(qq0[c], kw, acc0);
                acc1 = fma2(qq1[c], kw, acc1);
            }
            float2 ee0 = unpackf2(acc0), ee1 = unpackf2(acc1);
            if (dir) {
                int ge = g0 + 2*pp;
                if (ge   == gd0) ee0.x = -1e30f;
                if (ge+1 == gd0) ee0.y = -1e30f;
                if (ge   == gd1) ee1.x = -1e30f;
                if (ge+1 == gd1) ee1.y = -1e30f;
            }
            e0[2*p4] = ee0.x; e0[2*p4+1] = ee0.y;
            e1[2*p4] = ee1.x; e1[2*p4+1] = ee1.y;
            cm0 = fmaxf(cm0, fmaxf(ee0.x, ee0.y));
            cm1 = fmaxf(cm1, fmaxf(ee1.x, ee1.y));
        }
        // row reductions over the 4-lane tg group
        cm0 = fmaxf(cm0, __shfl_xor_sync(0xffffffffu, cm0, 1));
        cm0 = fmaxf(cm0, __shfl_xor_sync(0xffffffffu, cm0, 2));
        cm1 = fmaxf(cm1, __shfl_xor_sync(0xffffffffu, cm1, 1));
        cm1 = fmaxf(cm1, __shfl_xor_sync(0xffffffffu, cm1, 2));
        float mn0 = fmaxf(m0, cm0), mn1 = fmaxf(m1, cm1);
        float p0v[8], p1v[8];
        float cs0 = 0.f, cs1 = 0.f;
#pragma unroll
        for (int j = 0; j < 8; j++) {
            p0v[j] = __expf(e0[j] - mn0); cs0 += p0v[j];
            p1v[j] = __expf(e1[j] - mn1); cs1 += p1v[j];
        }
        cs0 += __shfl_xor_sync(0xffffffffu, cs0, 1);
        cs0 += __shfl_xor_sync(0xffffffffu, cs0, 2);
        cs1 += __shfl_xor_sync(0xffffffffu, cs1, 1);
        cs1 += __shfl_xor_sync(0xffffffffu, cs1, 2);
        float rs0 = __expf(m0 - mn0), rs1 = __expf(m1 - mn1);
        s0 = s0*rs0 + cs0; m0 = mn0;
        s1 = s1*rs1 + cs1; m1 = mn1;
        // rescale accumulators (rows r0 -> d0,d1; rows r1 -> d2,d3)
#pragma unroll
        for (int nt = 0; nt < 8; nt++) {
            dacc[nt][0] *= rs0; dacc[nt][1] *= rs0;
            dacc[nt][2] *= rs1; dacc[nt][3] *= rs1;
        }
        // A fragments: bf16x2 (even k low, odd k high)
        unsigned int a00 = cvtbf2(p0v[0], p0v[1]);   // k-step0: (r0, k0-7 pair)
        unsigned int a01 = cvtbf2(p1v[0], p1v[1]);   //          (r1, k0-7 pair)
        unsigned int a02 = cvtbf2(p0v[2], p0v[3]);   //          (r0, k8-15 pair)
        unsigned int a03 = cvtbf2(p1v[2], p1v[3]);
        unsigned int a10 = cvtbf2(p0v[4], p0v[5]);   // k-step1
        unsigned int a11 = cvtbf2(p1v[4], p1v[5]);
        unsigned int a12 = cvtbf2(p0v[6], p0v[7]);
        unsigned int a13 = cvtbf2(p1v[6], p1v[7]);
        // ---- tensor-core P·V: 8 n-tiles x 2 k-steps ----
#pragma unroll
        for (int nt = 0; nt < 8; nt++) {
            int cw = (nt*8 + gid)*24 + 2*tg;
            uint2 bb0 = *(const uint2*)(Vbf + cw);       // (b0,b1) k-step0
            mma_bf16(dacc[nt], a00, a01, a02, a03, bb0.x, bb0.y);
            uint2 bb1 = *(const uint2*)(Vbf + cw + 8);   // (b0,b1) k-step1
            mma_bf16(dacc[nt], a10, a11, a12, a13, bb1.x, bb1.y);
        }
        __syncthreads();
        // stage prefetched next chunk
        if (g0 + 32 < 256) {
#pragma unroll
            for (int t = 0; t < 4; t++) {
                int kl = stj + 4*t, ks = kl >> 3, kk = kl & 7;
                Vbf[stc*24 + ks*8 + 2*(kk&3) + (kk>>2)] = cvtbf2(pv[t].x, pv[t].y);
            }
            if (tid < 128) kfs[kc*17 + kpp] = packf2(pk.x, pk.y);
        }
        __syncthreads();
    }
    // ---- write raw sums: D layout rows (r0,r1), cols 2tg-based ----
#pragma unroll
    for (int nt = 0; nt < 8; nt++) {
        int c = nt*8 + 2*tg;
        out[(size_t)c*HWi + r0]     = dacc[nt][0];
        out[(size_t)(c+1)*HWi + r0] = dacc[nt][1];
        out[(size_t)c*HWi + r1]     = dacc[nt][2];
        out[(size_t)(c+1)*HWi + r1] = dacc[nt][3];
    }
    // ---- per-row softmax stats (tg-group replicated; tg==0 writes) ----
    if (tg == 0) {
        size_t idx = ((size_t)zc*Bz + b)*HWi + o*256 + half*128;
        float* mo = dir ? mH : mW;
        float* so = dir ? sH : sW;
        mo[idx + r0] = m0; so[idx + r0] = s0;
        mo[idx + r1] = m1; so[idx + r1] = s1;
    }
}

// ---------------- merge factors (exact two-direction softmax combine) ----------------
__global__ void factor_kernel(const float* __restrict__ mH, const float* __restrict__ sH,
                              const float* __restrict__ mW, const float* __restrict__ sW,
                              float* __restrict__ fH, float* __restrict__ fW) {
    int p = blockIdx.x*256 + threadIdx.x;
    int b = blockIdx.y, z = blockIdx.z;
    size_t zb = ((size_t)z*Bz + b)*HWi;
    int h = p >> 8, w = p & 255;
    float mh = mH[zb + w*256 + h], sh = sH[zb + w*256 + h];
    float mw = mW[zb + p],         sw = sW[zb + p];
    float m = fmaxf(mh, mw);
    float eh = __expf(mh - m), ew = __expf(mw - m);
    float inv = 1.f/(sh*eh + sw*ew);
    fH[zb + p] = eh*inv;
    fW[zb + p] = ew*inv;
}

// ---------------- merge + fused pool: combine directions, emit s (odd c), 12 moments ----------------
__global__ __launch_bounds__(256) void merge_kernel(
    const float* __restrict__ attHT, const float* __restrict__ attW,
    const float* __restrict__ fH, const float* __restrict__ fW,
    const float* __restrict__ x1, const float* __restrict__ x2,
    const float* __restrict__ gamma1, const float* __restrict__ gamma2,
    float* __restrict__ s1, float* __restrict__ s2, float* __restrict__ pp) {
    __shared__ float sm1[32][33], sm2[32][33];
    int t = blockIdx.x, c = blockIdx.y, b = blockIdx.z;
    int w0 = (t & 7)*32, h0 = (t >> 3)*32;
    size_t pbase = ((size_t)b*Cc + c)*HWi;
    int lx = threadIdx.x & 31, ly = threadIdx.x >> 5;
    const float* a1T = attHT + pbase;
    const float* a2T = attHT + (size_t)BCHW + pbase;
#pragma unroll
    for (int i = 0; i < 4; i++) {
        int wl = ly*4 + i;
        size_t idx = (size_t)(w0+wl)*256 + h0 + lx;
        sm1[wl][lx] = a1T[idx];
        sm2[wl][lx] = a2T[idx];
    }
    __syncthreads();
    float g1 = gamma1[0], g2 = gamma2[0];
    size_t fb0 = (size_t)b*HWi;
    size_t fb1 = (size_t)(Bz + b)*HWi;
    bool odd = (c & 1);
    float sum1=0, sum2=0, mx1=-1e30f, mx2=-1e30f;
    float q1=0, xs1=0, xq1=0, sx1=0, q2=0, xs2=0, xq2=0, sx2=0;
#pragma unroll
    for (int i = 0; i < 4; i++) {
        int hl = ly*4 + i;
        int p = (h0+hl)*256 + w0 + lx;
        float a1 = sm1[lx][hl]*fH[fb0 + p] + attW[pbase + p]*fW[fb0 + p];
        float a2 = sm2[lx][hl]*fH[fb1 + p] + attW[(size_t)BCHW + pbase + p]*fW[fb1 + p];
        float xa = x1[pbase + p], xb = x2[pbase + p];
        float v1 = g2*a2 + xb + xa;
        float v2 = g1*a1 + xa + xb;
        if (odd) { s1[pbase + p] = v1; s2[pbase + p] = v2; }
        sum1 += v1; sum2 += v2;
        mx1 = fmaxf(mx1, v1); mx2 = fmaxf(mx2, v2);
        if (odd) {
            q1 += v1*v1; xs1 += xa; xq1 += xa*xa; sx1 += v1*xa;
            q2 += v2*v2; xs2 += xb; xq2 += xb*xb; sx2 += v2*xb;
        }
    }
    float vals[12] = {sum1, mx1, sum2, mx2, q1, xs1, xq1, sx1, q2, xs2, xq2, sx2};
    __shared__ float red[12][8];
    int lane = threadIdx.x & 31, wid = threadIdx.x >> 5;
#pragma unroll
    for (int kk = 0; kk < 12; kk++) {
        float v = vals[kk];
        if (kk == 1 || kk == 3) {
#pragma unroll
            for (int s = 16; s > 0; s >>= 1) v = fmaxf(v, __shfl_xor_sync(0xffffffffu, v, s));
        } else {
#pragma unroll
            for (int s = 16; s > 0; s >>= 1) v += __shfl_xor_sync(0xffffffffu, v, s);
        }
        if (lane == 0) red[kk][wid] = v;
    }
    __syncthreads();
    if (threadIdx.x < 12) {
        int kk = threadIdx.x;
        float acc = red[kk][0];
        for (int wwi = 1; wwi < 8; wwi++)
            acc = (kk == 1 || kk == 3) ? fmaxf(acc, red[kk][wwi]) : acc + red[kk][wwi];
        pp[(((size_t)kk*Bz + b)*Cc + c)*64 + t] = acc;
    }
}

// ---------------- gate: reduce pool partials + tiny MLP ----------------
__global__ void gate_kernel(const float* __restrict__ w1a, const float* __restrict__ b1a,
                            const float* __restrict__ w2a, const float* __restrict__ b2a,
                            const float* __restrict__ w1b, const float* __restrict__ b1b,
                            const float* __restrict__ w2b, const float* __restrict__ b2b,
                            const float* __restrict__ pp, float* __restrict__ gate) {
    __shared__ float pool_s[4][Bz][Cc];
    __shared__ float hid[2][Bz][2][CRr];
    int tid = threadIdx.x;
    for (int e = tid; e < 4*Bz*Cc; e += 256) {
        int kk = e >> 7, rem = e & 127;
        int bb = rem >> 6, c = rem & 63;
        bool ismax = (kk == 1 || kk == 3);
        float acc = ismax ? -1e30f : 0.f;
        for (int sl = 0; sl < 64; sl++) {
            float v = pp[(((size_t)kk*Bz + bb)*Cc + c)*64 + sl];
            acc = ismax ? fmaxf(acc, v) : acc + v;
        }
        if (!ismax) acc *= (1.f/65536.f);
        pool_s[kk][bb][c] = acc;
    }
    __syncthreads();
    if (tid < 2*Bz*2*CRr) {
        int r  = tid & (CRr-1);
        int mm = (tid >> 2) & 1;
        int bb = (tid >> 3) & 1;
        int br = (tid >> 4) & 1;
        const float* w1 = br ? w1b : w1a;
        const float* b1 = br ? b1b : b1a;
        const float* p = pool_s[br*2 + mm][bb];
        float acc = b1[r];
        for (int c = 0; c < Cc; c++) acc += w1[r*Cc + c]*p[c];
        hid[br][bb][mm][r] = fmaxf(acc, 0.f);
    }
    __syncthreads();
    int c = tid & 63, bb = (tid >> 6) & 1, br = tid >> 7;
    const float* w2 = br ? w2b : w2a;
    const float* b2 = br ? b2b : b2a;
    float o = 2.f*b2[c];
    for (int mm = 0; mm < 2; mm++)
#pragma unroll
        for (int r = 0; r < CRr; r++) o += w2[c*CRr + r]*hid[br][bb][mm][r];
    gate[(br*Bz + bb)*Cc + c] = 1.f/(1.f + expf(-o));
}

// ---------------- BN stats from moments (t = gate*s + x, odd channels) ----------------
__global__ void bnstat_kernel(const float* __restrict__ pp, const float* __restrict__ gate,
                              float* __restrict__ stat) {
    int tid = threadIdx.x;                 // 128: [branch][c]
    int br = tid >> 6, c = tid & 63;
    if (!(c & 1)) return;
    int k_s  = br ? 2 : 0;
    int k_q  = br ? 8 : 4;
    int k_x  = br ? 9 : 5;
    int k_xq = br ? 10 : 6;
    int k_sx = br ? 11 : 7;
    float sumT = 0.f, sumT2 = 0.f;
    for (int b = 0; b < Bz; b++) {
        float gt = gate[(br*Bz + b)*Cc + c];
        float S=0, Q=0, X=0, XQ=0, SX=0;
        for (int sl = 0; sl < 64; sl++) {
            S  += pp[(((size_t)k_s*Bz + b)*Cc + c)*64 + sl];
            Q  += pp[(((size_t)k_q*Bz + b)*Cc + c)*64 + sl];
            X  += pp[(((size_t)k_x*Bz + b)*Cc + c)*64 + sl];
            XQ += pp[(((size_t)k_xq*Bz + b)*Cc + c)*64 + sl];
            SX += pp[(((size_t)k_sx*Bz + b)*Cc + c)*64 + sl];
        }
        sumT  += gt*S + X;
        sumT2 += gt*gt*Q + 2.f*gt*SX + XQ;
    }
    float N = (float)(Bz*HWi);
    float m = sumT/N;
    float var = sumT2/N - m*m;
    stat[(br*Cc + c)*2 + 0] = m;
    stat[(br*Cc + c)*2 + 1] = rsqrtf(var + 1e-5f);
}

// ---------------- finalize ----------------
__global__ void final_kernel(const float* __restrict__ x1, const float* __restrict__ x2,
                             const float* __restrict__ s1, const float* __restrict__ s2,
                             const float* __restrict__ gate, const float* __restrict__ stat,
                             const float* __restrict__ sc1, const float* __restrict__ bi1,
                             const float* __restrict__ sc2, const float* __restrict__ bi2,
                             float* __restrict__ out) {
    int n = blockIdx.x*256 + threadIdx.x;   // BCHW exact
    int c = (n >> 16) & 63;
    int b = n >> 22;
    float o1, o2;
    if ((c & 1) == 0) {
        o1 = x1[n]; o2 = x2[n];
    } else {
        float gt1 = gate[(0*Bz + b)*Cc + c];
        float gt2 = gate[(1*Bz + b)*Cc + c];
        float t1 = gt1*s1[n] + x1[n];
        float t2 = gt2*s2[n] + x2[n];
        float m1 = stat[(0*Cc + c)*2], is1 = stat[(0*Cc + c)*2 + 1];
        float m2 = stat[(1*Cc + c)*2], is2 = stat[(1*Cc + c)*2 + 1];
        o1 = fmaxf((t1 - m1)*is1*sc1[c] + bi1[c], 0.f);
        o2 = fmaxf((t2 - m2)*is2*sc2[c] + bi2[c], 0.f);
    }
    out[n] = o1;
    out[BCHW + n] = o2;
}

// ---------------- host launch ----------------
extern "C" void kernel_launch(void* const* d_in, const int* in_sizes, int n_in,
                              void* d_out, int out_size) {
    const float* x1  = (const float*)d_in[0];
    const float* x2  = (const float*)d_in[1];
    const float* wq1 = (const float*)d_in[2];
    const float* bq1 = (const float*)d_in[3];
    const float* wq2 = (const float*)d_in[4];
    const float* bq2 = (const float*)d_in[5];
    const float* wk1 = (const float*)d_in[6];
    const float* bk1 = (const float*)d_in[7];
    const float* wk2 = (const float*)d_in[8];
    const float* bk2 = (const float*)d_in[9];
    const float* wv1 = (const float*)d_in[10];
    const float* bv1 = (const float*)d_in[11];
    const float* wv2 = (const float*)d_in[12];
    const float* bv2 = (const float*)d_in[13];
    const float* gamma1 = (const float*)d_in[14];
    const float* gamma2 = (const float*)d_in[15];
    const float* sc1_w1 = (const float*)d_in[16];
    const float* sc1_b1 = (const float*)d_in[17];
    const float* sc1_w2 = (const float*)d_in[18];
    const float* sc1_b2 = (const float*)d_in[19];
    const float* sc2_w1 = (const float*)d_in[20];
    const float* sc2_b1 = (const float*)d_in[21];
    const float* sc2_w2 = (const float*)d_in[22];
    const float* sc2_b2 = (const float*)d_in[23];
    const float* bn1_scale = (const float*)d_in[24];
    const float* bn1_bias  = (const float*)d_in[25];
    const float* bn2_scale = (const float*)d_in[26];
    const float* bn2_bias  = (const float*)d_in[27];

    float *qkv, *qkvT, *mW, *sW, *mH, *sH, *fH, *fW;
    float *attHT, *attW, *s1, *s2, *pp, *gate, *stat;
    cudaGetSymbolAddress((void**)&qkv,  g_qkv);
    cudaGetSymbolAddress((void**)&qkvT, g_qkvT);
    cudaGetSymbolAddress((void**)&mW,  g_mW);
    cudaGetSymbolAddress((void**)&sW,  g_sW);
    cudaGetSymbolAddress((void**)&mH,  g_mH);
    cudaGetSymbolAddress((void**)&sH,  g_sH);
    cudaGetSymbolAddress((void**)&fH,  g_fH);
    cudaGetSymbolAddress((void**)&fW,  g_fW);
    cudaGetSymbolAddress((void**)&attHT, g_attHT);
    cudaGetSymbolAddress((void**)&attW,  g_attW);
    cudaGetSymbolAddress((void**)&s1, g_s1);
    cudaGetSymbolAddress((void**)&s2, g_s2);
    cudaGetSymbolAddress((void**)&pp, g_pp);
    cudaGetSymbolAddress((void**)&gate, g_gate);
    cudaGetSymbolAddress((void**)&stat, g_stat);

    float* q1 = qkv + (size_t)PQ1*HWi;
    float* q2 = qkv + (size_t)PQ2*HWi;
    float* k1 = qkv + (size_t)PK1*HWi;
    float* k2 = qkv + (size_t)PK2*HWi;
    float* v1 = qkv + (size_t)PV1*HWi;
    float* v2 = qkv + (size_t)PV2*HWi;

    // projections
    proj_kernel<<<512, 256>>>(x1, wq1, bq1, wk1, bk1, wv1, bv1, q1, k1, v1);
    proj_kernel<<<512, 256>>>(x2, wq2, bq2, wk2, bk2, wv2, bv2, q2, k2, v2);

    // transpose all q/k/v planes
    transpose_kernel<<<dim3(64, NPLANES), 256>>>(qkv, qkvT);

    // aggregation: online softmax + bf16 tensor-core P·V (one launch, both dirs/crisses)
    agg_kernel<<<dim3(256, 4, 4), 256>>>(qkv, qkvT, attW, attHT, mW, sW, mH, sH);

    // exact cross-direction merge factors
    factor_kernel<<<dim3(256, Bz, 2), 256>>>(mH, sH, mW, sW, fH, fW);

    // merge + ShareCA s-planes (odd channels) + fused pooled moments
    merge_kernel<<<dim3(64, Cc, Bz), 256>>>(attHT, attW, fH, fW, x1, x2,
                                            gamma1, gamma2, s1, s2, pp);

    // gates, BN stats, finalize
    gate_kernel<<<1, 256>>>(sc1_w1, sc1_b1, sc1_w2, sc1_b2,
                            sc2_w1, sc2_b1, sc2_w2, sc2_b2, pp, gate);
    bnstat_kernel<<<1, 128>>>(pp, gate, stat);
    final_kernel<<<BCHW/256, 256>>>(x1, x2, s1, s2, gate, stat,
                                    bn1_scale, bn1_bias, bn2_scale, bn2_bias, (float*)d_out);
}

// round 13
// speedup vs baseline: 3.4028x; 1.0248x over previous
#include <cuda_runtime.h>
#include <cuda_fp16.h>
#include <math.h>

#define Bz 2
#define Cc 64
#define CQ 8
#define CRr 4
#define HWi 65536
#define BCHW (Bz*Cc*HWi)      // 8388608

// plane offsets inside g_qk / g_qkT (fp32, 64 planes)
#define PQ1 0
#define PQ2 16
#define PK1 32
#define PK2 48

// ---------------- scratch (device globals) ----------------
__device__ float  g_qk [64*HWi];
__device__ float  g_qkT[64*HWi];
__device__ __half g_v  [256*HWi];     // v1: planes 0..127 (b*64+c), v2: 128..255
__device__ __half g_vT [256*HWi];
__device__ float g_mW [2*Bz*HWi];
__device__ float g_sW [2*Bz*HWi];
__device__ float g_mH [2*Bz*HWi];
__device__ float g_sH [2*Bz*HWi];
__device__ float g_fH [2*Bz*HWi];
__device__ float g_fW [2*Bz*HWi];
__device__ __half g_attHT[2*BCHW];
__device__ __half g_attW [2*BCHW];
__device__ float g_s1[BCHW];
__device__ float g_s2[BCHW];
__device__ float g_pp[12*Bz*Cc*64];   // [stat][b][c][tile]
__device__ float g_gate[2*Bz*Cc];
__device__ float g_stat[2*Cc*2];

// ---------------- packed f32x2 helpers ----------------
__device__ __forceinline__ unsigned long long fma2(unsigned long long a, unsigned long long b,
                                                   unsigned long long c) {
    unsigned long long d;
    asm("fma.rn.f32x2 %0, %1, %2, %3;" : "=l"(d) : "l"(a), "l"(b), "l"(c));
    return d;
}
__device__ __forceinline__ unsigned long long packf2(float lo, float hi) {
    unsigned long long r;
    asm("mov.b64 %0, {%1, %2};" : "=l"(r) : "f"(lo), "f"(hi));
    return r;
}
__device__ __forceinline__ float2 unpackf2(unsigned long long a) {
    float2 r;
    asm("mov.b64 {%0, %1}, %2;" : "=f"(r.x), "=f"(r.y) : "l"(a));
    return r;
}
// pack two f32 into f16x2: lo -> low half, hi -> high half
__device__ __forceinline__ unsigned int cvth2(float lo, float hi) {
    unsigned int r;
    asm("cvt.rn.f16x2.f32 %0, %1, %2;" : "=r"(r) : "f"(hi), "f"(lo));
    return r;
}
// D += A * B  (m16n8k16, f16 inputs, f32 accum)
__device__ __forceinline__ void mma_f16(float* d,
    unsigned int a0, unsigned int a1, unsigned int a2, unsigned int a3,
    unsigned int b0, unsigned int b1) {
    asm volatile("mma.sync.aligned.m16n8k16.row.col.f32.f16.f16.f32 "
        "{%0,%1,%2,%3}, {%4,%5,%6,%7}, {%8,%9}, {%0,%1,%2,%3};"
        : "+f"(d[0]), "+f"(d[1]), "+f"(d[2]), "+f"(d[3])
        : "r"(a0), "r"(a1), "r"(a2), "r"(a3), "r"(b0), "r"(b1));
}

// ---------------- fused projection: x -> q(8), k(8) fp32, v(64) fp16 ----------------
__global__ __launch_bounds__(256) void proj_kernel(
    const float* __restrict__ x,
    const float* __restrict__ wq, const float* __restrict__ bq,
    const float* __restrict__ wk, const float* __restrict__ bk,
    const float* __restrict__ wv, const float* __restrict__ bv,
    float* __restrict__ q, float* __restrict__ k, __half* __restrict__ v) {
    __shared__ unsigned long long ws2[64*40];
    __shared__ unsigned long long bs2[40];
    int tid = threadIdx.x;
    for (int i = tid; i < 64*40; i += 256) {
        int c = i / 40, t = i - (i/40)*40;
        float lo, hi;
        if (t < 4)      { lo = wq[(2*t)*Cc + c];       hi = wq[(2*t+1)*Cc + c]; }
        else if (t < 8) { lo = wk[(2*(t-4))*Cc + c];   hi = wk[(2*(t-4)+1)*Cc + c]; }
        else            { lo = wv[(2*(t-8))*Cc + c];   hi = wv[(2*(t-8)+1)*Cc + c]; }
        ws2[i] = packf2(lo, hi);
    }
    if (tid < 40) {
        int t = tid; float lo, hi;
        if (t < 4)      { lo = bq[2*t];       hi = bq[2*t+1]; }
        else if (t < 8) { lo = bk[2*(t-4)];   hi = bk[2*(t-4)+1]; }
        else            { lo = bv[2*(t-8)];   hi = bv[2*(t-8)+1]; }
        bs2[t] = packf2(lo, hi);
    }
    __syncthreads();
    int p = blockIdx.x*256 + tid;               // Bz*HW exact
    int b = p >> 16, hw = p & 65535;
    const float* xb = x + (size_t)b*Cc*HWi + hw;
    unsigned long long acc[40];
#pragma unroll
    for (int t = 0; t < 40; t++) acc[t] = bs2[t];
    for (int c = 0; c < Cc; c++) {
        float xv = __ldg(xb + (size_t)c*HWi);
        unsigned long long xx = packf2(xv, xv);
        const unsigned long long* w = ws2 + c*40;
#pragma unroll
        for (int t = 0; t < 40; t++) acc[t] = fma2(xx, w[t], acc[t]);
    }
    float* qo = q + (size_t)b*CQ*HWi + hw;
    float* ko = k + (size_t)b*CQ*HWi + hw;
    __half* vo = v + (size_t)b*Cc*HWi + hw;
#pragma unroll
    for (int t = 0; t < 4; t++) {
        float2 r = unpackf2(acc[t]);
        qo[(size_t)(2*t)*HWi] = r.x; qo[(size_t)(2*t+1)*HWi] = r.y;
    }
#pragma unroll
    for (int t = 4; t < 8; t++) {
        float2 r = unpackf2(acc[t]);
        ko[(size_t)(2*(t-4))*HWi] = r.x; ko[(size_t)(2*(t-4)+1)*HWi] = r.y;
    }
#pragma unroll
    for (int t = 8; t < 40; t++) {
        float2 r = unpackf2(acc[t]);
        vo[(size_t)(2*(t-8))*HWi]   = __float2half_rn(r.x);
        vo[(size_t)(2*(t-8)+1)*HWi] = __float2half_rn(r.y);
    }
}

// ---------------- tiled per-plane transpose (fp32 q/k) ----------------
__global__ __launch_bounds__(256) void transpose_f32(const float* __restrict__ src,
                                                     float* __restrict__ dst) {
    __shared__ float sm[32][33];
    int plane = blockIdx.y;
    int t = blockIdx.x;                     // 64 tiles
    int h0 = (t >> 3)*32, w0 = (t & 7)*32;
    const float* sp = src + (size_t)plane*HWi;
    float* dp = dst + (size_t)plane*HWi;
    int lx = threadIdx.x & 31, ly = threadIdx.x >> 5;
#pragma unroll
    for (int i = 0; i < 4; i++) {
        int hl = ly*4 + i;
        sm[hl][lx] = sp[(h0+hl)*256 + w0 + lx];
    }
    __syncthreads();
#pragma unroll
    for (int i = 0; i < 4; i++) {
        int wl = ly*4 + i;
        dp[(w0+wl)*256 + h0 + lx] = sm[lx][wl];
    }
}

// ---------------- tiled per-plane transpose (u16 = fp16 v) ----------------
__global__ __launch_bounds__(256) void transpose_u16(const unsigned short* __restrict__ src,
                                                     unsigned short* __restrict__ dst) {
    __shared__ unsigned short sm[32][33];
    int plane = blockIdx.y;
    int t = blockIdx.x;
    int h0 = (t >> 3)*32, w0 = (t & 7)*32;
    const unsigned short* sp = src + (size_t)plane*HWi;
    unsigned short* dp = dst + (size_t)plane*HWi;
    int lx = threadIdx.x & 31, ly = threadIdx.x >> 5;
#pragma unroll
    for (int i = 0; i < 4; i++) {
        int hl = ly*4 + i;
        sm[hl][lx] = sp[(h0+hl)*256 + w0 + lx];
    }
    __syncthreads();
#pragma unroll
    for (int i = 0; i < 4; i++) {
        int wl = ly*4 + i;
        dp[(w0+wl)*256 + h0 + lx] = sm[lx][wl];
    }
}

// ---------------- aggregation: online softmax (fp32) + f16 tensor-core P·V ----------------
// grid (256, 4, 4): x=o (line), y=(half<<1)|b, z=(dir<<1)|zc; 256 threads = 8 warps.
// Warp w owns m-tile rows [w*16, w*16+16) of the 128-row half-tile, all 64 channels.
// V already fp16 in gmem: staging is raw f16x2 word copies (no cvt). att written fp16.
__global__ __launch_bounds__(256,2) void agg_kernel(
    const float* __restrict__ qk, const float* __restrict__ qkT,
    const __half* __restrict__ vb, const __half* __restrict__ vbT,
    __half* __restrict__ attW, __half* __restrict__ attHT,
    float* __restrict__ mW, float* __restrict__ sW,
    float* __restrict__ mH, float* __restrict__ sH) {
    __shared__ __align__(16) unsigned int Vbf[64*24];     // [c][ks*8 + perm(kk)] f16x2 words
    __shared__ unsigned long long kfs[8*17];              // [c][g-pair] fp32 pairs
    int o = blockIdx.x;
    int b = blockIdx.y & 1, hf = blockIdx.y >> 1;
    int zc = blockIdx.z & 1, dir = blockIdx.z >> 1;
    const float* base = dir ? qkT : qk;
    const float* qp = base + (size_t)((zc ? PQ1 : PQ2) + b*CQ)*HWi + (size_t)o*256;
    const float* kp = base + (size_t)((zc ? PK2 : PK1) + b*CQ)*HWi + (size_t)o*256;
    const __half* vbase = dir ? vbT : vb;
    const unsigned int* vpw = (const unsigned int*)(vbase + (size_t)((zc ? 128 : 0) + b*Cc)*HWi)
                            + (size_t)o*128;              // f16x2 words; ch stride 32768 words
    __half* out = (dir ? attHT : attW) + (size_t)zc*BCHW + (size_t)b*Cc*HWi
                + (size_t)o*256 + hf*128;
    int tid = threadIdx.x;
    int w = tid >> 5, lane = tid & 31;
    int gid = lane >> 2, tg = lane & 3;
    int r0 = w*16 + gid, r1 = r0 + 8;           // local rows in half-tile

    // q for this thread's two rows, packed (q,q) for f32x2 energy FMAs
    unsigned long long qq0[8], qq1[8];
#pragma unroll
    for (int c = 0; c < 8; c++) {
        float v0 = qp[(size_t)c*HWi + hf*128 + r0];
        float v1 = qp[(size_t)c*HWi + hf*128 + r1];
        qq0[c] = packf2(v0, v0);
        qq1[c] = packf2(v1, v1);
    }
    float m0 = -1e30f, s0 = 0.f, m1 = -1e30f, s1 = 0.f;
    int gd0 = hf*128 + r0, gd1 = hf*128 + r1;

    float dacc[8][4];
#pragma unroll
    for (int i = 0; i < 8; i++)
#pragma unroll
        for (int j = 0; j < 4; j++) dacc[i][j] = 0.f;

    int stc = tid >> 2, stj = tid & 3;          // V staging coords (ch, word-group)
    int kc = tid >> 4, kpp = tid & 15;          // k staging coords (tid<128)

    unsigned int pv[4]; float2 pk = make_float2(0.f, 0.f);
    // ---- prefetch + stage chunk 0 ----
#pragma unroll
    for (int t = 0; t < 4; t++) {
        int kl = stj + 4*t;
        pv[t] = vpw[(size_t)stc*32768 + kl];
    }
    if (tid < 128) pk = *(const float2*)(kp + (size_t)kc*HWi + 2*kpp);
#pragma unroll
    for (int t = 0; t < 4; t++) {
        int kl = stj + 4*t, ks = kl >> 3, kk = kl & 7;
        Vbf[stc*24 + ks*8 + 2*(kk&3) + (kk>>2)] = pv[t];
    }
    if (tid < 128) kfs[kc*17 + kpp] = packf2(pk.x, pk.y);
    __syncthreads();

    for (int g0 = 0; g0 < 256; g0 += 32) {
        // prefetch next chunk into registers (latency overlapped with compute)
        if (g0 + 32 < 256) {
#pragma unroll
            for (int t = 0; t < 4; t++) {
                int kl = stj + 4*t;
                pv[t] = vpw[(size_t)stc*32768 + ((g0+32) >> 1) + kl];
            }
            if (tid < 128) pk = *(const float2*)(kp + (size_t)kc*HWi + g0 + 32 + 2*kpp);
        }
        // ---- energies (fp32, f32x2-paired over g) ----
        float e0[8], e1[8];
        float cm0 = -1e30f, cm1 = -1e30f;
#pragma unroll
        for (int p4 = 0; p4 < 4; p4++) {
            int pp = tg + 4*p4;
            unsigned long long acc0 = 0ull, acc1 = 0ull;
#pragma unroll
            for (int c = 0; c < 8; c++) {
                unsigned long long kw = kfs[c*17 + pp];
                acc0 = fma2(qq0[c], kw, acc0);
                acc1 = fma2(qq1[c], kw, acc1);
            }
            float2 ee0 = unpackf2(acc0), ee1 = unpackf2(acc1);
            if (dir) {
                int ge = g0 + 2*pp;
                if (ge   == gd0) ee0.x = -1e30f;
                if (ge+1 == gd0) ee0.y = -1e30f;
                if (ge   == gd1) ee1.x = -1e30f;
                if (ge+1 == gd1) ee1.y = -1e30f;
            }
            e0[2*p4] = ee0.x; e0[2*p4+1] = ee0.y;
            e1[2*p4] = ee1.x; e1[2*p4+1] = ee1.y;
            cm0 = fmaxf(cm0, fmaxf(ee0.x, ee0.y));
            cm1 = fmaxf(cm1, fmaxf(ee1.x, ee1.y));
        }
        // row reductions over the 4-lane tg group
        cm0 = fmaxf(cm0, __shfl_xor_sync(0xffffffffu, cm0, 1));
        cm0 = fmaxf(cm0, __shfl_xor_sync(0xffffffffu, cm0, 2));
        cm1 = fmaxf(cm1, __shfl_xor_sync(0xffffffffu, cm1, 1));
        cm1 = fmaxf(cm1, __shfl_xor_sync(0xffffffffu, cm1, 2));
        float mn0 = fmaxf(m0, cm0), mn1 = fmaxf(m1, cm1);
        float p0v[8], p1v[8];
        float cs0 = 0.f, cs1 = 0.f;
#pragma unroll
        for (int j = 0; j < 8; j++) {
            p0v[j] = __expf(e0[j] - mn0); cs0 += p0v[j];
            p1v[j] = __expf(e1[j] - mn1); cs1 += p1v[j];
        }
        cs0 += __shfl_xor_sync(0xffffffffu, cs0, 1);
        cs0 += __shfl_xor_sync(0xffffffffu, cs0, 2);
        cs1 += __shfl_xor_sync(0xffffffffu, cs1, 1);
        cs1 += __shfl_xor_sync(0xffffffffu, cs1, 2);
        float rs0 = __expf(m0 - mn0), rs1 = __expf(m1 - mn1);
        s0 = s0*rs0 + cs0; m0 = mn0;
        s1 = s1*rs1 + cs1; m1 = mn1;
        // rescale accumulators (rows r0 -> d0,d1; rows r1 -> d2,d3)
#pragma unroll
        for (int nt = 0; nt < 8; nt++) {
            dacc[nt][0] *= rs0; dacc[nt][1] *= rs0;
            dacc[nt][2] *= rs1; dacc[nt][3] *= rs1;
        }
        // A fragments: f16x2 (even k low, odd k high)
        unsigned int a00 = cvth2(p0v[0], p0v[1]);
        unsigned int a01 = cvth2(p1v[0], p1v[1]);
        unsigned int a02 = cvth2(p0v[2], p0v[3]);
        unsigned int a03 = cvth2(p1v[2], p1v[3]);
        unsigned int a10 = cvth2(p0v[4], p0v[5]);
        unsigned int a11 = cvth2(p1v[4], p1v[5]);
        unsigned int a12 = cvth2(p0v[6], p0v[7]);
        unsigned int a13 = cvth2(p1v[6], p1v[7]);
        // ---- tensor-core P·V: 8 n-tiles x 2 k-steps ----
#pragma unroll
        for (int nt = 0; nt < 8; nt++) {
            int cw = (nt*8 + gid)*24 + 2*tg;
            uint2 bb0 = *(const uint2*)(Vbf + cw);       // (b0,b1) k-step0
            mma_f16(dacc[nt], a00, a01, a02, a03, bb0.x, bb0.y);
            uint2 bb1 = *(const uint2*)(Vbf + cw + 8);   // (b0,b1) k-step1
            mma_f16(dacc[nt], a10, a11, a12, a13, bb1.x, bb1.y);
        }
        __syncthreads();
        // stage prefetched next chunk
        if (g0 + 32 < 256) {
#pragma unroll
            for (int t = 0; t < 4; t++) {
                int kl = stj + 4*t, ks = kl >> 3, kk = kl & 7;
                Vbf[stc*24 + ks*8 + 2*(kk&3) + (kk>>2)] = pv[t];
            }
            if (tid < 128) kfs[kc*17 + kpp] = packf2(pk.x, pk.y);
        }
        __syncthreads();
    }
    // ---- write raw sums (fp16): rows (r0,r1), cols 2tg-based ----
#pragma unroll
    for (int nt = 0; nt < 8; nt++) {
        int c = nt*8 + 2*tg;
        out[(size_t)c*HWi + r0]     = __float2half_rn(dacc[nt][0]);
        out[(size_t)(c+1)*HWi + r0] = __float2half_rn(dacc[nt][1]);
        out[(size_t)c*HWi + r1]     = __float2half_rn(dacc[nt][2]);
        out[(size_t)(c+1)*HWi + r1] = __float2half_rn(dacc[nt][3]);
    }
    // ---- per-row softmax stats (tg-group replicated; tg==0 writes) ----
    if (tg == 0) {
        size_t idx = ((size_t)zc*Bz + b)*HWi + o*256 + hf*128;
        float* mo = dir ? mH : mW;
        float* so = dir ? sH : sW;
        mo[idx + r0] = m0; so[idx + r0] = s0;
        mo[idx + r1] = m1; so[idx + r1] = s1;
    }
}

// ---------------- merge factors (exact two-direction softmax combine) ----------------
__global__ void factor_kernel(const float* __restrict__ mH, const float* __restrict__ sH,
                              const float* __restrict__ mW, const float* __restrict__ sW,
                              float* __restrict__ fH, float* __restrict__ fW) {
    int p = blockIdx.x*256 + threadIdx.x;
    int b = blockIdx.y, z = blockIdx.z;
    size_t zb = ((size_t)z*Bz + b)*HWi;
    int h = p >> 8, w = p & 255;
    float mh = mH[zb + w*256 + h], sh = sH[zb + w*256 + h];
    float mw = mW[zb + p],         sw = sW[zb + p];
    float m = fmaxf(mh, mw);
    float eh = __expf(mh - m), ew = __expf(mw - m);
    float inv = 1.f/(sh*eh + sw*ew);
    fH[zb + p] = eh*inv;
    fW[zb + p] = ew*inv;
}

// ---------------- merge + fused pool: combine directions, emit s (odd c), 12 moments ----------------
__global__ __launch_bounds__(256) void merge_kernel(
    const __half* __restrict__ attHT, const __half* __restrict__ attW,
    const float* __restrict__ fH, const float* __restrict__ fW,
    const float* __restrict__ x1, const float* __restrict__ x2,
    const float* __restrict__ gamma1, const float* __restrict__ gamma2,
    float* __restrict__ s1, float* __restrict__ s2, float* __restrict__ pp) {
    __shared__ float sm1[32][33], sm2[32][33];
    int t = blockIdx.x, c = blockIdx.y, b = blockIdx.z;
    int w0 = (t & 7)*32, h0 = (t >> 3)*32;
    size_t pbase = ((size_t)b*Cc + c)*HWi;
    int lx = threadIdx.x & 31, ly = threadIdx.x >> 5;
    const __half* a1T = attHT + pbase;
    const __half* a2T = attHT + (size_t)BCHW + pbase;
#pragma unroll
    for (int i = 0; i < 4; i++) {
        int wl = ly*4 + i;
        size_t idx = (size_t)(w0+wl)*256 + h0 + lx;
        sm1[wl][lx] = __half2float(a1T[idx]);
        sm2[wl][lx] = __half2float(a2T[idx]);
    }
    __syncthreads();
    float g1 = gamma1[0], g2 = gamma2[0];
    size_t fb0 = (size_t)b*HWi;
    size_t fb1 = (size_t)(Bz + b)*HWi;
    bool odd = (c & 1);
    float sum1=0, sum2=0, mx1=-1e30f, mx2=-1e30f;
    float q1=0, xs1=0, xq1=0, sx1=0, q2=0, xs2=0, xq2=0, sx2=0;
#pragma unroll
    for (int i = 0; i < 4; i++) {
        int hl = ly*4 + i;
        int p = (h0+hl)*256 + w0 + lx;
        float a1 = sm1[lx][hl]*fH[fb0 + p] + __half2float(attW[pbase + p])*fW[fb0 + p];
        float a2 = sm2[lx][hl]*fH[fb1 + p]
                 + __half2float(attW[(size_t)BCHW + pbase + p])*fW[fb1 + p];
        float xa = x1[pbase + p], xb = x2[pbase + p];
        float v1 = g2*a2 + xb + xa;
        float v2 = g1*a1 + xa + xb;
        if (odd) { s1[pbase + p] = v1; s2[pbase + p] = v2; }
        sum1 += v1; sum2 += v2;
        mx1 = fmaxf(mx1, v1); mx2 = fmaxf(mx2, v2);
        if (odd) {
            q1 += v1*v1; xs1 += xa; xq1 += xa*xa; sx1 += v1*xa;
            q2 += v2*v2; xs2 += xb; xq2 += xb*xb; sx2 += v2*xb;
        }
    }
    float vals[12] = {sum1, mx1, sum2, mx2, q1, xs1, xq1, sx1, q2, xs2, xq2, sx2};
    __shared__ float red[12][8];
    int lane = threadIdx.x & 31, wid = threadIdx.x >> 5;
#pragma unroll
    for (int kk = 0; kk < 12; kk++) {
        float v = vals[kk];
        if (kk == 1 || kk == 3) {
#pragma unroll
            for (int s = 16; s > 0; s >>= 1) v = fmaxf(v, __shfl_xor_sync(0xffffffffu, v, s));
        } else {
#pragma unroll
            for (int s = 16; s > 0; s >>= 1) v += __shfl_xor_sync(0xffffffffu, v, s);
        }
        if (lane == 0) red[kk][wid] = v;
    }
    __syncthreads();
    if (threadIdx.x < 12) {
        int kk = threadIdx.x;
        float acc = red[kk][0];
        for (int wwi = 1; wwi < 8; wwi++)
            acc = (kk == 1 || kk == 3) ? fmaxf(acc, red[kk][wwi]) : acc + red[kk][wwi];
        pp[(((size_t)kk*Bz + b)*Cc + c)*64 + t] = acc;
    }
}

// ---------------- gate: reduce pool partials + tiny MLP ----------------
__global__ void gate_kernel(const float* __restrict__ w1a, const float* __restrict__ b1a,
                            const float* __restrict__ w2a, const float* __restrict__ b2a,
                            const float* __restrict__ w1b, const float* __restrict__ b1b,
                            const float* __restrict__ w2b, const float* __restrict__ b2b,
                            const float* __restrict__ pp, float* __restrict__ gate) {
    __shared__ float pool_s[4][Bz][Cc];
    __shared__ float hid[2][Bz][2][CRr];
    int tid = threadIdx.x;
    for (int e = tid; e < 4*Bz*Cc; e += 256) {
        int kk = e >> 7, rem = e & 127;
        int bb = rem >> 6, c = rem & 63;
        bool ismax = (kk == 1 || kk == 3);
        float acc = ismax ? -1e30f : 0.f;
        for (int sl = 0; sl < 64; sl++) {
            float v = pp[(((size_t)kk*Bz + bb)*Cc + c)*64 + sl];
            acc = ismax ? fmaxf(acc, v) : acc + v;
        }
        if (!ismax) acc *= (1.f/65536.f);
        pool_s[kk][bb][c] = acc;
    }
    __syncthreads();
    if (tid < 2*Bz*2*CRr) {
        int r  = tid & (CRr-1);
        int mm = (tid >> 2) & 1;
        int bb = (tid >> 3) & 1;
        int br = (tid >> 4) & 1;
        const float* w1 = br ? w1b : w1a;
        const float* b1 = br ? b1b : b1a;
        const float* p = pool_s[br*2 + mm][bb];
        float acc = b1[r];
        for (int c = 0; c < Cc; c++) acc += w1[r*Cc + c]*p[c];
        hid[br][bb][mm][r] = fmaxf(acc, 0.f);
    }
    __syncthreads();
    int c = tid & 63, bb = (tid >> 6) & 1, br = tid >> 7;
    const float* w2 = br ? w2b : w2a;
    const float* b2 = br ? b2b : b2a;
    float o = 2.f*b2[c];
    for (int mm = 0; mm < 2; mm++)
#pragma unroll
        for (int r = 0; r < CRr; r++) o += w2[c*CRr + r]*hid[br][bb][mm][r];
    gate[(br*Bz + bb)*Cc + c] = 1.f/(1.f + expf(-o));
}

// ---------------- BN stats from moments (t = gate*s + x, odd channels) ----------------
__global__ void bnstat_kernel(const float* __restrict__ pp, const float* __restrict__ gate,
                              float* __restrict__ stat) {
    int tid = threadIdx.x;                 // 128: [branch][c]
    int br = tid >> 6, c = tid & 63;
    if (!(c & 1)) return;
    int k_s  = br ? 2 : 0;
    int k_q  = br ? 8 : 4;
    int k_x  = br ? 9 : 5;
    int k_xq = br ? 10 : 6;
    int k_sx = br ? 11 : 7;
    float sumT = 0.f, sumT2 = 0.f;
    for (int b = 0; b < Bz; b++) {
        float gt = gate[(br*Bz + b)*Cc + c];
        float S=0, Q=0, X=0, XQ=0, SX=0;
        for (int sl = 0; sl < 64; sl++) {
            S  += pp[(((size_t)k_s*Bz + b)*Cc + c)*64 + sl];
            Q  += pp[(((size_t)k_q*Bz + b)*Cc + c)*64 + sl];
            X  += pp[(((size_t)k_x*Bz + b)*Cc + c)*64 + sl];
            XQ += pp[(((size_t)k_xq*Bz + b)*Cc + c)*64 + sl];
            SX += pp[(((size_t)k_sx*Bz + b)*Cc + c)*64 + sl];
        }
        sumT  += gt*S + X;
        sumT2 += gt*gt*Q + 2.f*gt*SX + XQ;
    }
    float N = (float)(Bz*HWi);
    float m = sumT/N;
    float var = sumT2/N - m*m;
    stat[(br*Cc + c)*2 + 0] = m;
    stat[(br*Cc + c)*2 + 1] = rsqrtf(var + 1e-5f);
}

// ---------------- finalize ----------------
__global__ void final_kernel(const float* __restrict__ x1, const float* __restrict__ x2,
                             const float* __restrict__ s1, const float* __restrict__ s2,
                             const float* __restrict__ gate, const float* __restrict__ stat,
                             const float* __restrict__ sc1, const float* __restrict__ bi1,
                             const float* __restrict__ sc2, const float* __restrict__ bi2,
                             float* __restrict__ out) {
    int n = blockIdx.x*256 + threadIdx.x;   // BCHW exact
    int c = (n >> 16) & 63;
    int b = n >> 22;
    float o1, o2;
    if ((c & 1) == 0) {
        o1 = x1[n]; o2 = x2[n];
    } else {
        float gt1 = gate[(0*Bz + b)*Cc + c];
        float gt2 = gate[(1*Bz + b)*Cc + c];
        float t1 = gt1*s1[n] + x1[n];
        float t2 = gt2*s2[n] + x2[n];
        float m1 = stat[(0*Cc + c)*2], is1 = stat[(0*Cc + c)*2 + 1];
        float m2 = stat[(1*Cc + c)*2], is2 = stat[(1*Cc + c)*2 + 1];
        o1 = fmaxf((t1 - m1)*is1*sc1[c] + bi1[c], 0.f);
        o2 = fmaxf((t2 - m2)*is2*sc2[c] + bi2[c], 0.f);
    }
    out[n] = o1;
    out[BCHW + n] = o2;
}

// ---------------- host launch ----------------
extern "C" void kernel_launch(void* const* d_in, const int* in_sizes, int n_in,
                              void* d_out, int out_size) {
    const float* x1  = (const float*)d_in[0];
    const float* x2  = (const float*)d_in[1];
    const float* wq1 = (const float*)d_in[2];
    const float* bq1 = (const float*)d_in[3];
    const float* wq2 = (const float*)d_in[4];
    const float* bq2 = (const float*)d_in[5];
    const float* wk1 = (const float*)d_in[6];
    const float* bk1 = (const float*)d_in[7];
    const float* wk2 = (const float*)d_in[8];
    const float* bk2 = (const float*)d_in[9];
    const float* wv1 = (const float*)d_in[10];
    const float* bv1 = (const float*)d_in[11];
    const float* wv2 = (const float*)d_in[12];
    const float* bv2 = (const float*)d_in[13];
    const float* gamma1 = (const float*)d_in[14];
    const float* gamma2 = (const float*)d_in[15];
    const float* sc1_w1 = (const float*)d_in[16];
    const float* sc1_b1 = (const float*)d_in[17];
    const float* sc1_w2 = (const float*)d_in[18];
    const float* sc1_b2 = (const float*)d_in[19];
    const float* sc2_w1 = (const float*)d_in[20];
    const float* sc2_b1 = (const float*)d_in[21];
    const float* sc2_w2 = (const float*)d_in[22];
    const float* sc2_b2 = (const float*)d_in[23];
    const float* bn1_scale = (const float*)d_in[24];
    const float* bn1_bias  = (const float*)d_in[25];
    const float* bn2_scale = (const float*)d_in[26];
    const float* bn2_bias  = (const float*)d_in[27];

    float *qk, *qkT, *mW, *sW, *mH, *sH, *fH, *fW, *s1, *s2, *pp, *gate, *stat;
    __half *vh, *vhT, *attHT, *attW;
    cudaGetSymbolAddress((void**)&qk,  g_qk);
    cudaGetSymbolAddress((void**)&qkT, g_qkT);
    cudaGetSymbolAddress((void**)&vh,  g_v);
    cudaGetSymbolAddress((void**)&vhT, g_vT);
    cudaGetSymbolAddress((void**)&mW,  g_mW);
    cudaGetSymbolAddress((void**)&sW,  g_sW);
    cudaGetSymbolAddress((void**)&mH,  g_mH);
    cudaGetSymbolAddress((void**)&sH,  g_sH);
    cudaGetSymbolAddress((void**)&fH,  g_fH);
    cudaGetSymbolAddress((void**)&fW,  g_fW);
    cudaGetSymbolAddress((void**)&attHT, g_attHT);
    cudaGetSymbolAddress((void**)&attW,  g_attW);
    cudaGetSymbolAddress((void**)&s1, g_s1);
    cudaGetSymbolAddress((void**)&s2, g_s2);
    cudaGetSymbolAddress((void**)&pp, g_pp);
    cudaGetSymbolAddress((void**)&gate, g_gate);
    cudaGetSymbolAddress((void**)&stat, g_stat);

    float* q1 = qk + (size_t)PQ1*HWi;
    float* q2 = qk + (size_t)PQ2*HWi;
    float* k1 = qk + (size_t)PK1*HWi;
    float* k2 = qk + (size_t)PK2*HWi;
    __half* v1 = vh;                       // planes 0..127
    __half* v2 = vh + (size_t)128*HWi;     // planes 128..255

    // projections (q/k fp32, v fp16)
    proj_kernel<<<512, 256>>>(x1, wq1, bq1, wk1, bk1, wv1, bv1, q1, k1, v1);
    proj_kernel<<<512, 256>>>(x2, wq2, bq2, wk2, bk2, wv2, bv2, q2, k2, v2);

    // transposes: 64 fp32 q/k planes, 256 fp16 v planes
    transpose_f32<<<dim3(64, 64), 256>>>(qk, qkT);
    transpose_u16<<<dim3(64, 256), 256>>>((const unsigned short*)vh, (unsigned short*)vhT);

    // aggregation: online softmax + f16 tensor-core P·V (one launch, both dirs/crisses)
    agg_kernel<<<dim3(256, 4, 4), 256>>>(qk, qkT, vh, vhT, attW, attHT, mW, sW, mH, sH);

    // exact cross-direction merge factors
    factor_kernel<<<dim3(256, Bz, 2), 256>>>(mH, sH, mW, sW, fH, fW);

    // merge + ShareCA s-planes (odd channels) + fused pooled moments
    merge_kernel<<<dim3(64, Cc, Bz), 256>>>(attHT, attW, fH, fW, x1, x2,
                                            gamma1, gamma2, s1, s2, pp);

    // gates, BN stats, finalize
    gate_kernel<<<1, 256>>>(sc1_w1, sc1_b1, sc1_w2, sc1_b2,
                            sc2_w1, sc2_b1, sc2_w2, sc2_b2, pp, gate);
    bnstat_kernel<<<1, 128>>>(pp, gate, stat);
    final_kernel<<<BCHW/256, 256>>>(x1, x2, s1, s2, gate, stat,
                                    bn1_scale, bn1_bias, bn2_scale, bn2_bias, (float*)d_out);
}